// round 1
// baseline (speedup 1.0000x reference)
#include <cuda_runtime.h>

#define NB 4
#define NS 1024
#define ND 1024
#define NH 16
#define NDH 64

// Scratch (device globals: allocation-free per harness rules)
__device__ float g_q[(size_t)NB * NS * ND];
__device__ float g_k[(size_t)NB * NS * ND];
__device__ float g_v[(size_t)NB * NS * ND];
__device__ float g_ctx[(size_t)NB * NS * ND];
__device__ float g_dots[(size_t)NB * NH * NS * NS];  // scores -> attn (in place)
__device__ float g_pos[(size_t)NB * NH * NS * NS];   // q @ pe^T

// ---------------------------------------------------------------------------
// NT GEMM: C[i,j] = alpha * sum_k A[i,k] * B[j,k]
// Batch offset for operand X: (z/NH)*xOut + (z%NH)*xIn  (covers plain z-stride,
// per-head-only stride, and interleaved [B,S,H,DH] layouts uniformly).
// M,N implied by grid (y = M/BM, x = N/BN, z = batch).
// ---------------------------------------------------------------------------
template <int BM, int BN, int BK>
__global__ void __launch_bounds__(256) gemm_nt_kernel(
    const float* __restrict__ A, const float* __restrict__ Bp,
    float* __restrict__ C,
    int K, int lda, int ldb, int ldc,
    long aOut, long aIn, long bOut, long bIn, long cOut, long cIn,
    float alpha)
{
    constexpr int TM = 8, TN = 8;
    __shared__ float As[BK][BM + 4];
    __shared__ float Bs[BK][BN + 4];

    const int z = blockIdx.z;
    const int zo = z / NH, zi = z % NH;
    const float* Ab = A  + (long)zo * aOut + (long)zi * aIn;
    const float* Bb = Bp + (long)zo * bOut + (long)zi * bIn;
    float*       Cb = C  + (long)zo * cOut + (long)zi * cIn;

    const int tid  = threadIdx.x;
    const int row0 = blockIdx.y * BM;
    const int col0 = blockIdx.x * BN;

    float acc[TM][TN] = {};

    const int ty = tid >> 4;        // 0..15
    const int tx = tid & 15;        // 0..15

    for (int kt = 0; kt < K; kt += BK) {
        // Load A tile (BM x BK), K-contiguous, transposed into As[BK][BM]
        #pragma unroll
        for (int it = 0; it < (BM * BK) / (256 * 4); it++) {
            int idx = tid + it * 256;
            int r  = idx >> 2;      // BK/4 == 4 float4 per row
            int c4 = idx & 3;
            float4 va = *(const float4*)&Ab[(long)(row0 + r) * lda + kt + c4 * 4];
            As[c4 * 4 + 0][r] = va.x;
            As[c4 * 4 + 1][r] = va.y;
            As[c4 * 4 + 2][r] = va.z;
            As[c4 * 4 + 3][r] = va.w;
        }
        // Load B tile (BN x BK), K-contiguous
        #pragma unroll
        for (int it = 0; it < (BN * BK) / (256 * 4); it++) {
            int idx = tid + it * 256;
            int r  = idx >> 2;
            int c4 = idx & 3;
            float4 vb = *(const float4*)&Bb[(long)(col0 + r) * ldb + kt + c4 * 4];
            Bs[c4 * 4 + 0][r] = vb.x;
            Bs[c4 * 4 + 1][r] = vb.y;
            Bs[c4 * 4 + 2][r] = vb.z;
            Bs[c4 * 4 + 3][r] = vb.w;
        }
        __syncthreads();

        #pragma unroll
        for (int kk = 0; kk < BK; kk++) {
            float4 a0 = *(const float4*)&As[kk][ty * TM];
            float4 a1 = *(const float4*)&As[kk][ty * TM + 4];
            float4 b0 = *(const float4*)&Bs[kk][tx * TN];
            float4 b1 = *(const float4*)&Bs[kk][tx * TN + 4];
            float af[TM] = {a0.x, a0.y, a0.z, a0.w, a1.x, a1.y, a1.z, a1.w};
            float bf[TN] = {b0.x, b0.y, b0.z, b0.w, b1.x, b1.y, b1.z, b1.w};
            #pragma unroll
            for (int m = 0; m < TM; m++)
                #pragma unroll
                for (int n = 0; n < TN; n++)
                    acc[m][n] += af[m] * bf[n];
        }
        __syncthreads();
    }

    #pragma unroll
    for (int m = 0; m < TM; m++) {
        long r = (long)(row0 + ty * TM + m) * ldc + col0 + tx * TN;
        float4 o0 = make_float4(alpha * acc[m][0], alpha * acc[m][1],
                                alpha * acc[m][2], alpha * acc[m][3]);
        float4 o1 = make_float4(alpha * acc[m][4], alpha * acc[m][5],
                                alpha * acc[m][6], alpha * acc[m][7]);
        *(float4*)&Cb[r]     = o0;
        *(float4*)&Cb[r + 4] = o1;
    }
}

// ---------------------------------------------------------------------------
// Combine (dots + shifted pos), mask, softmax — one block per row (bh, i).
// shift(pos)[i,j] = pos[i, j-i+S-1] for j<=i, else 0.
// ---------------------------------------------------------------------------
__global__ void __launch_bounds__(256) softmax_kernel(const int* __restrict__ mask)
{
    const int i  = blockIdx.x;
    const int bh = blockIdx.y;
    const int b  = bh / NH;
    const long base = ((long)bh * NS + i) * NS;
    float* row        = g_dots + base;
    const float* prow = g_pos + base;
    const int tid = threadIdx.x;
    const int mi  = mask[b * NS + i];

    float v[4];
    float mx = -3.0e38f;
    #pragma unroll
    for (int u = 0; u < 4; u++) {
        int j = u * 256 + tid;
        float x = row[j];
        if (j <= i) x += prow[NS - 1 + j - i];
        if (mi == 0 || mask[b * NS + j] == 0) x = -1.0e9f;
        v[u] = x;
        mx = fmaxf(mx, x);
    }

    __shared__ float red[256];
    red[tid] = mx;
    __syncthreads();
    for (int s = 128; s > 0; s >>= 1) {
        if (tid < s) red[tid] = fmaxf(red[tid], red[tid + s]);
        __syncthreads();
    }
    mx = red[0];
    __syncthreads();

    float sum = 0.0f;
    #pragma unroll
    for (int u = 0; u < 4; u++) {
        v[u] = expf(v[u] - mx);
        sum += v[u];
    }
    red[tid] = sum;
    __syncthreads();
    for (int s = 128; s > 0; s >>= 1) {
        if (tid < s) red[tid] += red[tid + s];
        __syncthreads();
    }
    sum = red[0];

    #pragma unroll
    for (int u = 0; u < 4; u++) {
        int j = u * 256 + tid;
        row[j] = v[u] / sum;
    }
}

// ---------------------------------------------------------------------------
// attn @ v : per (b,h): C[i,d] = sum_j attn[i,j] * v[j,d]  (NN, N = DH = 64)
// v, ctx in [B,S,D] interleaved layout; ctx comes out ready for the NT output
// projection.
// ---------------------------------------------------------------------------
__global__ void __launch_bounds__(256) gemm_av_kernel()
{
    constexpr int BM = 128, BN = 64, BK = 16, TM = 8, TN = 4;
    __shared__ float As[BK][BM + 4];
    __shared__ float Bs[BK][BN];

    const int z = blockIdx.z;             // bh
    const int b = z / NH, h = z % NH;
    const float* Ab = g_dots + (long)z * NS * NS;
    const float* Bb = g_v   + (long)b * NS * ND + h * NDH;
    float*       Cb = g_ctx + (long)b * NS * ND + h * NDH;

    const int tid  = threadIdx.x;
    const int row0 = blockIdx.y * BM;
    const int ty = tid >> 4, tx = tid & 15;

    float acc[TM][TN] = {};

    for (int kt = 0; kt < NS; kt += BK) {
        // A tile 128x16 (K-contiguous rows of attn)
        #pragma unroll
        for (int it = 0; it < 2; it++) {
            int idx = tid + it * 256;
            int r  = idx >> 2;
            int c4 = idx & 3;
            float4 va = *(const float4*)&Ab[(long)(row0 + r) * NS + kt + c4 * 4];
            As[c4 * 4 + 0][r] = va.x;
            As[c4 * 4 + 1][r] = va.y;
            As[c4 * 4 + 2][r] = va.z;
            As[c4 * 4 + 3][r] = va.w;
        }
        // B tile 16x64 (natural layout, n-contiguous)
        {
            int r  = tid >> 4;            // 0..15
            int c4 = tid & 15;            // 0..15
            float4 vb = *(const float4*)&Bb[(long)(kt + r) * ND + c4 * 4];
            *(float4*)&Bs[r][c4 * 4] = vb;
        }
        __syncthreads();

        #pragma unroll
        for (int kk = 0; kk < BK; kk++) {
            float4 a0 = *(const float4*)&As[kk][ty * TM];
            float4 a1 = *(const float4*)&As[kk][ty * TM + 4];
            float4 bv = *(const float4*)&Bs[kk][tx * TN];
            float af[TM] = {a0.x, a0.y, a0.z, a0.w, a1.x, a1.y, a1.z, a1.w};
            float bf[TN] = {bv.x, bv.y, bv.z, bv.w};
            #pragma unroll
            for (int m = 0; m < TM; m++)
                #pragma unroll
                for (int n = 0; n < TN; n++)
                    acc[m][n] += af[m] * bf[n];
        }
        __syncthreads();
    }

    #pragma unroll
    for (int m = 0; m < TM; m++) {
        long r = (long)(row0 + ty * TM + m) * ND + tx * TN;
        *(float4*)&Cb[r] = make_float4(acc[m][0], acc[m][1], acc[m][2], acc[m][3]);
    }
}

// ---------------------------------------------------------------------------
extern "C" void kernel_launch(void* const* d_in, const int* in_sizes, int n_in,
                              void* d_out, int out_size)
{
    const float* query = (const float*)d_in[0];
    const float* key   = (const float*)d_in[1];
    const float* value = (const float*)d_in[2];
    const int*   mask  = (const int*)  d_in[3];
    const float* pe    = (const float*)d_in[4];
    const float* Wq    = (const float*)d_in[5];
    const float* Wk    = (const float*)d_in[6];
    const float* Wv    = (const float*)d_in[7];
    const float* Wo    = (const float*)d_in[8];
    float* out = (float*)d_out;

    float *q, *k, *v, *ctx, *dots, *pos;
    cudaGetSymbolAddress((void**)&q,    g_q);
    cudaGetSymbolAddress((void**)&k,    g_k);
    cudaGetSymbolAddress((void**)&v,    g_v);
    cudaGetSymbolAddress((void**)&ctx,  g_ctx);
    cudaGetSymbolAddress((void**)&dots, g_dots);
    cudaGetSymbolAddress((void**)&pos,  g_pos);

    const dim3 th(256);
    const long SD  = (long)NS * ND;     // per-batch stride of [B,S,D]
    const long SS  = (long)NS * NS;     // per-head score stride
    const long HSS = (long)NH * SS;

    // Projections: [4096,1024] = X[4096,1024] @ W^T   (plain NT, z=1)
    gemm_nt_kernel<128,128,16><<<dim3(8,32,1), th>>>(query, Wq, q, ND, ND, ND, ND,
                                                     0,0, 0,0, 0,0, 1.0f);
    gemm_nt_kernel<128,128,16><<<dim3(8,32,1), th>>>(key,   Wk, k, ND, ND, ND, ND,
                                                     0,0, 0,0, 0,0, 1.0f);
    gemm_nt_kernel<128,128,16><<<dim3(8,32,1), th>>>(value, Wv, v, ND, ND, ND, ND,
                                                     0,0, 0,0, 0,0, 1.0f);

    // dots = (q @ k^T) * DH^-0.5, per (b,h); q/k rows strided in [B,S,D]
    gemm_nt_kernel<128,128,16><<<dim3(8,8,NB*NH), th>>>(q, k, dots, NDH, ND, ND, NS,
                                                        SD, NDH, SD, NDH, HSS, SS,
                                                        0.125f);

    // pos = (q @ pe[h]^T) * DH^0.5
    gemm_nt_kernel<128,128,16><<<dim3(8,8,NB*NH), th>>>(q, pe, pos, NDH, ND, NDH, NS,
                                                        SD, NDH, 0L, (long)NS*NDH,
                                                        HSS, SS, 8.0f);

    // combine + skew-shift + mask + softmax (in place on dots)
    softmax_kernel<<<dim3(NS, NB*NH), th>>>(mask);

    // ctx = attn @ v  -> [B,S,D]
    gemm_av_kernel<<<dim3(1,8,NB*NH), th>>>();

    // out = ctx @ W_o^T
    gemm_nt_kernel<128,128,16><<<dim3(8,32,1), th>>>(ctx, Wo, out, ND, ND, ND, ND,
                                                     0,0, 0,0, 0,0, 1.0f);
}

// round 3
// speedup vs baseline: 2.0647x; 2.0647x over previous
#include <cuda_runtime.h>
#include <cuda_bf16.h>
#include <cstdint>

#define NB 4
#define NS 1024
#define ND 1024
#define NH 16
#define NDH 64

// Scratch (device globals: allocation-free per harness rules)
__device__ float g_q[(size_t)NB * NS * ND];
__device__ float g_k[(size_t)NB * NS * ND];
__device__ float g_v[(size_t)NB * NS * ND];
__device__ float g_vt[(size_t)NB * NH * NDH * NS];   // V^T per head: [B,H,DH,S]
__device__ float g_ctx[(size_t)NB * NS * ND];
__device__ float g_dots[(size_t)NB * NH * NS * NS];  // scores -> attn (in place)
__device__ float g_pos[(size_t)NB * NH * NS * NS];   // q @ pe^T

// ---------------------------------------------------------------------------
// Base-ISA tensor core helpers (sm_80+ PTX: assemble for plain sm_103)
// ---------------------------------------------------------------------------
static __device__ __forceinline__ uint32_t smem_u32(const void* p) {
    uint32_t a;
    asm("{ .reg .u64 t; cvta.to.shared.u64 t, %1; cvt.u32.u64 %0, t; }"
        : "=r"(a) : "l"(p));
    return a;
}
static __device__ __forceinline__ void ldsm_x4(uint32_t* r, uint32_t addr) {
    asm volatile("ldmatrix.sync.aligned.m8n8.x4.shared.b16 {%0,%1,%2,%3}, [%4];"
                 : "=r"(r[0]), "=r"(r[1]), "=r"(r[2]), "=r"(r[3]) : "r"(addr));
}
static __device__ __forceinline__ void mma_bf16(float* c, const uint32_t* a,
                                                const uint32_t* b) {
    asm volatile(
        "mma.sync.aligned.m16n8k16.row.col.f32.bf16.bf16.f32 "
        "{%0,%1,%2,%3}, {%4,%5,%6,%7}, {%8,%9}, {%0,%1,%2,%3};"
        : "+f"(c[0]), "+f"(c[1]), "+f"(c[2]), "+f"(c[3])
        : "r"(a[0]), "r"(a[1]), "r"(a[2]), "r"(a[3]), "r"(b[0]), "r"(b[1]));
}

// fp32 -> (hi, lo) bf16 pair stored to smem (uint2 = 4 bf16)
static __device__ __forceinline__ void cvt_wr(char* hi, char* lo, int off, float4 x) {
    __nv_bfloat162 h01 = __floats2bfloat162_rn(x.x, x.y);
    __nv_bfloat162 h23 = __floats2bfloat162_rn(x.z, x.w);
    __nv_bfloat162 l01 = __floats2bfloat162_rn(x.x - __low2float(h01),
                                               x.y - __high2float(h01));
    __nv_bfloat162 l23 = __floats2bfloat162_rn(x.z - __low2float(h23),
                                               x.w - __high2float(h23));
    uint2 h, l;
    h.x = *(uint32_t*)&h01; h.y = *(uint32_t*)&h23;
    l.x = *(uint32_t*)&l01; l.y = *(uint32_t*)&l23;
    *(uint2*)(hi + off) = h;
    *(uint2*)(lo + off) = l;
}

// ---------------------------------------------------------------------------
// HMMA bf16x3 NT GEMM: C[i,j] = alpha * sum_k A[i,k]*B[j,k]  (fp32 in/out)
// BM=128, BN=64, BK=32. 256 threads = 8 warps (4 M x 2 N), warp tile 32x32.
// Batch offset per operand: (z/NH)*xOut + (z%NH)*xIn.
// ---------------------------------------------------------------------------
constexpr int BM = 128, BN = 64, BK = 32;
constexpr int LDE = BK + 8;                       // 40 elems = 80 B row stride
constexpr int AH_OFF = 0;
constexpr int AL_OFF = BM * LDE * 2;              // 10240
constexpr int BH_OFF = 2 * BM * LDE * 2;          // 20480
constexpr int BL_OFF = BH_OFF + BN * LDE * 2;     // 25600
constexpr int SMEM_BYTES = BH_OFF + 2 * BN * LDE * 2;  // 30720

__global__ void __launch_bounds__(256, 2) hmma_gemm_nt(
    const float* __restrict__ A, const float* __restrict__ Bp, float* __restrict__ C,
    int K, int lda, int ldb, int ldc,
    long aOut, long aIn, long bOut, long bIn, long cOut, long cIn, float alpha)
{
    __shared__ __align__(128) char sm[SMEM_BYTES];
    const uint32_t sb = smem_u32(sm);

    const int tid = threadIdx.x;
    const int wid = tid >> 5, lane = tid & 31;
    const int z = blockIdx.z, zo = z / NH, zi = z % NH;
    const float* Ab = A + (long)zo * aOut + (long)zi * aIn + (long)(blockIdx.y * BM) * lda;
    const float* Bb = Bp + (long)zo * bOut + (long)zi * bIn + (long)(blockIdx.x * BN) * ldb;
    float* Cb = C + (long)zo * cOut + (long)zi * cIn + (long)(blockIdx.y * BM) * ldc
                + blockIdx.x * BN;

    // per-thread gmem/smem coords: A 128x8 float4 (4 iters), B 64x8 float4 (2)
    long aoff[4]; int abyte[4];
    #pragma unroll
    for (int i = 0; i < 4; ++i) {
        int idx = tid + i * 256, r = idx >> 3, c4 = idx & 7;
        aoff[i] = (long)r * lda + c4 * 4;
        abyte[i] = r * (LDE * 2) + c4 * 8;
    }
    long boff[2]; int bbyte[2];
    #pragma unroll
    for (int i = 0; i < 2; ++i) {
        int idx = tid + i * 256, r = idx >> 3, c4 = idx & 7;
        boff[i] = (long)r * ldb + c4 * 4;
        bbyte[i] = r * (LDE * 2) + c4 * 8;
    }

    float4 pa[4], pb[2];
    #pragma unroll
    for (int i = 0; i < 4; ++i) pa[i] = *(const float4*)(Ab + aoff[i]);
    #pragma unroll
    for (int i = 0; i < 2; ++i) pb[i] = *(const float4*)(Bb + boff[i]);

    float acc[2][4][4] = {};
    const int wm = wid & 3, wn = wid >> 2;

    // ldmatrix lane addresses
    const uint32_t aAddrH = sb + AH_OFF +
        (uint32_t)(((wm * 32 + (lane & 15)) * LDE + (lane >> 4) * 8) * 2);
    const uint32_t aAddrL = aAddrH + (AL_OFF - AH_OFF);
    const int brow = (lane & 7) | ((lane >> 1) & 8);
    const uint32_t bAddrH = sb + BH_OFF +
        (uint32_t)(((wn * 32 + brow) * LDE + ((lane >> 3) & 1) * 8) * 2);
    const uint32_t bAddrL = bAddrH + (BL_OFF - BH_OFF);

    const int nchunks = K >> 5;
    for (int c = 0; c < nchunks; ++c) {
        #pragma unroll
        for (int i = 0; i < 4; ++i) cvt_wr(sm + AH_OFF, sm + AL_OFF, abyte[i], pa[i]);
        #pragma unroll
        for (int i = 0; i < 2; ++i) cvt_wr(sm + BH_OFF, sm + BL_OFF, bbyte[i], pb[i]);
        __syncthreads();

        if (c + 1 < nchunks) {  // prefetch next chunk; lands during MMA below
            const int kt = (c + 1) << 5;
            #pragma unroll
            for (int i = 0; i < 4; ++i) pa[i] = *(const float4*)(Ab + aoff[i] + kt);
            #pragma unroll
            for (int i = 0; i < 2; ++i) pb[i] = *(const float4*)(Bb + boff[i] + kt);
        }

        #pragma unroll
        for (int ks = 0; ks < 2; ++ks) {
            uint32_t ah[2][4], alr[2][4], bh[2][4], blr[2][4];
            #pragma unroll
            for (int mt = 0; mt < 2; ++mt) {
                ldsm_x4(ah[mt],  aAddrH + mt * 16 * LDE * 2 + ks * 32);
                ldsm_x4(alr[mt], aAddrL + mt * 16 * LDE * 2 + ks * 32);
            }
            #pragma unroll
            for (int nt2 = 0; nt2 < 2; ++nt2) {
                ldsm_x4(bh[nt2],  bAddrH + nt2 * 16 * LDE * 2 + ks * 32);
                ldsm_x4(blr[nt2], bAddrL + nt2 * 16 * LDE * 2 + ks * 32);
            }
            #pragma unroll
            for (int mt = 0; mt < 2; ++mt)
                #pragma unroll
                for (int nt = 0; nt < 4; ++nt) {
                    float* cc = acc[mt][nt];
                    const uint32_t* bhp = &bh[nt >> 1][(nt & 1) * 2];
                    const uint32_t* blp = &blr[nt >> 1][(nt & 1) * 2];
                    mma_bf16(cc, ah[mt], bhp);   // hi*hi
                    mma_bf16(cc, ah[mt], blp);   // hi*lo
                    mma_bf16(cc, alr[mt], bhp);  // lo*hi
                }
        }
        __syncthreads();
    }

    // Epilogue: direct stores from fragments
    const int r0 = wm * 32 + (lane >> 2);
    const int c0 = wn * 32 + (lane & 3) * 2;
    #pragma unroll
    for (int mt = 0; mt < 2; ++mt)
        #pragma unroll
        for (int nt = 0; nt < 4; ++nt) {
            int row = r0 + mt * 16, col = c0 + nt * 8;
            float2 v0 = make_float2(acc[mt][nt][0] * alpha, acc[mt][nt][1] * alpha);
            float2 v1 = make_float2(acc[mt][nt][2] * alpha, acc[mt][nt][3] * alpha);
            *(float2*)(Cb + (long)row * ldc + col) = v0;
            *(float2*)(Cb + (long)(row + 8) * ldc + col) = v1;
        }
}

// ---------------------------------------------------------------------------
// V transpose per head: g_v [B,S,D] -> g_vt [B,H,DH,S]
// ---------------------------------------------------------------------------
__global__ void __launch_bounds__(256) transpose_v_kernel()
{
    __shared__ float t[32][33];
    const int bh = blockIdx.z;
    const int b = bh / NH, h = bh % NH;
    const int j0 = blockIdx.x * 32, d0 = blockIdx.y * 32;
    const int tx = threadIdx.x, ty = threadIdx.y;  // 32 x 8
    const float* src = g_v + (long)b * NS * ND + h * NDH;
    #pragma unroll
    for (int i = 0; i < 4; ++i) {
        int j = j0 + ty + i * 8;
        t[ty + i * 8][tx] = src[(long)j * ND + d0 + tx];
    }
    __syncthreads();
    float* dst = g_vt + (long)bh * NDH * NS;
    #pragma unroll
    for (int i = 0; i < 4; ++i) {
        int d = d0 + ty + i * 8;
        dst[(long)d * NS + j0 + tx] = t[tx][ty + i * 8];
    }
}

// ---------------------------------------------------------------------------
// Combine (dots + shifted pos), mask, softmax — one block per row (bh, i).
// shift(pos)[i,j] = pos[i, j-i+S-1] for j<=i, else 0.
// ---------------------------------------------------------------------------
__global__ void __launch_bounds__(256) softmax_kernel(const int* __restrict__ mask)
{
    const int i  = blockIdx.x;
    const int bh = blockIdx.y;
    const int b  = bh / NH;
    const long base = ((long)bh * NS + i) * NS;
    float* row        = g_dots + base;
    const float* prow = g_pos + base;
    const int tid = threadIdx.x;
    const int mi  = mask[b * NS + i];

    float v[4];
    float mx = -3.0e38f;
    #pragma unroll
    for (int u = 0; u < 4; u++) {
        int j = u * 256 + tid;
        float x = row[j];
        if (j <= i) x += prow[NS - 1 + j - i];
        if (mi == 0 || mask[b * NS + j] == 0) x = -1.0e9f;
        v[u] = x;
        mx = fmaxf(mx, x);
    }

    __shared__ float red[256];
    red[tid] = mx;
    __syncthreads();
    for (int s = 128; s > 0; s >>= 1) {
        if (tid < s) red[tid] = fmaxf(red[tid], red[tid + s]);
        __syncthreads();
    }
    mx = red[0];
    __syncthreads();

    float sum = 0.0f;
    #pragma unroll
    for (int u = 0; u < 4; u++) {
        v[u] = __expf(v[u] - mx);
        sum += v[u];
    }
    red[tid] = sum;
    __syncthreads();
    for (int s = 128; s > 0; s >>= 1) {
        if (tid < s) red[tid] += red[tid + s];
        __syncthreads();
    }
    sum = red[0];
    const float inv = 1.0f / sum;

    #pragma unroll
    for (int u = 0; u < 4; u++) {
        int j = u * 256 + tid;
        row[j] = v[u] * inv;
    }
}

// ---------------------------------------------------------------------------
extern "C" void kernel_launch(void* const* d_in, const int* in_sizes, int n_in,
                              void* d_out, int out_size)
{
    const float* query = (const float*)d_in[0];
    const float* key   = (const float*)d_in[1];
    const float* value = (const float*)d_in[2];
    const int*   mask  = (const int*)  d_in[3];
    const float* pe    = (const float*)d_in[4];
    const float* Wq    = (const float*)d_in[5];
    const float* Wk    = (const float*)d_in[6];
    const float* Wv    = (const float*)d_in[7];
    const float* Wo    = (const float*)d_in[8];
    float* out = (float*)d_out;

    float *q, *k, *v, *vt, *ctx, *dots, *pos;
    cudaGetSymbolAddress((void**)&q,    g_q);
    cudaGetSymbolAddress((void**)&k,    g_k);
    cudaGetSymbolAddress((void**)&v,    g_v);
    cudaGetSymbolAddress((void**)&vt,   g_vt);
    cudaGetSymbolAddress((void**)&ctx,  g_ctx);
    cudaGetSymbolAddress((void**)&dots, g_dots);
    cudaGetSymbolAddress((void**)&pos,  g_pos);

    const dim3 th(256);
    const long SD  = (long)NS * ND;
    const long SS  = (long)NS * NS;
    const long HSS = (long)NH * SS;

    // Projections: [4096,1024] = X @ W^T  (M=4096 -> grid.y=32, N=1024 -> grid.x=16)
    hmma_gemm_nt<<<dim3(16, 32, 1), th>>>(query, Wq, q, ND, ND, ND, ND,
                                          0, 0, 0, 0, 0, 0, 1.0f);
    hmma_gemm_nt<<<dim3(16, 32, 1), th>>>(key,   Wk, k, ND, ND, ND, ND,
                                          0, 0, 0, 0, 0, 0, 1.0f);
    hmma_gemm_nt<<<dim3(16, 32, 1), th>>>(value, Wv, v, ND, ND, ND, ND,
                                          0, 0, 0, 0, 0, 0, 1.0f);

    // dots = (q @ k^T) * DH^-0.5 per (b,h)
    hmma_gemm_nt<<<dim3(16, 8, NB * NH), th>>>(q, k, dots, NDH, ND, ND, NS,
                                               SD, NDH, SD, NDH, HSS, SS, 0.125f);
    // pos = (q @ pe[h]^T) * DH^0.5
    hmma_gemm_nt<<<dim3(16, 8, NB * NH), th>>>(q, pe, pos, NDH, ND, NDH, NS,
                                               SD, NDH, 0L, (long)NS * NDH,
                                               HSS, SS, 8.0f);

    // combine + skew-shift + mask + softmax (in place on dots)
    softmax_kernel<<<dim3(NS, NB * NH), th>>>(mask);

    // v^T per head
    transpose_v_kernel<<<dim3(32, 2, NB * NH), dim3(32, 8)>>>();

    // ctx = attn @ v  -> [B,S,D]
    hmma_gemm_nt<<<dim3(1, 8, NB * NH), th>>>(dots, vt, ctx, NS, NS, NS, ND,
                                              HSS, SS,
                                              (long)NH * NDH * NS, (long)NDH * NS,
                                              SD, (long)NDH, 1.0f);

    // out = ctx @ W_o^T
    hmma_gemm_nt<<<dim3(16, 32, 1), th>>>(ctx, Wo, out, ND, ND, ND, ND,
                                          0, 0, 0, 0, 0, 0, 1.0f);
}

// round 4
// speedup vs baseline: 2.1987x; 1.0649x over previous
#include <cuda_runtime.h>
#include <cuda_bf16.h>
#include <cstdint>

#define NB 4
#define NS 1024
#define ND 1024
#define NH 16
#define NDH 64

#define E_X   ((long)NB * NS * ND)       // 4194304
#define E_W   ((long)ND * ND)            // 1048576
#define E_PE  ((long)NH * NS * NDH)      // 1048576
#define E_ATT ((long)NB * NH * NS * NS)  // 67108864

// Plane buffers (hi at [0,E), lo at [E,2E)), uint4-declared for 16B alignment.
__device__ uint4 p_x[E_X / 4],  p_y[E_X / 4],  p_z[E_X / 4];
__device__ uint4 p_q[E_X / 4],  p_k[E_X / 4],  p_v[E_X / 4];
__device__ uint4 p_vt[E_X / 4], p_ctx[E_X / 4];
__device__ uint4 p_wq[E_W / 4], p_wk[E_W / 4], p_wv[E_W / 4], p_wo[E_W / 4];
__device__ uint4 p_pe[E_PE / 4];
__device__ uint4 p_attn[E_ATT / 4];
__device__ float4 g_dots4[E_ATT / 4];
__device__ float4 g_pos4[E_ATT / 4];

// ---------------------------------------------------------------------------
// Helpers (base-ISA PTX only: assembles for plain sm_103)
// ---------------------------------------------------------------------------
static __device__ __forceinline__ uint32_t smem_u32(const void* p) {
    uint32_t a;
    asm("{ .reg .u64 t; cvta.to.shared.u64 t, %1; cvt.u32.u64 %0, t; }"
        : "=r"(a) : "l"(p));
    return a;
}
static __device__ __forceinline__ void ldsm_x4(uint32_t* r, uint32_t addr) {
    asm volatile("ldmatrix.sync.aligned.m8n8.x4.shared.b16 {%0,%1,%2,%3}, [%4];"
                 : "=r"(r[0]), "=r"(r[1]), "=r"(r[2]), "=r"(r[3]) : "r"(addr));
}
static __device__ __forceinline__ void mma_bf16(float* c, const uint32_t* a,
                                                const uint32_t* b) {
    asm volatile(
        "mma.sync.aligned.m16n8k16.row.col.f32.bf16.bf16.f32 "
        "{%0,%1,%2,%3}, {%4,%5,%6,%7}, {%8,%9}, {%0,%1,%2,%3};"
        : "+f"(c[0]), "+f"(c[1]), "+f"(c[2]), "+f"(c[3])
        : "r"(a[0]), "r"(a[1]), "r"(a[2]), "r"(a[3]), "r"(b[0]), "r"(b[1]));
}
static __device__ __forceinline__ void cpa16(uint32_t d, const void* s) {
    asm volatile("cp.async.cg.shared.global [%0], [%1], 16;" :: "r"(d), "l"(s));
}
static __device__ __forceinline__ void cpa_commit() {
    asm volatile("cp.async.commit_group;" ::: "memory");
}
template <int N> static __device__ __forceinline__ void cpa_wait() {
    asm volatile("cp.async.wait_group %0;" :: "n"(N) : "memory");
}

// ---------------------------------------------------------------------------
// GEMM v2: C = alpha * A @ B^T, A/B are bf16 hi/lo planes, bf16x3 accumulation.
// BM=128, BN in {128, 64}, BK=32, 256 threads, 2-stage cp.async pipeline.
// OUTP: write hi/lo planes (bf16) instead of fp32.
// ---------------------------------------------------------------------------
template <int BN, bool OUTP>
__global__ void __launch_bounds__(256, 2) gemm2(
    const __nv_bfloat16* __restrict__ A, const __nv_bfloat16* __restrict__ Bp,
    void* __restrict__ Cv,
    int K, int lda, int ldb, int ldc,
    long aOut, long aIn, long bOut, long bIn, long cOut, long cIn,
    long aPl, long bPl, long cPl, float alpha, int tri)
{
    constexpr int BM = 128, LDE = 40;
    constexpr int WM = (BN == 128) ? 2 : 4;       // warps along M
    constexpr int MT = (BM / WM) / 16;            // m16 frags per warp (4 or 2)
    constexpr int AH = 0;
    constexpr int AL = BM * LDE * 2;              // 10240
    constexpr int BH = 2 * AL;                    // 20480
    constexpr int BL = BH + BN * LDE * 2;
    constexpr int STAGE = BH + 2 * BN * LDE * 2;

    if (tri && (int)(blockIdx.x * BN + blockIdx.y * BM) + 255 < NS) return;

    extern __shared__ __align__(128) char sm[];
    const uint32_t sb = smem_u32(sm);

    const int tid = threadIdx.x, wid = tid >> 5, lane = tid & 31;
    const int wm = wid % WM, wn = wid / WM;
    const int z = blockIdx.z, zo = z / NH, zi = z % NH;

    const __nv_bfloat16* Ab = A + (long)zo * aOut + (long)zi * aIn
                              + (long)(blockIdx.y * BM) * lda;
    const __nv_bfloat16* Bb = Bp + (long)zo * bOut + (long)zi * bIn
                              + (long)(blockIdx.x * BN) * ldb;

    auto issue = [&](int s, int kt) {
        const uint32_t st = sb + s * STAGE;
        #pragma unroll
        for (int t = 0; t < 2; ++t) {
            int r = (tid + t * 256) >> 2, sg = tid & 3;
            const __nv_bfloat16* g = Ab + (long)r * lda + kt + sg * 8;
            uint32_t d = st + r * 80 + sg * 16;
            cpa16(d + AH, g);
            cpa16(d + AL, g + aPl);
        }
        #pragma unroll
        for (int t = 0; t < BN / 64; ++t) {
            int r = (tid + t * 256) >> 2, sg = tid & 3;
            const __nv_bfloat16* g = Bb + (long)r * ldb + kt + sg * 8;
            uint32_t d = st + r * 80 + sg * 16;
            cpa16(d + BH, g);
            cpa16(d + BL, g + bPl);
        }
        cpa_commit();
    };

    const uint32_t aRelH = AH +
        (uint32_t)(((wm * MT * 16 + (lane & 15)) * LDE + (lane >> 4) * 8) * 2);
    const uint32_t aRelL = aRelH + (AL - AH);
    const int brow = (lane & 7) | ((lane >> 1) & 8);
    const uint32_t bRelH = BH +
        (uint32_t)(((wn * 32 + brow) * LDE + ((lane >> 3) & 1) * 8) * 2);
    const uint32_t bRelL = bRelH + (BL - BH);

    float acc[MT][4][4] = {};
    issue(0, 0);

    const int nch = K >> 5;
    for (int c = 0; c < nch; ++c) {
        if (c + 1 < nch) { issue((c + 1) & 1, (c + 1) << 5); cpa_wait<1>(); }
        else             { cpa_wait<0>(); }
        __syncthreads();
        const uint32_t s0 = sb + (c & 1) * STAGE;
        #pragma unroll
        for (int ks = 0; ks < 2; ++ks) {
            uint32_t ah[MT][4], al[MT][4], bh[2][4], bl[2][4];
            #pragma unroll
            for (int mt = 0; mt < MT; ++mt) {
                ldsm_x4(ah[mt], s0 + aRelH + mt * (16 * LDE * 2) + ks * 32);
                ldsm_x4(al[mt], s0 + aRelL + mt * (16 * LDE * 2) + ks * 32);
            }
            #pragma unroll
            for (int nt2 = 0; nt2 < 2; ++nt2) {
                ldsm_x4(bh[nt2], s0 + bRelH + nt2 * (16 * LDE * 2) + ks * 32);
                ldsm_x4(bl[nt2], s0 + bRelL + nt2 * (16 * LDE * 2) + ks * 32);
            }
            #pragma unroll
            for (int mt = 0; mt < MT; ++mt)
                #pragma unroll
                for (int nt = 0; nt < 4; ++nt) {
                    float* cc = acc[mt][nt];
                    const uint32_t* bhp = &bh[nt >> 1][(nt & 1) * 2];
                    const uint32_t* blp = &bl[nt >> 1][(nt & 1) * 2];
                    mma_bf16(cc, ah[mt], bhp);   // hi*hi
                    mma_bf16(cc, ah[mt], blp);   // hi*lo
                    mma_bf16(cc, al[mt], bhp);   // lo*hi
                }
        }
        __syncthreads();
    }

    const int r0 = wm * (MT * 16) + (lane >> 2);
    const int c0 = wn * 32 + (lane & 3) * 2;
    if (OUTP) {
        __nv_bfloat16* Ch = (__nv_bfloat16*)Cv + (long)zo * cOut + (long)zi * cIn
                            + (long)(blockIdx.y * BM) * ldc + blockIdx.x * BN;
        #pragma unroll
        for (int mt = 0; mt < MT; ++mt)
            #pragma unroll
            for (int nt = 0; nt < 4; ++nt)
                #pragma unroll
                for (int h = 0; h < 2; ++h) {
                    long off = (long)(r0 + mt * 16 + h * 8) * ldc + c0 + nt * 8;
                    float x0 = acc[mt][nt][h * 2 + 0] * alpha;
                    float x1 = acc[mt][nt][h * 2 + 1] * alpha;
                    __nv_bfloat162 hi = __floats2bfloat162_rn(x0, x1);
                    __nv_bfloat162 lo = __floats2bfloat162_rn(
                        x0 - __low2float(hi), x1 - __high2float(hi));
                    *(__nv_bfloat162*)(Ch + off)       = hi;
                    *(__nv_bfloat162*)(Ch + off + cPl) = lo;
                }
    } else {
        float* Cf = (float*)Cv + (long)zo * cOut + (long)zi * cIn
                    + (long)(blockIdx.y * BM) * ldc + blockIdx.x * BN;
        #pragma unroll
        for (int mt = 0; mt < MT; ++mt)
            #pragma unroll
            for (int nt = 0; nt < 4; ++nt)
                #pragma unroll
                for (int h = 0; h < 2; ++h) {
                    long off = (long)(r0 + mt * 16 + h * 8) * ldc + c0 + nt * 8;
                    float2 v = make_float2(acc[mt][nt][h * 2 + 0] * alpha,
                                           acc[mt][nt][h * 2 + 1] * alpha);
                    *(float2*)(Cf + off) = v;
                }
    }
}

// ---------------------------------------------------------------------------
// Split fp32 -> bf16 hi/lo planes
// ---------------------------------------------------------------------------
__global__ void __launch_bounds__(256) split_kernel(
    const float4* __restrict__ s, __nv_bfloat162* __restrict__ hi,
    __nv_bfloat162* __restrict__ lo, int n4)
{
    for (int i = blockIdx.x * 256 + threadIdx.x; i < n4; i += gridDim.x * 256) {
        float4 x = s[i];
        __nv_bfloat162 h0 = __floats2bfloat162_rn(x.x, x.y);
        __nv_bfloat162 h1 = __floats2bfloat162_rn(x.z, x.w);
        __nv_bfloat162 l0 = __floats2bfloat162_rn(x.x - __low2float(h0),
                                                  x.y - __high2float(h0));
        __nv_bfloat162 l1 = __floats2bfloat162_rn(x.z - __low2float(h1),
                                                  x.w - __high2float(h1));
        hi[2 * i] = h0; hi[2 * i + 1] = h1;
        lo[2 * i] = l0; lo[2 * i + 1] = l1;
    }
}

// ---------------------------------------------------------------------------
// V transpose per head on planes: [B,S,D] -> [B,H,DH,S]
// ---------------------------------------------------------------------------
__global__ void __launch_bounds__(256) transpose_v_kernel(
    const __nv_bfloat16* __restrict__ v, __nv_bfloat16* __restrict__ vt, long pl)
{
    __shared__ __nv_bfloat16 t0[32][33], t1[32][33];
    const int bh = blockIdx.z, b = bh / NH, h = bh % NH;
    const int j0 = blockIdx.x * 32, d0 = blockIdx.y * 32;
    const int tx = threadIdx.x, ty = threadIdx.y;  // 32 x 8
    const __nv_bfloat16* s0 = v + (long)b * NS * ND + h * NDH;
    #pragma unroll
    for (int i = 0; i < 4; ++i) {
        int j = j0 + ty + i * 8;
        long o = (long)j * ND + d0 + tx;
        t0[ty + i * 8][tx] = s0[o];
        t1[ty + i * 8][tx] = s0[o + pl];
    }
    __syncthreads();
    __nv_bfloat16* dst = vt + (long)bh * NDH * NS;
    #pragma unroll
    for (int i = 0; i < 4; ++i) {
        int d = d0 + ty + i * 8;
        long o = (long)d * NS + j0 + tx;
        dst[o]      = t0[tx][ty + i * 8];
        dst[o + pl] = t1[tx][ty + i * 8];
    }
}

// ---------------------------------------------------------------------------
// Combine (dots + shifted pos), mask, softmax; write attn as bf16 hi/lo planes.
// shift(pos)[i,j] = pos[i, j-i+S-1] for j<=i, else 0.
// ---------------------------------------------------------------------------
__global__ void __launch_bounds__(256) softmax_kernel(
    const int* __restrict__ mask, const float* __restrict__ dots,
    const float* __restrict__ pos, __nv_bfloat16* __restrict__ attn, long attnPl)
{
    const int i = blockIdx.x, bh = blockIdx.y, b = bh / NH;
    const long base = ((long)bh * NS + i) * NS;
    const float* row  = dots + base;
    const float* prow = pos + base;
    const int tid = threadIdx.x;
    const int mi = mask[b * NS + i];
    const int j0 = tid * 4;

    float4 x = *(const float4*)(row + j0);
    float v[4] = {x.x, x.y, x.z, x.w};
    const int4 m4 = *(const int4*)(mask + b * NS + j0);
    const int mj[4] = {m4.x, m4.y, m4.z, m4.w};
    float mx = -3.0e38f;
    #pragma unroll
    for (int u = 0; u < 4; ++u) {
        int j = j0 + u;
        if (j <= i) v[u] += prow[NS - 1 + j - i];
        if (mi == 0 || mj[u] == 0) v[u] = -1.0e9f;
        mx = fmaxf(mx, v[u]);
    }

    __shared__ float red[256];
    red[tid] = mx;
    __syncthreads();
    for (int s = 128; s > 0; s >>= 1) {
        if (tid < s) red[tid] = fmaxf(red[tid], red[tid + s]);
        __syncthreads();
    }
    mx = red[0];
    __syncthreads();

    float sum = 0.0f;
    #pragma unroll
    for (int u = 0; u < 4; ++u) { v[u] = __expf(v[u] - mx); sum += v[u]; }
    red[tid] = sum;
    __syncthreads();
    for (int s = 128; s > 0; s >>= 1) {
        if (tid < s) red[tid] += red[tid + s];
        __syncthreads();
    }
    const float inv = 1.0f / red[0];

    #pragma unroll
    for (int u = 0; u < 4; u += 2) {
        float p0 = v[u] * inv, p1 = v[u + 1] * inv;
        __nv_bfloat162 hi = __floats2bfloat162_rn(p0, p1);
        __nv_bfloat162 lo = __floats2bfloat162_rn(p0 - __low2float(hi),
                                                  p1 - __high2float(hi));
        *(__nv_bfloat162*)(attn + base + j0 + u)          = hi;
        *(__nv_bfloat162*)(attn + attnPl + base + j0 + u) = lo;
    }
}

// ---------------------------------------------------------------------------
extern "C" void kernel_launch(void* const* d_in, const int* in_sizes, int n_in,
                              void* d_out, int out_size)
{
    const float* query = (const float*)d_in[0];
    const float* key   = (const float*)d_in[1];
    const float* value = (const float*)d_in[2];
    const int*   mask  = (const int*)  d_in[3];
    const float* pe    = (const float*)d_in[4];
    const float* Wq    = (const float*)d_in[5];
    const float* Wk    = (const float*)d_in[6];
    const float* Wv    = (const float*)d_in[7];
    const float* Wo    = (const float*)d_in[8];
    float* out = (float*)d_out;

    void *vx, *vy, *vz, *vq, *vk, *vv, *vvt, *vctx, *vwq, *vwk, *vwv, *vwo,
         *vpe, *vattn, *vdots, *vpos;
    cudaGetSymbolAddress(&vx, p_x);     cudaGetSymbolAddress(&vy, p_y);
    cudaGetSymbolAddress(&vz, p_z);     cudaGetSymbolAddress(&vq, p_q);
    cudaGetSymbolAddress(&vk, p_k);     cudaGetSymbolAddress(&vv, p_v);
    cudaGetSymbolAddress(&vvt, p_vt);   cudaGetSymbolAddress(&vctx, p_ctx);
    cudaGetSymbolAddress(&vwq, p_wq);   cudaGetSymbolAddress(&vwk, p_wk);
    cudaGetSymbolAddress(&vwv, p_wv);   cudaGetSymbolAddress(&vwo, p_wo);
    cudaGetSymbolAddress(&vpe, p_pe);   cudaGetSymbolAddress(&vattn, p_attn);
    cudaGetSymbolAddress(&vdots, g_dots4); cudaGetSymbolAddress(&vpos, g_pos4);

    __nv_bfloat16* bq   = (__nv_bfloat16*)vq;
    __nv_bfloat16* bk   = (__nv_bfloat16*)vk;
    __nv_bfloat16* bv   = (__nv_bfloat16*)vv;
    __nv_bfloat16* bvt  = (__nv_bfloat16*)vvt;
    __nv_bfloat16* bctx = (__nv_bfloat16*)vctx;
    __nv_bfloat16* batt = (__nv_bfloat16*)vattn;
    float* dots = (float*)vdots;
    float* pos  = (float*)vpos;

    auto SPL = [](const float* src, void* pl, long n) {
        int n4 = (int)(n / 4);
        split_kernel<<<(n4 + 255) / 256 < 4096 ? (n4 + 255) / 256 : 4096, 256>>>(
            (const float4*)src, (__nv_bfloat162*)pl,
            (__nv_bfloat162*)((__nv_bfloat16*)pl + n), n4);
    };
    SPL(query, vx, E_X);  SPL(key, vy, E_X);  SPL(value, vz, E_X);
    SPL(Wq, vwq, E_W);    SPL(Wk, vwk, E_W);  SPL(Wv, vwv, E_W);
    SPL(Wo, vwo, E_W);    SPL(pe, vpe, E_PE);

    const int SM128 = 2 * (20480 + 2 * 128 * 80);  // 81920
    const int SM64  = 2 * (20480 + 2 * 64 * 80);   // 61440
    cudaFuncSetAttribute(gemm2<128, true>,  cudaFuncAttributeMaxDynamicSharedMemorySize, SM128);
    cudaFuncSetAttribute(gemm2<128, false>, cudaFuncAttributeMaxDynamicSharedMemorySize, SM128);
    cudaFuncSetAttribute(gemm2<64, true>,   cudaFuncAttributeMaxDynamicSharedMemorySize, SM64);

    const dim3 th(256);
    const long SD  = (long)NS * ND;
    const long SS  = (long)NS * NS;
    const long HSS = (long)NH * SS;

    // Projections -> q,k,v planes
    gemm2<128, true><<<dim3(8, 32, 1), th, SM128>>>(
        (__nv_bfloat16*)vx, (__nv_bfloat16*)vwq, vq, ND, ND, ND, ND,
        0, 0, 0, 0, 0, 0, E_X, E_W, E_X, 1.0f, 0);
    gemm2<128, true><<<dim3(8, 32, 1), th, SM128>>>(
        (__nv_bfloat16*)vy, (__nv_bfloat16*)vwk, vk, ND, ND, ND, ND,
        0, 0, 0, 0, 0, 0, E_X, E_W, E_X, 1.0f, 0);
    gemm2<128, true><<<dim3(8, 32, 1), th, SM128>>>(
        (__nv_bfloat16*)vz, (__nv_bfloat16*)vwv, vv, ND, ND, ND, ND,
        0, 0, 0, 0, 0, 0, E_X, E_W, E_X, 1.0f, 0);

    // dots = (q @ k^T) * DH^-0.5   (fp32 out)
    gemm2<128, false><<<dim3(8, 8, NB * NH), th, SM128>>>(
        bq, bk, vdots, NDH, ND, ND, NS,
        SD, NDH, SD, NDH, HSS, SS, E_X, E_X, 0, 0.125f, 0);

    // pos = (q @ pe^T) * DH^0.5   (fp32 out, triangular grid)
    gemm2<128, false><<<dim3(8, 8, NB * NH), th, SM128>>>(
        bq, (__nv_bfloat16*)vpe, vpos, NDH, ND, NDH, NS,
        SD, NDH, 0, (long)NS * NDH, HSS, SS, E_X, E_PE, 0, 8.0f, 1);

    // combine + skew + mask + softmax -> attn planes
    softmax_kernel<<<dim3(NS, NB * NH), th>>>(mask, dots, pos, batt, E_ATT);

    // v^T per head (planes)
    transpose_v_kernel<<<dim3(32, 2, NB * NH), dim3(32, 8)>>>(bv, bvt, E_X);

    // ctx = attn @ vt^T -> ctx planes
    gemm2<64, true><<<dim3(1, 8, NB * NH), th, SM64>>>(
        batt, bvt, vctx, NS, NS, NS, ND,
        HSS, SS, (long)NH * NDH * NS, (long)NDH * NS, SD, (long)NDH,
        E_ATT, E_X, E_X, 1.0f, 0);

    // out = ctx @ Wo^T (fp32)
    gemm2<128, false><<<dim3(8, 32, 1), th, SM128>>>(
        bctx, (__nv_bfloat16*)vwo, out, ND, ND, ND, ND,
        0, 0, 0, 0, 0, 0, E_X, E_W, 0, 1.0f, 0);
}

// round 5
// speedup vs baseline: 2.6271x; 1.1949x over previous
#include <cuda_runtime.h>
#include <cuda_bf16.h>
#include <cstdint>

#define NB 4
#define NS 1024
#define ND 1024
#define NH 16
#define NDH 64

#define E_X   ((long)NB * NS * ND)       // 4194304
#define E_W   ((long)ND * ND)            // 1048576
#define E_PE  ((long)NH * NS * NDH)      // 1048576
#define E_ATT ((long)NB * NH * NS * NS)  // 67108864

// Plane buffers (hi at [0,E), lo at [E,2E)), uint4-declared for 16B alignment.
__device__ uint4 p_x[E_X / 4],  p_y[E_X / 4],  p_z[E_X / 4];
__device__ uint4 p_q[E_X / 4],  p_k[E_X / 4],  p_v[E_X / 4];
__device__ uint4 p_vt[E_X / 4], p_ctx[E_X / 4];
__device__ uint4 p_wq[E_W / 4], p_wk[E_W / 4], p_wv[E_W / 4], p_wo[E_W / 4];
__device__ uint4 p_pe[E_PE / 4];
__device__ float g_pshift[E_ATT];        // shifted pos logits (lower triangle valid)

// ---------------------------------------------------------------------------
// Base-ISA helpers
// ---------------------------------------------------------------------------
static __device__ __forceinline__ uint32_t smem_u32(const void* p) {
    uint32_t a;
    asm("{ .reg .u64 t; cvta.to.shared.u64 t, %1; cvt.u32.u64 %0, t; }"
        : "=r"(a) : "l"(p));
    return a;
}
static __device__ __forceinline__ void ldsm_x4(uint32_t* r, uint32_t addr) {
    asm volatile("ldmatrix.sync.aligned.m8n8.x4.shared.b16 {%0,%1,%2,%3}, [%4];"
                 : "=r"(r[0]), "=r"(r[1]), "=r"(r[2]), "=r"(r[3]) : "r"(addr));
}
static __device__ __forceinline__ void mma_bf16(float* c, const uint32_t* a,
                                                const uint32_t* b) {
    asm volatile(
        "mma.sync.aligned.m16n8k16.row.col.f32.bf16.bf16.f32 "
        "{%0,%1,%2,%3}, {%4,%5,%6,%7}, {%8,%9}, {%0,%1,%2,%3};"
        : "+f"(c[0]), "+f"(c[1]), "+f"(c[2]), "+f"(c[3])
        : "r"(a[0]), "r"(a[1]), "r"(a[2]), "r"(a[3]), "r"(b[0]), "r"(b[1]));
}
static __device__ __forceinline__ void cpa16(uint32_t d, const void* s) {
    asm volatile("cp.async.cg.shared.global [%0], [%1], 16;" :: "r"(d), "l"(s));
}
static __device__ __forceinline__ void cpa_commit() {
    asm volatile("cp.async.commit_group;" ::: "memory");
}
template <int N> static __device__ __forceinline__ void cpa_wait() {
    asm volatile("cp.async.wait_group %0;" :: "n"(N) : "memory");
}
static __device__ __forceinline__ uint32_t packbf(float x, float y) {
    __nv_bfloat162 t = __floats2bfloat162_rn(x, y);
    return *(uint32_t*)&t;
}

// ---------------------------------------------------------------------------
// GEMM: C = alpha * A @ B^T, bf16 hi/lo planes in, bf16x3 accumulation.
// MODE 0: fp32 out.  MODE 1: bf16 hi/lo plane out.  MODE 2: shifted fp32 out
// (C[i, c-(NS-1)+i] = val, predicated j>=0) for the Music-Transformer skew.
// ---------------------------------------------------------------------------
template <int BN, int MODE>
__global__ void __launch_bounds__(256, 2) gemm2(
    const __nv_bfloat16* __restrict__ A, const __nv_bfloat16* __restrict__ Bp,
    void* __restrict__ Cv,
    int K, int lda, int ldb, int ldc,
    long aOut, long aIn, long bOut, long bIn, long cOut, long cIn,
    long aPl, long bPl, long cPl, float alpha, int tri)
{
    constexpr int BM = 128, LDE = 40;
    constexpr int WM = 2;                         // warps along M
    constexpr int MT = (BM / WM) / 16;            // 4
    constexpr int AH = 0;
    constexpr int AL = BM * LDE * 2;
    constexpr int BH = 2 * AL;
    constexpr int BL = BH + BN * LDE * 2;
    constexpr int STAGE = BH + 2 * BN * LDE * 2;

    if (tri && (int)(blockIdx.x * BN + blockIdx.y * BM) + 255 < NS) return;

    extern __shared__ __align__(128) char sm[];
    const uint32_t sb = smem_u32(sm);

    const int tid = threadIdx.x, wid = tid >> 5, lane = tid & 31;
    const int wm = wid % WM, wn = wid / WM;
    const int z = blockIdx.z, zo = z / NH, zi = z % NH;

    const __nv_bfloat16* Ab = A + (long)zo * aOut + (long)zi * aIn
                              + (long)(blockIdx.y * BM) * lda;
    const __nv_bfloat16* Bb = Bp + (long)zo * bOut + (long)zi * bIn
                              + (long)(blockIdx.x * BN) * ldb;

    auto issue = [&](int s, int kt) {
        const uint32_t st = sb + s * STAGE;
        #pragma unroll
        for (int t = 0; t < 2; ++t) {
            int r = (tid + t * 256) >> 2, sg = tid & 3;
            const __nv_bfloat16* g = Ab + (long)r * lda + kt + sg * 8;
            uint32_t d = st + r * 80 + sg * 16;
            cpa16(d + AH, g);
            cpa16(d + AL, g + aPl);
        }
        #pragma unroll
        for (int t = 0; t < BN / 64; ++t) {
            int r = (tid + t * 256) >> 2, sg = tid & 3;
            const __nv_bfloat16* g = Bb + (long)r * ldb + kt + sg * 8;
            uint32_t d = st + r * 80 + sg * 16;
            cpa16(d + BH, g);
            cpa16(d + BL, g + bPl);
        }
        cpa_commit();
    };

    const uint32_t aRelH = AH +
        (uint32_t)(((wm * MT * 16 + (lane & 15)) * LDE + (lane >> 4) * 8) * 2);
    const uint32_t aRelL = aRelH + (AL - AH);
    const int brow = (lane & 7) | ((lane >> 1) & 8);
    const uint32_t bRelH = BH +
        (uint32_t)(((wn * 32 + brow) * LDE + ((lane >> 3) & 1) * 8) * 2);
    const uint32_t bRelL = bRelH + (BL - BH);

    float acc[MT][4][4] = {};
    issue(0, 0);

    const int nch = K >> 5;
    for (int c = 0; c < nch; ++c) {
        if (c + 1 < nch) { issue((c + 1) & 1, (c + 1) << 5); cpa_wait<1>(); }
        else             { cpa_wait<0>(); }
        __syncthreads();
        const uint32_t s0 = sb + (c & 1) * STAGE;
        #pragma unroll
        for (int ks = 0; ks < 2; ++ks) {
            uint32_t ah[MT][4], al[MT][4], bh[2][4], bl[2][4];
            #pragma unroll
            for (int mt = 0; mt < MT; ++mt) {
                ldsm_x4(ah[mt], s0 + aRelH + mt * (16 * LDE * 2) + ks * 32);
                ldsm_x4(al[mt], s0 + aRelL + mt * (16 * LDE * 2) + ks * 32);
            }
            #pragma unroll
            for (int nt2 = 0; nt2 < 2; ++nt2) {
                ldsm_x4(bh[nt2], s0 + bRelH + nt2 * (16 * LDE * 2) + ks * 32);
                ldsm_x4(bl[nt2], s0 + bRelL + nt2 * (16 * LDE * 2) + ks * 32);
            }
            #pragma unroll
            for (int mt = 0; mt < MT; ++mt)
                #pragma unroll
                for (int nt = 0; nt < 4; ++nt) {
                    float* cc = acc[mt][nt];
                    const uint32_t* bhp = &bh[nt >> 1][(nt & 1) * 2];
                    const uint32_t* blp = &bl[nt >> 1][(nt & 1) * 2];
                    mma_bf16(cc, ah[mt], bhp);
                    mma_bf16(cc, ah[mt], blp);
                    mma_bf16(cc, al[mt], bhp);
                }
        }
        __syncthreads();
    }

    const int r0 = wm * (MT * 16) + (lane >> 2);
    const int c0 = wn * 32 + (lane & 3) * 2;
    if (MODE == 1) {
        __nv_bfloat16* Ch = (__nv_bfloat16*)Cv + (long)zo * cOut + (long)zi * cIn
                            + (long)(blockIdx.y * BM) * ldc + blockIdx.x * BN;
        #pragma unroll
        for (int mt = 0; mt < MT; ++mt)
            #pragma unroll
            for (int nt = 0; nt < 4; ++nt)
                #pragma unroll
                for (int h = 0; h < 2; ++h) {
                    long off = (long)(r0 + mt * 16 + h * 8) * ldc + c0 + nt * 8;
                    float x0 = acc[mt][nt][h * 2 + 0] * alpha;
                    float x1 = acc[mt][nt][h * 2 + 1] * alpha;
                    __nv_bfloat162 hi = __floats2bfloat162_rn(x0, x1);
                    __nv_bfloat162 lo = __floats2bfloat162_rn(
                        x0 - __low2float(hi), x1 - __high2float(hi));
                    *(__nv_bfloat162*)(Ch + off)       = hi;
                    *(__nv_bfloat162*)(Ch + off + cPl) = lo;
                }
    } else if (MODE == 0) {
        float* Cf = (float*)Cv + (long)zo * cOut + (long)zi * cIn
                    + (long)(blockIdx.y * BM) * ldc + blockIdx.x * BN;
        #pragma unroll
        for (int mt = 0; mt < MT; ++mt)
            #pragma unroll
            for (int nt = 0; nt < 4; ++nt)
                #pragma unroll
                for (int h = 0; h < 2; ++h) {
                    long off = (long)(r0 + mt * 16 + h * 8) * ldc + c0 + nt * 8;
                    float2 v = make_float2(acc[mt][nt][h * 2 + 0] * alpha,
                                           acc[mt][nt][h * 2 + 1] * alpha);
                    *(float2*)(Cf + off) = v;
                }
    } else {  // MODE 2: shifted store  Cshift[i, c-(NS-1)+i]
        float* Cf = (float*)Cv + (long)zo * cOut + (long)zi * cIn;
        const int ig0 = blockIdx.y * BM + r0;
        const int cg0 = blockIdx.x * BN + c0;
        #pragma unroll
        for (int mt = 0; mt < MT; ++mt)
            #pragma unroll
            for (int h = 0; h < 2; ++h) {
                int ig = ig0 + mt * 16 + h * 8;
                #pragma unroll
                for (int nt = 0; nt < 4; ++nt) {
                    int j = cg0 + nt * 8 - (NS - 1) + ig;
                    float x0 = acc[mt][nt][h * 2 + 0] * alpha;
                    float x1 = acc[mt][nt][h * 2 + 1] * alpha;
                    if (j >= 0)     Cf[(long)ig * NS + j]     = x0;
                    if (j + 1 >= 0) Cf[(long)ig * NS + j + 1] = x1;
                }
            }
    }
}

// ---------------------------------------------------------------------------
// Fused attention: per (i-tile of 128, bh): online-softmax flash loop over j.
// logit = 0.125*(q@k^T) + Pshift (j<=i) + mask_bias; O = softmax @ v.
// 8 warps x 16 rows; j-tiles of 64; k/vt/pshift double-buffered cp.async.
// ---------------------------------------------------------------------------
constexpr int F_SQ  = 0;                         // q hi/lo: 2 * 128*72*2
constexpr int F_SQP = 128 * 72 * 2;              // 18432 per plane
constexpr int F_SK  = 2 * F_SQP;                 // 36864
constexpr int F_KST = 2 * (64 * 72 * 2);         // 18432 per stage (hi+lo)
constexpr int F_KP  = 64 * 72 * 2;               // 9216
constexpr int F_SV  = F_SK + 2 * F_KST;          // 73728
constexpr int F_SP  = F_SV + 2 * F_KST;          // 110592
constexpr int F_PST = 128 * 68 * 4;              // 34816 per stage
constexpr int F_SM  = F_SP + 2 * F_PST;          // 180224 (mask bias)
constexpr int F_TOT = F_SM + NS * 4;             // 184320

__global__ void __launch_bounds__(256, 1) fused_attn(
    const __nv_bfloat16* __restrict__ q, const __nv_bfloat16* __restrict__ k,
    const __nv_bfloat16* __restrict__ vt, const float* __restrict__ pshift,
    const int* __restrict__ mask, __nv_bfloat16* __restrict__ ctx)
{
    extern __shared__ __align__(128) char sm[];
    const uint32_t sb = smem_u32(sm);
    const int tid = threadIdx.x, wid = tid >> 5, lane = tid & 31;
    const int i0 = blockIdx.x * 128;
    const int bh = blockIdx.y, b = bh / NH, h = bh % NH;

    const __nv_bfloat16* qg  = q + (long)b * NS * ND + (long)i0 * ND + h * NDH;
    const __nv_bfloat16* kg  = k + (long)b * NS * ND + h * NDH;
    const __nv_bfloat16* vtg = vt + (long)bh * NDH * NS;
    const float* pg = pshift + (long)bh * NS * NS + (long)i0 * NS;

    // mask bias to smem
    float* mbias = (float*)(sm + F_SM);
    for (int j = tid; j < NS; j += 256)
        mbias[j] = mask[b * NS + j] ? 0.0f : -1.5e9f;

    // Q -> smem (cp.async, group 0)
    #pragma unroll
    for (int t = 0; t < 8; ++t) {
        int idx = tid + t * 256;
        int pl = idx >> 10, rem = idx & 1023, r = rem >> 3, ch = rem & 7;
        cpa16(sb + F_SQ + pl * F_SQP + (r * 72 + ch * 8) * 2,
              qg + (long)pl * E_X + (long)r * ND + ch * 8);
    }
    cpa_commit();

    auto issue = [&](int jt) {
        const int st = jt & 1, j0 = jt * 64;
        #pragma unroll
        for (int t = 0; t < 4; ++t) {   // K tile
            int idx = tid + t * 256;
            int pl = idx >> 9, rem = idx & 511, r = rem >> 3, ch = rem & 7;
            cpa16(sb + F_SK + st * F_KST + pl * F_KP + (r * 72 + ch * 8) * 2,
                  kg + (long)pl * E_X + (long)(j0 + r) * ND + ch * 8);
        }
        #pragma unroll
        for (int t = 0; t < 4; ++t) {   // VT tile
            int idx = tid + t * 256;
            int pl = idx >> 9, rem = idx & 511, d = rem >> 3, ch = rem & 7;
            cpa16(sb + F_SV + st * F_KST + pl * F_KP + (d * 72 + ch * 8) * 2,
                  vtg + (long)pl * E_X + (long)d * NS + j0 + ch * 8);
        }
        if (j0 <= i0 + 127) {
            #pragma unroll
            for (int t = 0; t < 8; ++t) {   // Pshift tile (fp32)
                int idx = tid + t * 256;
                int r = idx >> 4, ch = idx & 15;
                cpa16(sb + F_SP + st * F_PST + (r * 68 + ch * 4) * 4,
                      pg + (long)r * NS + j0 + ch * 4);
            }
        }
        cpa_commit();
    };

    issue(0);
    cpa_wait<1>();
    __syncthreads();

    // Q fragments (once)
    uint32_t qah[4][4], qal[4][4];
    {
        uint32_t base = sb + F_SQ + ((wid * 16 + (lane & 15)) * 72 + (lane >> 4) * 8) * 2;
        #pragma unroll
        for (int kt = 0; kt < 4; ++kt) {
            ldsm_x4(qah[kt], base + kt * 32);
            ldsm_x4(qal[kt], base + F_SQP + kt * 32);
        }
    }

    const int rA = wid * 16 + (lane >> 2);  // local row (and rA+8)
    const int iA = i0 + rA, iB = iA + 8;
    const int miA = mask[b * NS + iA], miB = mask[b * NS + iB];
    const int brow = (lane & 7) | ((lane >> 1) & 8);
    const int bcol = ((lane >> 3) & 1) * 8;

    float oacc[8][4] = {};
    float mA = -1.0e30f, mB = -1.0e30f, lA = 0.0f, lB = 0.0f;

    for (int jt = 0; jt < 16; ++jt) {
        if (jt + 1 < 16) { issue(jt + 1); cpa_wait<1>(); }
        else             { cpa_wait<0>(); }
        __syncthreads();

        const int st = jt & 1, j0 = jt * 64;
        const uint32_t kb = sb + F_SK + st * F_KST;
        const uint32_t vb = sb + F_SV + st * F_KST;
        const bool anyP = (j0 <= i0 + 127);
        const float* psm = (const float*)(sm + F_SP + st * F_PST);

        // ---- S = q @ k^T (bf16x3) ----
        float sacc[8][4] = {};
        #pragma unroll
        for (int kt = 0; kt < 4; ++kt) {
            uint32_t bhf[4][4], blf[4][4];
            #pragma unroll
            for (int p = 0; p < 4; ++p) {
                ldsm_x4(bhf[p], kb + ((p * 16 + brow) * 72 + bcol + kt * 16) * 2);
                ldsm_x4(blf[p], kb + F_KP + ((p * 16 + brow) * 72 + bcol + kt * 16) * 2);
            }
            #pragma unroll
            for (int nt = 0; nt < 8; ++nt) {
                const uint32_t* bp = &bhf[nt >> 1][(nt & 1) * 2];
                const uint32_t* lp = &blf[nt >> 1][(nt & 1) * 2];
                mma_bf16(sacc[nt], qah[kt], bp);
                mma_bf16(sacc[nt], qah[kt], lp);
                mma_bf16(sacc[nt], qal[kt], bp);
            }
        }

        // ---- logits: scale + pshift + mask ----
        #pragma unroll
        for (int nt = 0; nt < 8; ++nt) {
            int jl = nt * 8 + (lane & 3) * 2;
            int jg = j0 + jl;
            float p0A = 0, p1A = 0, p0B = 0, p1B = 0;
            if (anyP) {
                float2 fa = *(const float2*)(psm + rA % 128 * 0 + (wid * 16 + (lane >> 2)) * 68 + jl);
                float2 fb = *(const float2*)(psm + (wid * 16 + (lane >> 2) + 8) * 68 + jl);
                p0A = (jg     <= iA) ? fa.x : 0.0f;
                p1A = (jg + 1 <= iA) ? fa.y : 0.0f;
                p0B = (jg     <= iB) ? fb.x : 0.0f;
                p1B = (jg + 1 <= iB) ? fb.y : 0.0f;
            }
            float b0 = mbias[jg], b1 = mbias[jg + 1];
            sacc[nt][0] = miA ? fmaf(sacc[nt][0], 0.125f, p0A) + b0 : -1.0e9f;
            sacc[nt][1] = miA ? fmaf(sacc[nt][1], 0.125f, p1A) + b1 : -1.0e9f;
            sacc[nt][2] = miB ? fmaf(sacc[nt][2], 0.125f, p0B) + b0 : -1.0e9f;
            sacc[nt][3] = miB ? fmaf(sacc[nt][3], 0.125f, p1B) + b1 : -1.0e9f;
        }

        // ---- online softmax update ----
        float rmA = -1.0e30f, rmB = -1.0e30f;
        #pragma unroll
        for (int nt = 0; nt < 8; ++nt) {
            rmA = fmaxf(rmA, fmaxf(sacc[nt][0], sacc[nt][1]));
            rmB = fmaxf(rmB, fmaxf(sacc[nt][2], sacc[nt][3]));
        }
        rmA = fmaxf(rmA, __shfl_xor_sync(0xffffffffu, rmA, 1));
        rmA = fmaxf(rmA, __shfl_xor_sync(0xffffffffu, rmA, 2));
        rmB = fmaxf(rmB, __shfl_xor_sync(0xffffffffu, rmB, 1));
        rmB = fmaxf(rmB, __shfl_xor_sync(0xffffffffu, rmB, 2));

        float mnA = fmaxf(mA, rmA), mnB = fmaxf(mB, rmB);
        float alA = __expf(mA - mnA), alB = __expf(mB - mnB);
        mA = mnA; mB = mnB;

        float rsA = 0.0f, rsB = 0.0f;
        #pragma unroll
        for (int nt = 0; nt < 8; ++nt) {
            sacc[nt][0] = __expf(sacc[nt][0] - mnA);
            sacc[nt][1] = __expf(sacc[nt][1] - mnA);
            sacc[nt][2] = __expf(sacc[nt][2] - mnB);
            sacc[nt][3] = __expf(sacc[nt][3] - mnB);
            rsA += sacc[nt][0] + sacc[nt][1];
            rsB += sacc[nt][2] + sacc[nt][3];
        }
        rsA += __shfl_xor_sync(0xffffffffu, rsA, 1);
        rsA += __shfl_xor_sync(0xffffffffu, rsA, 2);
        rsB += __shfl_xor_sync(0xffffffffu, rsB, 1);
        rsB += __shfl_xor_sync(0xffffffffu, rsB, 2);
        lA = lA * alA + rsA;
        lB = lB * alB + rsB;
        #pragma unroll
        for (int nt = 0; nt < 8; ++nt) {
            oacc[nt][0] *= alA; oacc[nt][1] *= alA;
            oacc[nt][2] *= alB; oacc[nt][3] *= alB;
        }

        // ---- pack P into A-fragments (hi/lo) ----
        uint32_t pah[4][4], pal[4][4];
        #pragma unroll
        for (int kt = 0; kt < 4; ++kt) {
            const float* e = sacc[2 * kt];
            const float* o = sacc[2 * kt + 1];
            pah[kt][0] = packbf(e[0], e[1]); pah[kt][1] = packbf(e[2], e[3]);
            pah[kt][2] = packbf(o[0], o[1]); pah[kt][3] = packbf(o[2], o[3]);
            #pragma unroll
            for (int u = 0; u < 4; ++u) {
                __nv_bfloat162 hv = *(__nv_bfloat162*)&pah[kt][u];
                const float* src = (u < 2) ? e : o;
                float x0 = src[(u & 1) * 2]     - __low2float(hv);
                float x1 = src[(u & 1) * 2 + 1] - __high2float(hv);
                pal[kt][u] = packbf(x0, x1);
            }
        }

        // ---- O += P @ V (bf16x3) ----
        #pragma unroll
        for (int kt = 0; kt < 4; ++kt) {
            uint32_t vhf[4][4], vlf[4][4];
            #pragma unroll
            for (int p = 0; p < 4; ++p) {
                ldsm_x4(vhf[p], vb + ((p * 16 + brow) * 72 + bcol + kt * 16) * 2);
                ldsm_x4(vlf[p], vb + F_KP + ((p * 16 + brow) * 72 + bcol + kt * 16) * 2);
            }
            #pragma unroll
            for (int nt = 0; nt < 8; ++nt) {
                const uint32_t* bp = &vhf[nt >> 1][(nt & 1) * 2];
                const uint32_t* lp = &vlf[nt >> 1][(nt & 1) * 2];
                mma_bf16(oacc[nt], pah[kt], bp);
                mma_bf16(oacc[nt], pah[kt], lp);
                mma_bf16(oacc[nt], pal[kt], bp);
            }
        }
        __syncthreads();
    }

    // ---- epilogue: normalize, split hi/lo, store ctx planes ----
    const float ivA = 1.0f / lA, ivB = 1.0f / lB;
    __nv_bfloat16* cg = ctx + (long)b * NS * ND + (long)iA * ND + h * NDH;
    __nv_bfloat16* cg2 = cg + 8 * ND;
    #pragma unroll
    for (int nt = 0; nt < 8; ++nt) {
        int c = nt * 8 + (lane & 3) * 2;
        float a0 = oacc[nt][0] * ivA, a1 = oacc[nt][1] * ivA;
        float b0 = oacc[nt][2] * ivB, b1 = oacc[nt][3] * ivB;
        __nv_bfloat162 ha = __floats2bfloat162_rn(a0, a1);
        __nv_bfloat162 la = __floats2bfloat162_rn(a0 - __low2float(ha),
                                                  a1 - __high2float(ha));
        __nv_bfloat162 hb = __floats2bfloat162_rn(b0, b1);
        __nv_bfloat162 lb = __floats2bfloat162_rn(b0 - __low2float(hb),
                                                  b1 - __high2float(hb));
        *(__nv_bfloat162*)(cg + c)        = ha;
        *(__nv_bfloat162*)(cg + E_X + c)  = la;
        *(__nv_bfloat162*)(cg2 + c)       = hb;
        *(__nv_bfloat162*)(cg2 + E_X + c) = lb;
    }
}

// ---------------------------------------------------------------------------
// Split fp32 -> bf16 hi/lo planes
// ---------------------------------------------------------------------------
__global__ void __launch_bounds__(256) split_kernel(
    const float4* __restrict__ s, __nv_bfloat162* __restrict__ hi,
    __nv_bfloat162* __restrict__ lo, int n4)
{
    for (int i = blockIdx.x * 256 + threadIdx.x; i < n4; i += gridDim.x * 256) {
        float4 x = s[i];
        __nv_bfloat162 h0 = __floats2bfloat162_rn(x.x, x.y);
        __nv_bfloat162 h1 = __floats2bfloat162_rn(x.z, x.w);
        __nv_bfloat162 l0 = __floats2bfloat162_rn(x.x - __low2float(h0),
                                                  x.y - __high2float(h0));
        __nv_bfloat162 l1 = __floats2bfloat162_rn(x.z - __low2float(h1),
                                                  x.w - __high2float(h1));
        hi[2 * i] = h0; hi[2 * i + 1] = h1;
        lo[2 * i] = l0; lo[2 * i + 1] = l1;
    }
}

// ---------------------------------------------------------------------------
// V transpose per head on planes: [B,S,D] -> [B,H,DH,S]
// ---------------------------------------------------------------------------
__global__ void __launch_bounds__(256) transpose_v_kernel(
    const __nv_bfloat16* __restrict__ v, __nv_bfloat16* __restrict__ vt, long pl)
{
    __shared__ __nv_bfloat16 t0[32][33], t1[32][33];
    const int bh = blockIdx.z, b = bh / NH, h = bh % NH;
    const int j0 = blockIdx.x * 32, d0 = blockIdx.y * 32;
    const int tx = threadIdx.x, ty = threadIdx.y;
    const __nv_bfloat16* s0 = v + (long)b * NS * ND + h * NDH;
    #pragma unroll
    for (int i = 0; i < 4; ++i) {
        int j = j0 + ty + i * 8;
        long o = (long)j * ND + d0 + tx;
        t0[ty + i * 8][tx] = s0[o];
        t1[ty + i * 8][tx] = s0[o + pl];
    }
    __syncthreads();
    __nv_bfloat16* dst = vt + (long)bh * NDH * NS;
    #pragma unroll
    for (int i = 0; i < 4; ++i) {
        int d = d0 + ty + i * 8;
        long o = (long)d * NS + j0 + tx;
        dst[o]      = t0[tx][ty + i * 8];
        dst[o + pl] = t1[tx][ty + i * 8];
    }
}

// ---------------------------------------------------------------------------
extern "C" void kernel_launch(void* const* d_in, const int* in_sizes, int n_in,
                              void* d_out, int out_size)
{
    const float* query = (const float*)d_in[0];
    const float* key   = (const float*)d_in[1];
    const float* value = (const float*)d_in[2];
    const int*   mask  = (const int*)  d_in[3];
    const float* pe    = (const float*)d_in[4];
    const float* Wq    = (const float*)d_in[5];
    const float* Wk    = (const float*)d_in[6];
    const float* Wv    = (const float*)d_in[7];
    const float* Wo    = (const float*)d_in[8];
    float* out = (float*)d_out;

    void *vx, *vy, *vz, *vq, *vk, *vv, *vvt, *vctx, *vwq, *vwk, *vwv, *vwo,
         *vpe, *vps;
    cudaGetSymbolAddress(&vx, p_x);     cudaGetSymbolAddress(&vy, p_y);
    cudaGetSymbolAddress(&vz, p_z);     cudaGetSymbolAddress(&vq, p_q);
    cudaGetSymbolAddress(&vk, p_k);     cudaGetSymbolAddress(&vv, p_v);
    cudaGetSymbolAddress(&vvt, p_vt);   cudaGetSymbolAddress(&vctx, p_ctx);
    cudaGetSymbolAddress(&vwq, p_wq);   cudaGetSymbolAddress(&vwk, p_wk);
    cudaGetSymbolAddress(&vwv, p_wv);   cudaGetSymbolAddress(&vwo, p_wo);
    cudaGetSymbolAddress(&vpe, p_pe);   cudaGetSymbolAddress(&vps, g_pshift);

    __nv_bfloat16* bq   = (__nv_bfloat16*)vq;
    __nv_bfloat16* bk   = (__nv_bfloat16*)vk;
    __nv_bfloat16* bv   = (__nv_bfloat16*)vv;
    __nv_bfloat16* bvt  = (__nv_bfloat16*)vvt;
    __nv_bfloat16* bctx = (__nv_bfloat16*)vctx;

    auto SPL = [](const float* src, void* pl, long n) {
        int n4 = (int)(n / 4);
        split_kernel<<<(n4 + 255) / 256 < 4096 ? (n4 + 255) / 256 : 4096, 256>>>(
            (const float4*)src, (__nv_bfloat162*)pl,
            (__nv_bfloat162*)((__nv_bfloat16*)pl + n), n4);
    };
    SPL(query, vx, E_X);  SPL(key, vy, E_X);  SPL(value, vz, E_X);
    SPL(Wq, vwq, E_W);    SPL(Wk, vwk, E_W);  SPL(Wv, vwv, E_W);
    SPL(Wo, vwo, E_W);    SPL(pe, vpe, E_PE);

    const int SM128 = 2 * (20480 + 2 * 128 * 80);  // 81920
    cudaFuncSetAttribute(gemm2<128, 0>, cudaFuncAttributeMaxDynamicSharedMemorySize, SM128);
    cudaFuncSetAttribute(gemm2<128, 1>, cudaFuncAttributeMaxDynamicSharedMemorySize, SM128);
    cudaFuncSetAttribute(gemm2<128, 2>, cudaFuncAttributeMaxDynamicSharedMemorySize, SM128);
    cudaFuncSetAttribute(fused_attn, cudaFuncAttributeMaxDynamicSharedMemorySize, F_TOT);

    const dim3 th(256);
    const long SD  = (long)NS * ND;
    const long SS  = (long)NS * NS;
    const long HSS = (long)NH * SS;

    // Projections -> q,k,v planes
    gemm2<128, 1><<<dim3(8, 32, 1), th, SM128>>>(
        (__nv_bfloat16*)vx, (__nv_bfloat16*)vwq, vq, ND, ND, ND, ND,
        0, 0, 0, 0, 0, 0, E_X, E_W, E_X, 1.0f, 0);
    gemm2<128, 1><<<dim3(8, 32, 1), th, SM128>>>(
        (__nv_bfloat16*)vy, (__nv_bfloat16*)vwk, vk, ND, ND, ND, ND,
        0, 0, 0, 0, 0, 0, E_X, E_W, E_X, 1.0f, 0);
    gemm2<128, 1><<<dim3(8, 32, 1), th, SM128>>>(
        (__nv_bfloat16*)vz, (__nv_bfloat16*)vwv, vv, ND, ND, ND, ND,
        0, 0, 0, 0, 0, 0, E_X, E_W, E_X, 1.0f, 0);

    // Pshift = shifted (q @ pe^T) * 8  (triangular grid, shifted epilogue)
    gemm2<128, 2><<<dim3(8, 8, NB * NH), th, SM128>>>(
        bq, (__nv_bfloat16*)vpe, vps, NDH, ND, NDH, NS,
        SD, NDH, 0, (long)NS * NDH, HSS, SS, E_X, E_PE, 0, 8.0f, 1);

    // v^T per head (planes)
    transpose_v_kernel<<<dim3(32, 2, NB * NH), dim3(32, 8)>>>(bv, bvt, E_X);

    // fused: QK^T + skew + mask + softmax + AV -> ctx planes
    fused_attn<<<dim3(8, NB * NH), th, F_TOT>>>(
        bq, bk, bvt, (const float*)vps, mask, bctx);

    // out = ctx @ Wo^T (fp32)
    gemm2<128, 0><<<dim3(8, 32, 1), th, SM128>>>(
        bctx, (__nv_bfloat16*)vwo, out, ND, ND, ND, ND,
        0, 0, 0, 0, 0, 0, E_X, E_W, 0, 1.0f, 0);
}

// round 6
// speedup vs baseline: 2.6496x; 1.0086x over previous
#include <cuda_runtime.h>
#include <cuda_bf16.h>
#include <cstdint>

#define NB 4
#define NS 1024
#define ND 1024
#define NH 16
#define NDH 64

#define E_X   ((long)NB * NS * ND)       // 4194304
#define E_W   ((long)ND * ND)            // 1048576
#define E_PE  ((long)NH * NS * NDH)      // 1048576
#define E_ATT ((long)NB * NH * NS * NS)  // 67108864

#define LOG2E 1.4426950408889634f

// Plane buffers (hi at [0,E), lo at [E,2E)), uint4-declared for 16B alignment.
__device__ uint4 p_x[E_X / 4],  p_y[E_X / 4],  p_z[E_X / 4];
__device__ uint4 p_q[E_X / 4],  p_k[E_X / 4],  p_v[E_X / 4];
__device__ uint4 p_vt[E_X / 4], p_ctx[E_X / 4];
__device__ uint4 p_wq[E_W / 4], p_wk[E_W / 4], p_wv[E_W / 4], p_wo[E_W / 4];
__device__ uint4 p_pe[E_PE / 4];
__device__ float g_pshift[E_ATT];        // shifted pos logits (log2-scaled)

// ---------------------------------------------------------------------------
// Base-ISA helpers
// ---------------------------------------------------------------------------
static __device__ __forceinline__ uint32_t smem_u32(const void* p) {
    uint32_t a;
    asm("{ .reg .u64 t; cvta.to.shared.u64 t, %1; cvt.u32.u64 %0, t; }"
        : "=r"(a) : "l"(p));
    return a;
}
static __device__ __forceinline__ void ldsm_x4(uint32_t* r, uint32_t addr) {
    asm volatile("ldmatrix.sync.aligned.m8n8.x4.shared.b16 {%0,%1,%2,%3}, [%4];"
                 : "=r"(r[0]), "=r"(r[1]), "=r"(r[2]), "=r"(r[3]) : "r"(addr));
}
static __device__ __forceinline__ void mma_bf16(float* c, const uint32_t* a,
                                                const uint32_t* b) {
    asm volatile(
        "mma.sync.aligned.m16n8k16.row.col.f32.bf16.bf16.f32 "
        "{%0,%1,%2,%3}, {%4,%5,%6,%7}, {%8,%9}, {%0,%1,%2,%3};"
        : "+f"(c[0]), "+f"(c[1]), "+f"(c[2]), "+f"(c[3])
        : "r"(a[0]), "r"(a[1]), "r"(a[2]), "r"(a[3]), "r"(b[0]), "r"(b[1]));
}
static __device__ __forceinline__ void cpa16(uint32_t d, const void* s) {
    asm volatile("cp.async.cg.shared.global [%0], [%1], 16;" :: "r"(d), "l"(s));
}
static __device__ __forceinline__ void cpa_commit() {
    asm volatile("cp.async.commit_group;" ::: "memory");
}
template <int N> static __device__ __forceinline__ void cpa_wait() {
    asm volatile("cp.async.wait_group %0;" :: "n"(N) : "memory");
}
static __device__ __forceinline__ uint32_t packbf(float x, float y) {
    __nv_bfloat162 t = __floats2bfloat162_rn(x, y);
    return *(uint32_t*)&t;
}

// ---------------------------------------------------------------------------
// GEMM: C = alpha * A @ B^T, bf16 hi/lo planes in, bf16x3 accumulation.
// MODE 0: fp32 out.  MODE 1: bf16 hi/lo plane out.  MODE 2: shifted fp32 out
// (C[i, c-(NS-1)+i] = val, predicated j>=0) for the Music-Transformer skew.
// ---------------------------------------------------------------------------
template <int BN, int MODE>
__global__ void __launch_bounds__(256, 2) gemm2(
    const __nv_bfloat16* __restrict__ A, const __nv_bfloat16* __restrict__ Bp,
    void* __restrict__ Cv,
    int K, int lda, int ldb, int ldc,
    long aOut, long aIn, long bOut, long bIn, long cOut, long cIn,
    long aPl, long bPl, long cPl, float alpha, int tri)
{
    constexpr int BM = 128, LDE = 40;
    constexpr int WM = 2;
    constexpr int MT = (BM / WM) / 16;            // 4
    constexpr int AH = 0;
    constexpr int AL = BM * LDE * 2;
    constexpr int BH = 2 * AL;
    constexpr int BL = BH + BN * LDE * 2;
    constexpr int STAGE = BH + 2 * BN * LDE * 2;

    if (tri && (int)(blockIdx.x * BN + blockIdx.y * BM) + 255 < NS) return;

    extern __shared__ __align__(128) char sm[];
    const uint32_t sb = smem_u32(sm);

    const int tid = threadIdx.x, wid = tid >> 5, lane = tid & 31;
    const int wm = wid % WM, wn = wid / WM;
    const int z = blockIdx.z, zo = z / NH, zi = z % NH;

    const __nv_bfloat16* Ab = A + (long)zo * aOut + (long)zi * aIn
                              + (long)(blockIdx.y * BM) * lda;
    const __nv_bfloat16* Bb = Bp + (long)zo * bOut + (long)zi * bIn
                              + (long)(blockIdx.x * BN) * ldb;

    auto issue = [&](int s, int kt) {
        const uint32_t st = sb + s * STAGE;
        #pragma unroll
        for (int t = 0; t < 2; ++t) {
            int r = (tid + t * 256) >> 2, sg = tid & 3;
            const __nv_bfloat16* g = Ab + (long)r * lda + kt + sg * 8;
            uint32_t d = st + r * 80 + sg * 16;
            cpa16(d + AH, g);
            cpa16(d + AL, g + aPl);
        }
        #pragma unroll
        for (int t = 0; t < BN / 64; ++t) {
            int r = (tid + t * 256) >> 2, sg = tid & 3;
            const __nv_bfloat16* g = Bb + (long)r * ldb + kt + sg * 8;
            uint32_t d = st + r * 80 + sg * 16;
            cpa16(d + BH, g);
            cpa16(d + BL, g + bPl);
        }
        cpa_commit();
    };

    const uint32_t aRelH = AH +
        (uint32_t)(((wm * MT * 16 + (lane & 15)) * LDE + (lane >> 4) * 8) * 2);
    const uint32_t aRelL = aRelH + (AL - AH);
    const int brow = (lane & 7) | ((lane >> 1) & 8);
    const uint32_t bRelH = BH +
        (uint32_t)(((wn * 32 + brow) * LDE + ((lane >> 3) & 1) * 8) * 2);
    const uint32_t bRelL = bRelH + (BL - BH);

    float acc[MT][4][4] = {};
    issue(0, 0);

    const int nch = K >> 5;
    for (int c = 0; c < nch; ++c) {
        if (c + 1 < nch) { issue((c + 1) & 1, (c + 1) << 5); cpa_wait<1>(); }
        else             { cpa_wait<0>(); }
        __syncthreads();
        const uint32_t s0 = sb + (c & 1) * STAGE;
        #pragma unroll
        for (int ks = 0; ks < 2; ++ks) {
            uint32_t ah[MT][4], al[MT][4], bh[2][4], bl[2][4];
            #pragma unroll
            for (int mt = 0; mt < MT; ++mt) {
                ldsm_x4(ah[mt], s0 + aRelH + mt * (16 * LDE * 2) + ks * 32);
                ldsm_x4(al[mt], s0 + aRelL + mt * (16 * LDE * 2) + ks * 32);
            }
            #pragma unroll
            for (int nt2 = 0; nt2 < 2; ++nt2) {
                ldsm_x4(bh[nt2], s0 + bRelH + nt2 * (16 * LDE * 2) + ks * 32);
                ldsm_x4(bl[nt2], s0 + bRelL + nt2 * (16 * LDE * 2) + ks * 32);
            }
            #pragma unroll
            for (int mt = 0; mt < MT; ++mt)
                #pragma unroll
                for (int nt = 0; nt < 4; ++nt) {
                    float* cc = acc[mt][nt];
                    const uint32_t* bhp = &bh[nt >> 1][(nt & 1) * 2];
                    const uint32_t* blp = &bl[nt >> 1][(nt & 1) * 2];
                    mma_bf16(cc, ah[mt], bhp);
                    mma_bf16(cc, ah[mt], blp);
                    mma_bf16(cc, al[mt], bhp);
                }
        }
        __syncthreads();
    }

    const int r0 = wm * (MT * 16) + (lane >> 2);
    const int c0 = wn * 32 + (lane & 3) * 2;
    if (MODE == 1) {
        __nv_bfloat16* Ch = (__nv_bfloat16*)Cv + (long)zo * cOut + (long)zi * cIn
                            + (long)(blockIdx.y * BM) * ldc + blockIdx.x * BN;
        #pragma unroll
        for (int mt = 0; mt < MT; ++mt)
            #pragma unroll
            for (int nt = 0; nt < 4; ++nt)
                #pragma unroll
                for (int h = 0; h < 2; ++h) {
                    long off = (long)(r0 + mt * 16 + h * 8) * ldc + c0 + nt * 8;
                    float x0 = acc[mt][nt][h * 2 + 0] * alpha;
                    float x1 = acc[mt][nt][h * 2 + 1] * alpha;
                    __nv_bfloat162 hi = __floats2bfloat162_rn(x0, x1);
                    __nv_bfloat162 lo = __floats2bfloat162_rn(
                        x0 - __low2float(hi), x1 - __high2float(hi));
                    *(__nv_bfloat162*)(Ch + off)       = hi;
                    *(__nv_bfloat162*)(Ch + off + cPl) = lo;
                }
    } else if (MODE == 0) {
        float* Cf = (float*)Cv + (long)zo * cOut + (long)zi * cIn
                    + (long)(blockIdx.y * BM) * ldc + blockIdx.x * BN;
        #pragma unroll
        for (int mt = 0; mt < MT; ++mt)
            #pragma unroll
            for (int nt = 0; nt < 4; ++nt)
                #pragma unroll
                for (int h = 0; h < 2; ++h) {
                    long off = (long)(r0 + mt * 16 + h * 8) * ldc + c0 + nt * 8;
                    float2 v = make_float2(acc[mt][nt][h * 2 + 0] * alpha,
                                           acc[mt][nt][h * 2 + 1] * alpha);
                    *(float2*)(Cf + off) = v;
                }
    } else {  // MODE 2: shifted store  Cshift[i, c-(NS-1)+i]
        float* Cf = (float*)Cv + (long)zo * cOut + (long)zi * cIn;
        const int ig0 = blockIdx.y * BM + r0;
        const int cg0 = blockIdx.x * BN + c0;
        #pragma unroll
        for (int mt = 0; mt < MT; ++mt)
            #pragma unroll
            for (int h = 0; h < 2; ++h) {
                int ig = ig0 + mt * 16 + h * 8;
                #pragma unroll
                for (int nt = 0; nt < 4; ++nt) {
                    int j = cg0 + nt * 8 - (NS - 1) + ig;
                    float x0 = acc[mt][nt][h * 2 + 0] * alpha;
                    float x1 = acc[mt][nt][h * 2 + 1] * alpha;
                    if (j >= 0)     Cf[(long)ig * NS + j]     = x0;
                    if (j + 1 >= 0) Cf[(long)ig * NS + j + 1] = x1;
                }
            }
    }
}

// ---------------------------------------------------------------------------
// Fused attention (log2-domain softmax): per (i-tile 128, bh).
// logit2 = (0.125*log2e)*(q@k^T) + Pshift2 (j<=i) + mbias; O = softmax @ v.
// K+P and V in separate cp.async groups: V load overlaps QK + softmax.
// ---------------------------------------------------------------------------
constexpr int F_SQ  = 0;
constexpr int F_SQP = 128 * 72 * 2;              // 18432 per plane
constexpr int F_SK  = 2 * F_SQP;                 // 36864
constexpr int F_KST = 2 * (64 * 72 * 2);         // 18432 per stage (hi+lo)
constexpr int F_KP  = 64 * 72 * 2;               // 9216
constexpr int F_SV  = F_SK + 2 * F_KST;          // 73728
constexpr int F_SP  = F_SV + 2 * F_KST;          // 110592
constexpr int F_PST = 128 * 68 * 4;              // 34816 per stage
constexpr int F_SM  = F_SP + 2 * F_PST;          // 180224 (mask bias)
constexpr int F_TOT = F_SM + NS * 4;             // 184320

__global__ void __launch_bounds__(256, 1) fused_attn(
    const __nv_bfloat16* __restrict__ q, const __nv_bfloat16* __restrict__ k,
    const __nv_bfloat16* __restrict__ vt, const float* __restrict__ pshift,
    const int* __restrict__ mask, __nv_bfloat16* __restrict__ ctx)
{
    extern __shared__ __align__(128) char sm[];
    const uint32_t sb = smem_u32(sm);
    const int tid = threadIdx.x, wid = tid >> 5, lane = tid & 31;
    const int i0 = blockIdx.x * 128;
    const int bh = blockIdx.y, b = bh / NH, h = bh % NH;
    const float SC = 0.125f * LOG2E;

    const __nv_bfloat16* qg  = q + (long)b * NS * ND + (long)i0 * ND + h * NDH;
    const __nv_bfloat16* kg  = k + (long)b * NS * ND + h * NDH;
    const __nv_bfloat16* vtg = vt + (long)bh * NDH * NS;
    const float* pg = pshift + (long)bh * NS * NS + (long)i0 * NS;

    float* mbias = (float*)(sm + F_SM);
    for (int j = tid; j < NS; j += 256)
        mbias[j] = mask[b * NS + j] ? 0.0f : -1.5e9f;

    // Q -> smem (own group)
    #pragma unroll
    for (int t = 0; t < 8; ++t) {
        int idx = tid + t * 256;
        int pl = idx >> 10, rem = idx & 1023, r = rem >> 3, ch = rem & 7;
        cpa16(sb + F_SQ + pl * F_SQP + (r * 72 + ch * 8) * 2,
              qg + (long)pl * E_X + (long)r * ND + ch * 8);
    }
    cpa_commit();

    auto issueKP = [&](int jt) {
        const int st = jt & 1, j0 = jt * 64;
        #pragma unroll
        for (int t = 0; t < 4; ++t) {   // K tile
            int idx = tid + t * 256;
            int pl = idx >> 9, rem = idx & 511, r = rem >> 3, ch = rem & 7;
            cpa16(sb + F_SK + st * F_KST + pl * F_KP + (r * 72 + ch * 8) * 2,
                  kg + (long)pl * E_X + (long)(j0 + r) * ND + ch * 8);
        }
        if (j0 <= i0 + 127) {
            #pragma unroll
            for (int t = 0; t < 8; ++t) {   // Pshift tile (fp32)
                int idx = tid + t * 256;
                int r = idx >> 4, ch = idx & 15;
                cpa16(sb + F_SP + st * F_PST + (r * 68 + ch * 4) * 4,
                      pg + (long)r * NS + j0 + ch * 4);
            }
        }
        cpa_commit();
    };
    auto issueV = [&](int jt) {
        const int st = jt & 1, j0 = jt * 64;
        #pragma unroll
        for (int t = 0; t < 4; ++t) {
            int idx = tid + t * 256;
            int pl = idx >> 9, rem = idx & 511, d = rem >> 3, ch = rem & 7;
            cpa16(sb + F_SV + st * F_KST + pl * F_KP + (d * 72 + ch * 8) * 2,
                  vtg + (long)pl * E_X + (long)d * NS + j0 + ch * 8);
        }
        cpa_commit();
    };

    issueKP(0);
    cpa_wait<1>();          // Q done (KP0 may still fly)
    __syncthreads();

    // Q fragments (once)
    uint32_t qah[4][4], qal[4][4];
    {
        uint32_t base = sb + F_SQ + ((wid * 16 + (lane & 15)) * 72 + (lane >> 4) * 8) * 2;
        #pragma unroll
        for (int kt = 0; kt < 4; ++kt) {
            ldsm_x4(qah[kt], base + kt * 32);
            ldsm_x4(qal[kt], base + F_SQP + kt * 32);
        }
    }
    issueV(0);

    const int rA = wid * 16 + (lane >> 2);
    const int iA = i0 + rA, iB = iA + 8;
    const int miA = mask[b * NS + iA], miB = mask[b * NS + iB];
    const int brow = (lane & 7) | ((lane >> 1) & 8);
    const int bcol = ((lane >> 3) & 1) * 8;

    float oacc[8][4] = {};
    float mA = -1.0e30f, mB = -1.0e30f, lA = 0.0f, lB = 0.0f;

    for (int jt = 0; jt < 16; ++jt) {
        if (jt + 1 < 16) { issueKP(jt + 1); issueV(jt + 1); cpa_wait<3>(); }
        else             { cpa_wait<1>(); }
        __syncthreads();

        const int st = jt & 1, j0 = jt * 64;
        const uint32_t kb = sb + F_SK + st * F_KST;
        const uint32_t vb = sb + F_SV + st * F_KST;
        const bool anyP = (j0 <= i0 + 127);
        const float* psm = (const float*)(sm + F_SP + st * F_PST);

        // ---- S = q @ k^T (bf16x3) ----
        float sacc[8][4] = {};
        #pragma unroll
        for (int kt = 0; kt < 4; ++kt) {
            uint32_t bhf[4][4], blf[4][4];
            #pragma unroll
            for (int p = 0; p < 4; ++p) {
                ldsm_x4(bhf[p], kb + ((p * 16 + brow) * 72 + bcol + kt * 16) * 2);
                ldsm_x4(blf[p], kb + F_KP + ((p * 16 + brow) * 72 + bcol + kt * 16) * 2);
            }
            #pragma unroll
            for (int nt = 0; nt < 8; ++nt) {
                const uint32_t* bp = &bhf[nt >> 1][(nt & 1) * 2];
                const uint32_t* lp = &blf[nt >> 1][(nt & 1) * 2];
                mma_bf16(sacc[nt], qah[kt], bp);
                mma_bf16(sacc[nt], qah[kt], lp);
                mma_bf16(sacc[nt], qal[kt], bp);
            }
        }

        // ---- logits (log2 domain): scale + pshift + mask ----
        #pragma unroll
        for (int nt = 0; nt < 8; ++nt) {
            int jl = nt * 8 + (lane & 3) * 2;
            int jg = j0 + jl;
            float p0A = 0, p1A = 0, p0B = 0, p1B = 0;
            if (anyP) {
                float2 fa = *(const float2*)(psm + rA * 68 + jl);
                float2 fb = *(const float2*)(psm + (rA + 8) * 68 + jl);
                p0A = (jg     <= iA) ? fa.x : 0.0f;
                p1A = (jg + 1 <= iA) ? fa.y : 0.0f;
                p0B = (jg     <= iB) ? fb.x : 0.0f;
                p1B = (jg + 1 <= iB) ? fb.y : 0.0f;
            }
            float b0 = mbias[jg], b1 = mbias[jg + 1];
            sacc[nt][0] = miA ? fmaf(sacc[nt][0], SC, p0A) + b0 : -1.0e9f;
            sacc[nt][1] = miA ? fmaf(sacc[nt][1], SC, p1A) + b1 : -1.0e9f;
            sacc[nt][2] = miB ? fmaf(sacc[nt][2], SC, p0B) + b0 : -1.0e9f;
            sacc[nt][3] = miB ? fmaf(sacc[nt][3], SC, p1B) + b1 : -1.0e9f;
        }

        // ---- online softmax (base-2) ----
        float rmA = -1.0e30f, rmB = -1.0e30f;
        #pragma unroll
        for (int nt = 0; nt < 8; ++nt) {
            rmA = fmaxf(rmA, fmaxf(sacc[nt][0], sacc[nt][1]));
            rmB = fmaxf(rmB, fmaxf(sacc[nt][2], sacc[nt][3]));
        }
        rmA = fmaxf(rmA, __shfl_xor_sync(0xffffffffu, rmA, 1));
        rmA = fmaxf(rmA, __shfl_xor_sync(0xffffffffu, rmA, 2));
        rmB = fmaxf(rmB, __shfl_xor_sync(0xffffffffu, rmB, 1));
        rmB = fmaxf(rmB, __shfl_xor_sync(0xffffffffu, rmB, 2));

        float mnA = fmaxf(mA, rmA), mnB = fmaxf(mB, rmB);
        float alA = exp2f(mA - mnA), alB = exp2f(mB - mnB);
        mA = mnA; mB = mnB;

        float rsA = 0.0f, rsB = 0.0f;
        #pragma unroll
        for (int nt = 0; nt < 8; ++nt) {
            sacc[nt][0] = exp2f(sacc[nt][0] - mnA);
            sacc[nt][1] = exp2f(sacc[nt][1] - mnA);
            sacc[nt][2] = exp2f(sacc[nt][2] - mnB);
            sacc[nt][3] = exp2f(sacc[nt][3] - mnB);
            rsA += sacc[nt][0] + sacc[nt][1];
            rsB += sacc[nt][2] + sacc[nt][3];
        }
        rsA += __shfl_xor_sync(0xffffffffu, rsA, 1);
        rsA += __shfl_xor_sync(0xffffffffu, rsA, 2);
        rsB += __shfl_xor_sync(0xffffffffu, rsB, 1);
        rsB += __shfl_xor_sync(0xffffffffu, rsB, 2);
        lA = lA * alA + rsA;
        lB = lB * alB + rsB;
        #pragma unroll
        for (int nt = 0; nt < 8; ++nt) {
            oacc[nt][0] *= alA; oacc[nt][1] *= alA;
            oacc[nt][2] *= alB; oacc[nt][3] *= alB;
        }

        // ---- pack P into A-fragments (hi/lo) ----
        uint32_t pah[4][4], pal[4][4];
        #pragma unroll
        for (int kt = 0; kt < 4; ++kt) {
            const float* e = sacc[2 * kt];
            const float* o = sacc[2 * kt + 1];
            pah[kt][0] = packbf(e[0], e[1]); pah[kt][1] = packbf(e[2], e[3]);
            pah[kt][2] = packbf(o[0], o[1]); pah[kt][3] = packbf(o[2], o[3]);
            #pragma unroll
            for (int u = 0; u < 4; ++u) {
                __nv_bfloat162 hv = *(__nv_bfloat162*)&pah[kt][u];
                const float* src = (u < 2) ? e : o;
                float x0 = src[(u & 1) * 2]     - __low2float(hv);
                float x1 = src[(u & 1) * 2 + 1] - __high2float(hv);
                pal[kt][u] = packbf(x0, x1);
            }
        }

        // ---- V now needed: drain its group ----
        if (jt + 1 < 16) cpa_wait<2>();
        else             cpa_wait<0>();
        __syncthreads();

        // ---- O += P @ V (bf16x3) ----
        #pragma unroll
        for (int kt = 0; kt < 4; ++kt) {
            uint32_t vhf[4][4], vlf[4][4];
            #pragma unroll
            for (int p = 0; p < 4; ++p) {
                ldsm_x4(vhf[p], vb + ((p * 16 + brow) * 72 + bcol + kt * 16) * 2);
                ldsm_x4(vlf[p], vb + F_KP + ((p * 16 + brow) * 72 + bcol + kt * 16) * 2);
            }
            #pragma unroll
            for (int nt = 0; nt < 8; ++nt) {
                const uint32_t* bp = &vhf[nt >> 1][(nt & 1) * 2];
                const uint32_t* lp = &vlf[nt >> 1][(nt & 1) * 2];
                mma_bf16(oacc[nt], pah[kt], bp);
                mma_bf16(oacc[nt], pah[kt], lp);
                mma_bf16(oacc[nt], pal[kt], bp);
            }
        }
        __syncthreads();
    }

    // ---- epilogue: normalize, stage in smem (reuse K area), coalesced store ----
    const float ivA = 1.0f / lA, ivB = 1.0f / lB;
    __nv_bfloat16* so = (__nv_bfloat16*)(sm + F_SK);
    constexpr int OP = 128 * 72;
    #pragma unroll
    for (int nt = 0; nt < 8; ++nt) {
        int c = nt * 8 + (lane & 3) * 2;
        float a0 = oacc[nt][0] * ivA, a1 = oacc[nt][1] * ivA;
        float b0 = oacc[nt][2] * ivB, b1 = oacc[nt][3] * ivB;
        __nv_bfloat162 ha = __floats2bfloat162_rn(a0, a1);
        __nv_bfloat162 la = __floats2bfloat162_rn(a0 - __low2float(ha),
                                                  a1 - __high2float(ha));
        __nv_bfloat162 hb = __floats2bfloat162_rn(b0, b1);
        __nv_bfloat162 lb = __floats2bfloat162_rn(b0 - __low2float(hb),
                                                  b1 - __high2float(hb));
        *(__nv_bfloat162*)(so + rA * 72 + c)            = ha;
        *(__nv_bfloat162*)(so + OP + rA * 72 + c)       = la;
        *(__nv_bfloat162*)(so + (rA + 8) * 72 + c)      = hb;
        *(__nv_bfloat162*)(so + OP + (rA + 8) * 72 + c) = lb;
    }
    __syncthreads();
    __nv_bfloat16* cgb = ctx + (long)b * NS * ND + (long)i0 * ND + h * NDH;
    #pragma unroll
    for (int t = 0; t < 8; ++t) {
        int idx = tid + t * 256;
        int pl = idx >> 10, rem = idx & 1023, r = rem >> 3, ch = rem & 7;
        uint4 val = *(const uint4*)(so + pl * OP + r * 72 + ch * 8);
        *(uint4*)(cgb + (long)pl * E_X + (long)r * ND + ch * 8) = val;
    }
}

// ---------------------------------------------------------------------------
// Merged split: fp32 -> bf16 hi/lo planes, 8 segments (seg = blockIdx.y)
// ---------------------------------------------------------------------------
struct SplitArgs {
    const float4* s[8];
    __nv_bfloat16* d[8];
    int n4[8];
};
__global__ void __launch_bounds__(256) split_all(SplitArgs a)
{
    const int seg = blockIdx.y;
    const int n4 = a.n4[seg];
    const float4* s = a.s[seg];
    __nv_bfloat162* hi = (__nv_bfloat162*)a.d[seg];
    __nv_bfloat162* lo = (__nv_bfloat162*)(a.d[seg] + (long)n4 * 4);
    for (int i = blockIdx.x * 256 + threadIdx.x; i < n4; i += gridDim.x * 256) {
        float4 x = s[i];
        __nv_bfloat162 h0 = __floats2bfloat162_rn(x.x, x.y);
        __nv_bfloat162 h1 = __floats2bfloat162_rn(x.z, x.w);
        __nv_bfloat162 l0 = __floats2bfloat162_rn(x.x - __low2float(h0),
                                                  x.y - __high2float(h0));
        __nv_bfloat162 l1 = __floats2bfloat162_rn(x.z - __low2float(h1),
                                                  x.w - __high2float(h1));
        hi[2 * i] = h0; hi[2 * i + 1] = h1;
        lo[2 * i] = l0; lo[2 * i + 1] = l1;
    }
}

// ---------------------------------------------------------------------------
// V transpose per head on planes: [B,S,D] -> [B,H,DH,S]
// ---------------------------------------------------------------------------
__global__ void __launch_bounds__(256) transpose_v_kernel(
    const __nv_bfloat16* __restrict__ v, __nv_bfloat16* __restrict__ vt, long pl)
{
    __shared__ __nv_bfloat16 t0[32][33], t1[32][33];
    const int bh = blockIdx.z, b = bh / NH, h = bh % NH;
    const int j0 = blockIdx.x * 32, d0 = blockIdx.y * 32;
    const int tx = threadIdx.x, ty = threadIdx.y;
    const __nv_bfloat16* s0 = v + (long)b * NS * ND + h * NDH;
    #pragma unroll
    for (int i = 0; i < 4; ++i) {
        int j = j0 + ty + i * 8;
        long o = (long)j * ND + d0 + tx;
        t0[ty + i * 8][tx] = s0[o];
        t1[ty + i * 8][tx] = s0[o + pl];
    }
    __syncthreads();
    __nv_bfloat16* dst = vt + (long)bh * NDH * NS;
    #pragma unroll
    for (int i = 0; i < 4; ++i) {
        int d = d0 + ty + i * 8;
        long o = (long)d * NS + j0 + tx;
        dst[o]      = t0[tx][ty + i * 8];
        dst[o + pl] = t1[tx][ty + i * 8];
    }
}

// ---------------------------------------------------------------------------
extern "C" void kernel_launch(void* const* d_in, const int* in_sizes, int n_in,
                              void* d_out, int out_size)
{
    const float* query = (const float*)d_in[0];
    const float* key   = (const float*)d_in[1];
    const float* value = (const float*)d_in[2];
    const int*   mask  = (const int*)  d_in[3];
    const float* pe    = (const float*)d_in[4];
    const float* Wq    = (const float*)d_in[5];
    const float* Wk    = (const float*)d_in[6];
    const float* Wv    = (const float*)d_in[7];
    const float* Wo    = (const float*)d_in[8];
    float* out = (float*)d_out;

    void *vx, *vy, *vz, *vq, *vk, *vv, *vvt, *vctx, *vwq, *vwk, *vwv, *vwo,
         *vpe, *vps;
    cudaGetSymbolAddress(&vx, p_x);     cudaGetSymbolAddress(&vy, p_y);
    cudaGetSymbolAddress(&vz, p_z);     cudaGetSymbolAddress(&vq, p_q);
    cudaGetSymbolAddress(&vk, p_k);     cudaGetSymbolAddress(&vv, p_v);
    cudaGetSymbolAddress(&vvt, p_vt);   cudaGetSymbolAddress(&vctx, p_ctx);
    cudaGetSymbolAddress(&vwq, p_wq);   cudaGetSymbolAddress(&vwk, p_wk);
    cudaGetSymbolAddress(&vwv, p_wv);   cudaGetSymbolAddress(&vwo, p_wo);
    cudaGetSymbolAddress(&vpe, p_pe);   cudaGetSymbolAddress(&vps, g_pshift);

    __nv_bfloat16* bq   = (__nv_bfloat16*)vq;
    __nv_bfloat16* bk   = (__nv_bfloat16*)vk;
    __nv_bfloat16* bv   = (__nv_bfloat16*)vv;
    __nv_bfloat16* bvt  = (__nv_bfloat16*)vvt;
    __nv_bfloat16* bctx = (__nv_bfloat16*)vctx;

    // One split launch for all 8 tensors
    SplitArgs sa;
    sa.s[0] = (const float4*)query; sa.d[0] = (__nv_bfloat16*)vx;  sa.n4[0] = (int)(E_X / 4);
    sa.s[1] = (const float4*)key;   sa.d[1] = (__nv_bfloat16*)vy;  sa.n4[1] = (int)(E_X / 4);
    sa.s[2] = (const float4*)value; sa.d[2] = (__nv_bfloat16*)vz;  sa.n4[2] = (int)(E_X / 4);
    sa.s[3] = (const float4*)Wq;    sa.d[3] = (__nv_bfloat16*)vwq; sa.n4[3] = (int)(E_W / 4);
    sa.s[4] = (const float4*)Wk;    sa.d[4] = (__nv_bfloat16*)vwk; sa.n4[4] = (int)(E_W / 4);
    sa.s[5] = (const float4*)Wv;    sa.d[5] = (__nv_bfloat16*)vwv; sa.n4[5] = (int)(E_W / 4);
    sa.s[6] = (const float4*)Wo;    sa.d[6] = (__nv_bfloat16*)vwo; sa.n4[6] = (int)(E_W / 4);
    sa.s[7] = (const float4*)pe;    sa.d[7] = (__nv_bfloat16*)vpe; sa.n4[7] = (int)(E_PE / 4);
    split_all<<<dim3(1024, 8), 256>>>(sa);

    const int SM128 = 2 * (20480 + 2 * 128 * 80);  // 81920
    cudaFuncSetAttribute(gemm2<128, 0>, cudaFuncAttributeMaxDynamicSharedMemorySize, SM128);
    cudaFuncSetAttribute(gemm2<128, 1>, cudaFuncAttributeMaxDynamicSharedMemorySize, SM128);
    cudaFuncSetAttribute(gemm2<128, 2>, cudaFuncAttributeMaxDynamicSharedMemorySize, SM128);
    cudaFuncSetAttribute(fused_attn, cudaFuncAttributeMaxDynamicSharedMemorySize, F_TOT);

    const dim3 th(256);
    const long SD  = (long)NS * ND;
    const long SS  = (long)NS * NS;
    const long HSS = (long)NH * SS;

    // q,k projections merged (z selects via pointer deltas; zo=0, zi=z)
    const long dA = (long)(((char*)vy - (char*)vx) / 2);
    const long dB = (long)(((char*)vwk - (char*)vwq) / 2);
    const long dC = (long)(((char*)vk - (char*)vq) / 2);
    gemm2<128, 1><<<dim3(8, 32, 2), th, SM128>>>(
        (__nv_bfloat16*)vx, (__nv_bfloat16*)vwq, vq, ND, ND, ND, ND,
        0, dA, 0, dB, 0, dC, E_X, E_W, E_X, 1.0f, 0);
    // v projection
    gemm2<128, 1><<<dim3(8, 32, 1), th, SM128>>>(
        (__nv_bfloat16*)vz, (__nv_bfloat16*)vwv, vv, ND, ND, ND, ND,
        0, 0, 0, 0, 0, 0, E_X, E_W, E_X, 1.0f, 0);

    // Pshift = shifted (q @ pe^T) * 8 * log2e  (triangular, shifted epilogue)
    gemm2<128, 2><<<dim3(8, 8, NB * NH), th, SM128>>>(
        bq, (__nv_bfloat16*)vpe, vps, NDH, ND, NDH, NS,
        SD, NDH, 0, (long)NS * NDH, HSS, SS, E_X, E_PE, 0, 8.0f * LOG2E, 1);

    // v^T per head (planes)
    transpose_v_kernel<<<dim3(32, 2, NB * NH), dim3(32, 8)>>>(bv, bvt, E_X);

    // fused: QK^T + skew + mask + softmax + AV -> ctx planes
    fused_attn<<<dim3(8, NB * NH), th, F_TOT>>>(
        bq, bk, bvt, (const float*)vps, mask, bctx);

    // out = ctx @ Wo^T (fp32)
    gemm2<128, 0><<<dim3(8, 32, 1), th, SM128>>>(
        bctx, (__nv_bfloat16*)vwo, out, ND, ND, ND, ND,
        0, 0, 0, 0, 0, 0, E_X, E_W, 0, 1.0f, 0);
}

// round 7
// speedup vs baseline: 2.7585x; 1.0411x over previous
#include <cuda_runtime.h>
#include <cuda_bf16.h>
#include <cstdint>

#define NB 4
#define NS 1024
#define ND 1024
#define NH 16
#define NDH 64

#define E_X   ((long)NB * NS * ND)       // 4194304
#define E_W   ((long)ND * ND)            // 1048576
#define E_PE  ((long)NH * NS * NDH)      // 1048576
#define E_ATT ((long)NB * NH * NS * NS)  // 67108864

#define LOG2E 1.4426950408889634f

// Plane buffers (hi at [0,E), lo at [E,2E)), uint4-declared for 16B alignment.
__device__ uint4 p_x[E_X / 4],  p_y[E_X / 4],  p_z[E_X / 4];
__device__ uint4 p_q[E_X / 4],  p_k[E_X / 4],  p_v[E_X / 4];
__device__ uint4 p_vt[E_X / 4], p_ctx[E_X / 4];
__device__ uint4 p_wq[E_W / 4], p_wk[E_W / 4], p_wv[E_W / 4], p_wo[E_W / 4];
__device__ uint4 p_pe[E_PE / 4];
__device__ float g_pshift[E_ATT];        // shifted pos logits (log2-scaled)

// ---------------------------------------------------------------------------
// Base-ISA helpers
// ---------------------------------------------------------------------------
static __device__ __forceinline__ uint32_t smem_u32(const void* p) {
    uint32_t a;
    asm("{ .reg .u64 t; cvta.to.shared.u64 t, %1; cvt.u32.u64 %0, t; }"
        : "=r"(a) : "l"(p));
    return a;
}
static __device__ __forceinline__ void ldsm_x4(uint32_t* r, uint32_t addr) {
    asm volatile("ldmatrix.sync.aligned.m8n8.x4.shared.b16 {%0,%1,%2,%3}, [%4];"
                 : "=r"(r[0]), "=r"(r[1]), "=r"(r[2]), "=r"(r[3]) : "r"(addr));
}
static __device__ __forceinline__ void mma_bf16(float* c, const uint32_t* a,
                                                const uint32_t* b) {
    asm volatile(
        "mma.sync.aligned.m16n8k16.row.col.f32.bf16.bf16.f32 "
        "{%0,%1,%2,%3}, {%4,%5,%6,%7}, {%8,%9}, {%0,%1,%2,%3};"
        : "+f"(c[0]), "+f"(c[1]), "+f"(c[2]), "+f"(c[3])
        : "r"(a[0]), "r"(a[1]), "r"(a[2]), "r"(a[3]), "r"(b[0]), "r"(b[1]));
}
static __device__ __forceinline__ void cpa16(uint32_t d, const void* s) {
    asm volatile("cp.async.cg.shared.global [%0], [%1], 16;" :: "r"(d), "l"(s));
}
static __device__ __forceinline__ void cpa_commit() {
    asm volatile("cp.async.commit_group;" ::: "memory");
}
template <int N> static __device__ __forceinline__ void cpa_wait() {
    asm volatile("cp.async.wait_group %0;" :: "n"(N) : "memory");
}
static __device__ __forceinline__ uint32_t packbf(float x, float y) {
    __nv_bfloat162 t = __floats2bfloat162_rn(x, y);
    return *(uint32_t*)&t;
}

// ---------------------------------------------------------------------------
// GEMM: C = alpha * A @ B^T, bf16 hi/lo planes in, bf16x3 accumulation.
// MODE 0: fp32 out.  MODE 1: bf16 hi/lo plane out.  MODE 2: shifted fp32 out
// (C[i, c-(NS-1)+i] = val, predicated j>=0) for the Music-Transformer skew.
// ---------------------------------------------------------------------------
template <int BN, int MODE>
__global__ void __launch_bounds__(256, 2) gemm2(
    const __nv_bfloat16* __restrict__ A, const __nv_bfloat16* __restrict__ Bp,
    void* __restrict__ Cv,
    int K, int lda, int ldb, int ldc,
    long aOut, long aIn, long bOut, long bIn, long cOut, long cIn,
    long aPl, long bPl, long cPl, float alpha, int tri)
{
    constexpr int BM = 128, LDE = 40;
    constexpr int WM = 2;
    constexpr int MT = (BM / WM) / 16;            // 4
    constexpr int AH = 0;
    constexpr int AL = BM * LDE * 2;
    constexpr int BH = 2 * AL;
    constexpr int BL = BH + BN * LDE * 2;
    constexpr int STAGE = BH + 2 * BN * LDE * 2;

    if (tri && (int)(blockIdx.x * BN + blockIdx.y * BM) + 255 < NS) return;

    extern __shared__ __align__(128) char sm[];
    const uint32_t sb = smem_u32(sm);

    const int tid = threadIdx.x, wid = tid >> 5, lane = tid & 31;
    const int wm = wid % WM, wn = wid / WM;
    const int z = blockIdx.z, zo = z / NH, zi = z % NH;

    const __nv_bfloat16* Ab = A + (long)zo * aOut + (long)zi * aIn
                              + (long)(blockIdx.y * BM) * lda;
    const __nv_bfloat16* Bb = Bp + (long)zo * bOut + (long)zi * bIn
                              + (long)(blockIdx.x * BN) * ldb;

    auto issue = [&](int s, int kt) {
        const uint32_t st = sb + s * STAGE;
        #pragma unroll
        for (int t = 0; t < 2; ++t) {
            int r = (tid + t * 256) >> 2, sg = tid & 3;
            const __nv_bfloat16* g = Ab + (long)r * lda + kt + sg * 8;
            uint32_t d = st + r * 80 + sg * 16;
            cpa16(d + AH, g);
            cpa16(d + AL, g + aPl);
        }
        #pragma unroll
        for (int t = 0; t < BN / 64; ++t) {
            int r = (tid + t * 256) >> 2, sg = tid & 3;
            const __nv_bfloat16* g = Bb + (long)r * ldb + kt + sg * 8;
            uint32_t d = st + r * 80 + sg * 16;
            cpa16(d + BH, g);
            cpa16(d + BL, g + bPl);
        }
        cpa_commit();
    };

    const uint32_t aRelH = AH +
        (uint32_t)(((wm * MT * 16 + (lane & 15)) * LDE + (lane >> 4) * 8) * 2);
    const uint32_t aRelL = aRelH + (AL - AH);
    const int brow = (lane & 7) | ((lane >> 1) & 8);
    const uint32_t bRelH = BH +
        (uint32_t)(((wn * 32 + brow) * LDE + ((lane >> 3) & 1) * 8) * 2);
    const uint32_t bRelL = bRelH + (BL - BH);

    float acc[MT][4][4] = {};
    issue(0, 0);

    const int nch = K >> 5;
    for (int c = 0; c < nch; ++c) {
        if (c + 1 < nch) { issue((c + 1) & 1, (c + 1) << 5); cpa_wait<1>(); }
        else             { cpa_wait<0>(); }
        __syncthreads();
        const uint32_t s0 = sb + (c & 1) * STAGE;
        #pragma unroll
        for (int ks = 0; ks < 2; ++ks) {
            uint32_t ah[MT][4], al[MT][4], bh[2][4], bl[2][4];
            #pragma unroll
            for (int mt = 0; mt < MT; ++mt) {
                ldsm_x4(ah[mt], s0 + aRelH + mt * (16 * LDE * 2) + ks * 32);
                ldsm_x4(al[mt], s0 + aRelL + mt * (16 * LDE * 2) + ks * 32);
            }
            #pragma unroll
            for (int nt2 = 0; nt2 < 2; ++nt2) {
                ldsm_x4(bh[nt2], s0 + bRelH + nt2 * (16 * LDE * 2) + ks * 32);
                ldsm_x4(bl[nt2], s0 + bRelL + nt2 * (16 * LDE * 2) + ks * 32);
            }
            #pragma unroll
            for (int mt = 0; mt < MT; ++mt)
                #pragma unroll
                for (int nt = 0; nt < 4; ++nt) {
                    float* cc = acc[mt][nt];
                    const uint32_t* bhp = &bh[nt >> 1][(nt & 1) * 2];
                    const uint32_t* blp = &bl[nt >> 1][(nt & 1) * 2];
                    mma_bf16(cc, ah[mt], bhp);
                    mma_bf16(cc, ah[mt], blp);
                    mma_bf16(cc, al[mt], bhp);
                }
        }
        __syncthreads();
    }

    const int r0 = wm * (MT * 16) + (lane >> 2);
    const int c0 = wn * 32 + (lane & 3) * 2;
    if (MODE == 1) {
        __nv_bfloat16* Ch = (__nv_bfloat16*)Cv + (long)zo * cOut + (long)zi * cIn
                            + (long)(blockIdx.y * BM) * ldc + blockIdx.x * BN;
        #pragma unroll
        for (int mt = 0; mt < MT; ++mt)
            #pragma unroll
            for (int nt = 0; nt < 4; ++nt)
                #pragma unroll
                for (int h = 0; h < 2; ++h) {
                    long off = (long)(r0 + mt * 16 + h * 8) * ldc + c0 + nt * 8;
                    float x0 = acc[mt][nt][h * 2 + 0] * alpha;
                    float x1 = acc[mt][nt][h * 2 + 1] * alpha;
                    __nv_bfloat162 hi = __floats2bfloat162_rn(x0, x1);
                    __nv_bfloat162 lo = __floats2bfloat162_rn(
                        x0 - __low2float(hi), x1 - __high2float(hi));
                    *(__nv_bfloat162*)(Ch + off)       = hi;
                    *(__nv_bfloat162*)(Ch + off + cPl) = lo;
                }
    } else if (MODE == 0) {
        float* Cf = (float*)Cv + (long)zo * cOut + (long)zi * cIn
                    + (long)(blockIdx.y * BM) * ldc + blockIdx.x * BN;
        #pragma unroll
        for (int mt = 0; mt < MT; ++mt)
            #pragma unroll
            for (int nt = 0; nt < 4; ++nt)
                #pragma unroll
                for (int h = 0; h < 2; ++h) {
                    long off = (long)(r0 + mt * 16 + h * 8) * ldc + c0 + nt * 8;
                    float2 v = make_float2(acc[mt][nt][h * 2 + 0] * alpha,
                                           acc[mt][nt][h * 2 + 1] * alpha);
                    *(float2*)(Cf + off) = v;
                }
    } else {  // MODE 2: shifted store  Cshift[i, c-(NS-1)+i]
        float* Cf = (float*)Cv + (long)zo * cOut + (long)zi * cIn;
        const int ig0 = blockIdx.y * BM + r0;
        const int cg0 = blockIdx.x * BN + c0;
        #pragma unroll
        for (int mt = 0; mt < MT; ++mt)
            #pragma unroll
            for (int h = 0; h < 2; ++h) {
                int ig = ig0 + mt * 16 + h * 8;
                #pragma unroll
                for (int nt = 0; nt < 4; ++nt) {
                    int j = cg0 + nt * 8 - (NS - 1) + ig;
                    float x0 = acc[mt][nt][h * 2 + 0] * alpha;
                    float x1 = acc[mt][nt][h * 2 + 1] * alpha;
                    if (j >= 0)     Cf[(long)ig * NS + j]     = x0;
                    if (j + 1 >= 0) Cf[(long)ig * NS + j + 1] = x1;
                }
            }
    }
}

// ---------------------------------------------------------------------------
// Fused attention v2 (2 CTAs/SM): smem diet — Q loaded through the K area and
// consumed to registers in the prologue; P single-stage with a deterministic
// commit ladder (KV group at tile top, P group mid-tile).
// ---------------------------------------------------------------------------
constexpr int G_KST = 18432, G_KP = 9216;        // K/V stage: hi+lo, 64x72 bf16
constexpr int G_K  = 0;                          // 2 stages -> [0, 36864)
constexpr int G_V  = 36864;                      // 2 stages -> [36864, 73728)
constexpr int G_MB = 73728;                      // mask bias  [73728, 77824)
constexpr int G_P  = 77824;                      // P single stage 128*68*4
constexpr int G_TOT = 112640;

__global__ void __launch_bounds__(256, 2) fused_attn(
    const __nv_bfloat16* __restrict__ q, const __nv_bfloat16* __restrict__ k,
    const __nv_bfloat16* __restrict__ vt, const float* __restrict__ pshift,
    const int* __restrict__ mask, __nv_bfloat16* __restrict__ ctx)
{
    extern __shared__ __align__(128) char sm[];
    const uint32_t sb = smem_u32(sm);
    const int tid = threadIdx.x, wid = tid >> 5, lane = tid & 31;
    const int i0 = (7 - blockIdx.x) * 128;       // heavy-first
    const int bh = blockIdx.y, b = bh / NH, h = bh % NH;
    const float SC = 0.125f * LOG2E;

    const __nv_bfloat16* qg  = q + (long)b * NS * ND + (long)i0 * ND + h * NDH;
    const __nv_bfloat16* kg  = k + (long)b * NS * ND + h * NDH;
    const __nv_bfloat16* vtg = vt + (long)bh * NDH * NS;
    const float* pg = pshift + (long)bh * NS * NS + (long)i0 * NS;

    float* mbias = (float*)(sm + G_MB);
    for (int j = tid; j < NS; j += 256)
        mbias[j] = mask[b * NS + j] ? 0.0f : -1.5e9f;

    // ---- Prologue: Q through the K area, consume to registers ----
    #pragma unroll
    for (int t = 0; t < 8; ++t) {
        int idx = tid + t * 256;
        int pl = idx >> 10, rem = idx & 1023, r = rem >> 3, ch = rem & 7;
        cpa16(sb + pl * G_KST + (r * 72 + ch * 8) * 2,
              qg + (long)pl * E_X + (long)r * ND + ch * 8);
    }
    cpa_commit();
    cpa_wait<0>();
    __syncthreads();

    uint32_t qah[4][4], qal[4][4];
    {
        uint32_t base = sb + ((wid * 16 + (lane & 15)) * 72 + (lane >> 4) * 8) * 2;
        #pragma unroll
        for (int kt = 0; kt < 4; ++kt) {
            ldsm_x4(qah[kt], base + kt * 32);
            ldsm_x4(qal[kt], base + G_KST + kt * 32);
        }
    }
    __syncthreads();     // Q fully consumed; K area free for reuse

    auto issueKV = [&](int jt) {
        const int st = jt & 1, j0 = jt * 64;
        #pragma unroll
        for (int t = 0; t < 4; ++t) {   // K tile
            int idx = tid + t * 256;
            int pl = idx >> 9, rem = idx & 511, r = rem >> 3, ch = rem & 7;
            cpa16(sb + G_K + st * G_KST + pl * G_KP + (r * 72 + ch * 8) * 2,
                  kg + (long)pl * E_X + (long)(j0 + r) * ND + ch * 8);
        }
        #pragma unroll
        for (int t = 0; t < 4; ++t) {   // V tile
            int idx = tid + t * 256;
            int pl = idx >> 9, rem = idx & 511, d = rem >> 3, ch = rem & 7;
            cpa16(sb + G_V + st * G_KST + pl * G_KP + (d * 72 + ch * 8) * 2,
                  vtg + (long)pl * E_X + (long)d * NS + j0 + ch * 8);
        }
        cpa_commit();
    };
    auto issueP = [&](int jt) {
        const int j0 = jt * 64;
        if (j0 <= i0 + 127) {
            #pragma unroll
            for (int t = 0; t < 8; ++t) {
                int idx = tid + t * 256;
                int r = idx >> 4, ch = idx & 15;
                cpa16(sb + G_P + (r * 68 + ch * 4) * 4,
                      pg + (long)r * NS + j0 + ch * 4);
            }
        }
        cpa_commit();   // always commit (possibly empty) for group counting
    };

    issueKV(0);   // C_kv0
    issueP(0);    // C_p0

    const int rA = wid * 16 + (lane >> 2);
    const int iA = i0 + rA, iB = iA + 8;
    const int miA = mask[b * NS + iA], miB = mask[b * NS + iB];
    const int brow = (lane & 7) | ((lane >> 1) & 8);
    const int bcol = ((lane >> 3) & 1) * 8;

    float oacc[8][4] = {};
    float mA = -1.0e30f, mB = -1.0e30f, lA = 0.0f, lB = 0.0f;

    for (int jt = 0; jt < 16; ++jt) {
        // top: issue next KV, wait for this tile's KV (P(jt) + KV(jt+1) pending)
        if (jt + 1 < 16) { issueKV(jt + 1); cpa_wait<2>(); }
        else             { cpa_wait<1>(); }
        __syncthreads();

        const int st = jt & 1, j0 = jt * 64;
        const uint32_t kb = sb + G_K + st * G_KST;
        const uint32_t vb = sb + G_V + st * G_KST;
        const bool anyP = (j0 <= i0 + 127);
        const float* psm = (const float*)(sm + G_P);

        // ---- S = q @ k^T (bf16x3) ----
        float sacc[8][4] = {};
        #pragma unroll
        for (int kt = 0; kt < 4; ++kt) {
            uint32_t bhf[4][4], blf[4][4];
            #pragma unroll
            for (int p = 0; p < 4; ++p) {
                ldsm_x4(bhf[p], kb + ((p * 16 + brow) * 72 + bcol + kt * 16) * 2);
                ldsm_x4(blf[p], kb + G_KP + ((p * 16 + brow) * 72 + bcol + kt * 16) * 2);
            }
            #pragma unroll
            for (int nt = 0; nt < 8; ++nt) {
                const uint32_t* bp = &bhf[nt >> 1][(nt & 1) * 2];
                const uint32_t* lp = &blf[nt >> 1][(nt & 1) * 2];
                mma_bf16(sacc[nt], qah[kt], bp);
                mma_bf16(sacc[nt], qah[kt], lp);
                mma_bf16(sacc[nt], qal[kt], bp);
            }
        }

        // ---- wait P(jt), make visible ----
        if (jt + 1 < 16) cpa_wait<1>();
        else             cpa_wait<0>();
        __syncthreads();

        // ---- logits (log2 domain): scale + pshift + mask ----
        #pragma unroll
        for (int nt = 0; nt < 8; ++nt) {
            int jl = nt * 8 + (lane & 3) * 2;
            int jg = j0 + jl;
            float p0A = 0, p1A = 0, p0B = 0, p1B = 0;
            if (anyP) {
                float2 fa = *(const float2*)(psm + rA * 68 + jl);
                float2 fb = *(const float2*)(psm + (rA + 8) * 68 + jl);
                p0A = (jg     <= iA) ? fa.x : 0.0f;
                p1A = (jg + 1 <= iA) ? fa.y : 0.0f;
                p0B = (jg     <= iB) ? fb.x : 0.0f;
                p1B = (jg + 1 <= iB) ? fb.y : 0.0f;
            }
            float b0 = mbias[jg], b1 = mbias[jg + 1];
            sacc[nt][0] = miA ? fmaf(sacc[nt][0], SC, p0A) + b0 : -1.0e9f;
            sacc[nt][1] = miA ? fmaf(sacc[nt][1], SC, p1A) + b1 : -1.0e9f;
            sacc[nt][2] = miB ? fmaf(sacc[nt][2], SC, p0B) + b0 : -1.0e9f;
            sacc[nt][3] = miB ? fmaf(sacc[nt][3], SC, p1B) + b1 : -1.0e9f;
        }
        __syncthreads();              // all threads done reading P(jt)
        if (jt + 1 < 16) issueP(jt + 1);   // C_p(jt+1) into the single P buffer

        // ---- online softmax (base-2) ----
        float rmA = -1.0e30f, rmB = -1.0e30f;
        #pragma unroll
        for (int nt = 0; nt < 8; ++nt) {
            rmA = fmaxf(rmA, fmaxf(sacc[nt][0], sacc[nt][1]));
            rmB = fmaxf(rmB, fmaxf(sacc[nt][2], sacc[nt][3]));
        }
        rmA = fmaxf(rmA, __shfl_xor_sync(0xffffffffu, rmA, 1));
        rmA = fmaxf(rmA, __shfl_xor_sync(0xffffffffu, rmA, 2));
        rmB = fmaxf(rmB, __shfl_xor_sync(0xffffffffu, rmB, 1));
        rmB = fmaxf(rmB, __shfl_xor_sync(0xffffffffu, rmB, 2));

        float mnA = fmaxf(mA, rmA), mnB = fmaxf(mB, rmB);
        float alA = exp2f(mA - mnA), alB = exp2f(mB - mnB);
        mA = mnA; mB = mnB;

        float rsA = 0.0f, rsB = 0.0f;
        #pragma unroll
        for (int nt = 0; nt < 8; ++nt) {
            sacc[nt][0] = exp2f(sacc[nt][0] - mnA);
            sacc[nt][1] = exp2f(sacc[nt][1] - mnA);
            sacc[nt][2] = exp2f(sacc[nt][2] - mnB);
            sacc[nt][3] = exp2f(sacc[nt][3] - mnB);
            rsA += sacc[nt][0] + sacc[nt][1];
            rsB += sacc[nt][2] + sacc[nt][3];
        }
        rsA += __shfl_xor_sync(0xffffffffu, rsA, 1);
        rsA += __shfl_xor_sync(0xffffffffu, rsA, 2);
        rsB += __shfl_xor_sync(0xffffffffu, rsB, 1);
        rsB += __shfl_xor_sync(0xffffffffu, rsB, 2);
        lA = lA * alA + rsA;
        lB = lB * alB + rsB;
        #pragma unroll
        for (int nt = 0; nt < 8; ++nt) {
            oacc[nt][0] *= alA; oacc[nt][1] *= alA;
            oacc[nt][2] *= alB; oacc[nt][3] *= alB;
        }

        // ---- pack P into A-fragments (hi/lo) ----
        uint32_t pah[4][4], pal[4][4];
        #pragma unroll
        for (int kt = 0; kt < 4; ++kt) {
            const float* e = sacc[2 * kt];
            const float* o = sacc[2 * kt + 1];
            pah[kt][0] = packbf(e[0], e[1]); pah[kt][1] = packbf(e[2], e[3]);
            pah[kt][2] = packbf(o[0], o[1]); pah[kt][3] = packbf(o[2], o[3]);
            #pragma unroll
            for (int u = 0; u < 4; ++u) {
                __nv_bfloat162 hv = *(__nv_bfloat162*)&pah[kt][u];
                const float* src = (u < 2) ? e : o;
                float x0 = src[(u & 1) * 2]     - __low2float(hv);
                float x1 = src[(u & 1) * 2 + 1] - __high2float(hv);
                pal[kt][u] = packbf(x0, x1);
            }
        }

        // ---- O += P @ V (bf16x3) ----
        #pragma unroll
        for (int kt = 0; kt < 4; ++kt) {
            uint32_t vhf[4][4], vlf[4][4];
            #pragma unroll
            for (int p = 0; p < 4; ++p) {
                ldsm_x4(vhf[p], vb + ((p * 16 + brow) * 72 + bcol + kt * 16) * 2);
                ldsm_x4(vlf[p], vb + G_KP + ((p * 16 + brow) * 72 + bcol + kt * 16) * 2);
            }
            #pragma unroll
            for (int nt = 0; nt < 8; ++nt) {
                const uint32_t* bp = &vhf[nt >> 1][(nt & 1) * 2];
                const uint32_t* lp = &vlf[nt >> 1][(nt & 1) * 2];
                mma_bf16(oacc[nt], pah[kt], bp);
                mma_bf16(oacc[nt], pah[kt], lp);
                mma_bf16(oacc[nt], pal[kt], bp);
            }
        }
        __syncthreads();     // protect K/V stages from next top's issue
    }

    // ---- epilogue: normalize, stage in smem (K area), coalesced store ----
    const float ivA = 1.0f / lA, ivB = 1.0f / lB;
    __nv_bfloat16* so = (__nv_bfloat16*)sm;
    constexpr int OP = 128 * 72;
    #pragma unroll
    for (int nt = 0; nt < 8; ++nt) {
        int c = nt * 8 + (lane & 3) * 2;
        float a0 = oacc[nt][0] * ivA, a1 = oacc[nt][1] * ivA;
        float b0 = oacc[nt][2] * ivB, b1 = oacc[nt][3] * ivB;
        __nv_bfloat162 ha = __floats2bfloat162_rn(a0, a1);
        __nv_bfloat162 la = __floats2bfloat162_rn(a0 - __low2float(ha),
                                                  a1 - __high2float(ha));
        __nv_bfloat162 hb = __floats2bfloat162_rn(b0, b1);
        __nv_bfloat162 lb = __floats2bfloat162_rn(b0 - __low2float(hb),
                                                  b1 - __high2float(hb));
        *(__nv_bfloat162*)(so + rA * 72 + c)            = ha;
        *(__nv_bfloat162*)(so + OP + rA * 72 + c)       = la;
        *(__nv_bfloat162*)(so + (rA + 8) * 72 + c)      = hb;
        *(__nv_bfloat162*)(so + OP + (rA + 8) * 72 + c) = lb;
    }
    __syncthreads();
    __nv_bfloat16* cgb = ctx + (long)b * NS * ND + (long)i0 * ND + h * NDH;
    #pragma unroll
    for (int t = 0; t < 8; ++t) {
        int idx = tid + t * 256;
        int pl = idx >> 10, rem = idx & 1023, r = rem >> 3, ch = rem & 7;
        uint4 val = *(const uint4*)(so + pl * OP + r * 72 + ch * 8);
        *(uint4*)(cgb + (long)pl * E_X + (long)r * ND + ch * 8) = val;
    }
}

// ---------------------------------------------------------------------------
// Merged split: fp32 -> bf16 hi/lo planes, 8 segments (seg = blockIdx.y)
// ---------------------------------------------------------------------------
struct SplitArgs {
    const float4* s[8];
    __nv_bfloat16* d[8];
    int n4[8];
};
__global__ void __launch_bounds__(256) split_all(SplitArgs a)
{
    const int seg = blockIdx.y;
    const int n4 = a.n4[seg];
    const float4* s = a.s[seg];
    __nv_bfloat162* hi = (__nv_bfloat162*)a.d[seg];
    __nv_bfloat162* lo = (__nv_bfloat162*)(a.d[seg] + (long)n4 * 4);
    for (int i = blockIdx.x * 256 + threadIdx.x; i < n4; i += gridDim.x * 256) {
        float4 x = s[i];
        __nv_bfloat162 h0 = __floats2bfloat162_rn(x.x, x.y);
        __nv_bfloat162 h1 = __floats2bfloat162_rn(x.z, x.w);
        __nv_bfloat162 l0 = __floats2bfloat162_rn(x.x - __low2float(h0),
                                                  x.y - __high2float(h0));
        __nv_bfloat162 l1 = __floats2bfloat162_rn(x.z - __low2float(h1),
                                                  x.w - __high2float(h1));
        hi[2 * i] = h0; hi[2 * i + 1] = h1;
        lo[2 * i] = l0; lo[2 * i + 1] = l1;
    }
}

// ---------------------------------------------------------------------------
// V transpose per head on planes: [B,S,D] -> [B,H,DH,S]
// ---------------------------------------------------------------------------
__global__ void __launch_bounds__(256) transpose_v_kernel(
    const __nv_bfloat16* __restrict__ v, __nv_bfloat16* __restrict__ vt, long pl)
{
    __shared__ __nv_bfloat16 t0[32][33], t1[32][33];
    const int bh = blockIdx.z, b = bh / NH, h = bh % NH;
    const int j0 = blockIdx.x * 32, d0 = blockIdx.y * 32;
    const int tx = threadIdx.x, ty = threadIdx.y;
    const __nv_bfloat16* s0 = v + (long)b * NS * ND + h * NDH;
    #pragma unroll
    for (int i = 0; i < 4; ++i) {
        int j = j0 + ty + i * 8;
        long o = (long)j * ND + d0 + tx;
        t0[ty + i * 8][tx] = s0[o];
        t1[ty + i * 8][tx] = s0[o + pl];
    }
    __syncthreads();
    __nv_bfloat16* dst = vt + (long)bh * NDH * NS;
    #pragma unroll
    for (int i = 0; i < 4; ++i) {
        int d = d0 + ty + i * 8;
        long o = (long)d * NS + j0 + tx;
        dst[o]      = t0[tx][ty + i * 8];
        dst[o + pl] = t1[tx][ty + i * 8];
    }
}

// ---------------------------------------------------------------------------
extern "C" void kernel_launch(void* const* d_in, const int* in_sizes, int n_in,
                              void* d_out, int out_size)
{
    const float* query = (const float*)d_in[0];
    const float* key   = (const float*)d_in[1];
    const float* value = (const float*)d_in[2];
    const int*   mask  = (const int*)  d_in[3];
    const float* pe    = (const float*)d_in[4];
    const float* Wq    = (const float*)d_in[5];
    const float* Wk    = (const float*)d_in[6];
    const float* Wv    = (const float*)d_in[7];
    const float* Wo    = (const float*)d_in[8];
    float* out = (float*)d_out;

    void *vx, *vy, *vz, *vq, *vk, *vv, *vvt, *vctx, *vwq, *vwk, *vwv, *vwo,
         *vpe, *vps;
    cudaGetSymbolAddress(&vx, p_x);     cudaGetSymbolAddress(&vy, p_y);
    cudaGetSymbolAddress(&vz, p_z);     cudaGetSymbolAddress(&vq, p_q);
    cudaGetSymbolAddress(&vk, p_k);     cudaGetSymbolAddress(&vv, p_v);
    cudaGetSymbolAddress(&vvt, p_vt);   cudaGetSymbolAddress(&vctx, p_ctx);
    cudaGetSymbolAddress(&vwq, p_wq);   cudaGetSymbolAddress(&vwk, p_wk);
    cudaGetSymbolAddress(&vwv, p_wv);   cudaGetSymbolAddress(&vwo, p_wo);
    cudaGetSymbolAddress(&vpe, p_pe);   cudaGetSymbolAddress(&vps, g_pshift);

    __nv_bfloat16* bq   = (__nv_bfloat16*)vq;
    __nv_bfloat16* bv   = (__nv_bfloat16*)vv;
    __nv_bfloat16* bvt  = (__nv_bfloat16*)vvt;
    __nv_bfloat16* bctx = (__nv_bfloat16*)vctx;

    SplitArgs sa;
    sa.s[0] = (const float4*)query; sa.d[0] = (__nv_bfloat16*)vx;  sa.n4[0] = (int)(E_X / 4);
    sa.s[1] = (const float4*)key;   sa.d[1] = (__nv_bfloat16*)vy;  sa.n4[1] = (int)(E_X / 4);
    sa.s[2] = (const float4*)value; sa.d[2] = (__nv_bfloat16*)vz;  sa.n4[2] = (int)(E_X / 4);
    sa.s[3] = (const float4*)Wq;    sa.d[3] = (__nv_bfloat16*)vwq; sa.n4[3] = (int)(E_W / 4);
    sa.s[4] = (const float4*)Wk;    sa.d[4] = (__nv_bfloat16*)vwk; sa.n4[4] = (int)(E_W / 4);
    sa.s[5] = (const float4*)Wv;    sa.d[5] = (__nv_bfloat16*)vwv; sa.n4[5] = (int)(E_W / 4);
    sa.s[6] = (const float4*)Wo;    sa.d[6] = (__nv_bfloat16*)vwo; sa.n4[6] = (int)(E_W / 4);
    sa.s[7] = (const float4*)pe;    sa.d[7] = (__nv_bfloat16*)vpe; sa.n4[7] = (int)(E_PE / 4);
    split_all<<<dim3(1024, 8), 256>>>(sa);

    const int SM128 = 2 * (20480 + 2 * 128 * 80);  // 81920
    cudaFuncSetAttribute(gemm2<128, 0>, cudaFuncAttributeMaxDynamicSharedMemorySize, SM128);
    cudaFuncSetAttribute(gemm2<128, 1>, cudaFuncAttributeMaxDynamicSharedMemorySize, SM128);
    cudaFuncSetAttribute(gemm2<128, 2>, cudaFuncAttributeMaxDynamicSharedMemorySize, SM128);
    cudaFuncSetAttribute(fused_attn, cudaFuncAttributeMaxDynamicSharedMemorySize, G_TOT);

    const dim3 th(256);
    const long SD  = (long)NS * ND;
    const long SS  = (long)NS * NS;
    const long HSS = (long)NH * SS;

    // q,k projections merged (z via runtime pointer deltas)
    const long dA = (long)(((char*)vy - (char*)vx) / 2);
    const long dB = (long)(((char*)vwk - (char*)vwq) / 2);
    const long dC = (long)(((char*)vk - (char*)vq) / 2);
    gemm2<128, 1><<<dim3(8, 32, 2), th, SM128>>>(
        (__nv_bfloat16*)vx, (__nv_bfloat16*)vwq, vq, ND, ND, ND, ND,
        0, dA, 0, dB, 0, dC, E_X, E_W, E_X, 1.0f, 0);
    gemm2<128, 1><<<dim3(8, 32, 1), th, SM128>>>(
        (__nv_bfloat16*)vz, (__nv_bfloat16*)vwv, vv, ND, ND, ND, ND,
        0, 0, 0, 0, 0, 0, E_X, E_W, E_X, 1.0f, 0);

    // Pshift = shifted (q @ pe^T) * 8 * log2e  (triangular, shifted epilogue)
    gemm2<128, 2><<<dim3(8, 8, NB * NH), th, SM128>>>(
        bq, (__nv_bfloat16*)vpe, vps, NDH, ND, NDH, NS,
        SD, NDH, 0, (long)NS * NDH, HSS, SS, E_X, E_PE, 0, 8.0f * LOG2E, 1);

    // v^T per head (planes)
    transpose_v_kernel<<<dim3(32, 2, NB * NH), dim3(32, 8)>>>(bv, bvt, E_X);

    // fused: QK^T + skew + mask + softmax + AV -> ctx planes
    fused_attn<<<dim3(8, NB * NH), th, G_TOT>>>(
        bq, (const __nv_bfloat16*)vk, bvt, (const float*)vps, mask, bctx);

    // out = ctx @ Wo^T (fp32)
    gemm2<128, 0><<<dim3(8, 32, 1), th, SM128>>>(
        bctx, (__nv_bfloat16*)vwo, out, ND, ND, ND, ND,
        0, 0, 0, 0, 0, 0, E_X, E_W, 0, 1.0f, 0);
}

// round 8
// speedup vs baseline: 2.8872x; 1.0467x over previous
#include <cuda_runtime.h>
#include <cuda_bf16.h>
#include <cuda_fp16.h>
#include <cstdint>

#define NB 4
#define NS 1024
#define ND 1024
#define NH 16
#define NDH 64

#define E_X   ((long)NB * NS * ND)       // 4194304
#define E_W   ((long)ND * ND)            // 1048576
#define E_PE  ((long)NH * NS * NDH)      // 1048576
#define E_ATT ((long)NB * NH * NS * NS)  // 67108864

#define LOG2E 1.4426950408889634f

// Plane buffers (hi at [0,E), lo at [E,2E)), uint4-declared for 16B alignment.
__device__ uint4 p_x[E_X / 4],  p_y[E_X / 4],  p_z[E_X / 4];
__device__ uint4 p_q[E_X / 4],  p_k[E_X / 4];
__device__ uint4 p_vt[E_X / 4], p_ctx[E_X / 4];
__device__ uint4 p_wq[E_W / 4], p_wk[E_W / 4], p_wv[E_W / 4], p_wo[E_W / 4];
__device__ uint4 p_pe[E_PE / 4];
__device__ float g_pshift[E_ATT];        // shifted pos logits (log2-scaled)

// ---------------------------------------------------------------------------
// Base-ISA helpers
// ---------------------------------------------------------------------------
static __device__ __forceinline__ uint32_t smem_u32(const void* p) {
    uint32_t a;
    asm("{ .reg .u64 t; cvta.to.shared.u64 t, %1; cvt.u32.u64 %0, t; }"
        : "=r"(a) : "l"(p));
    return a;
}
static __device__ __forceinline__ void ldsm_x4(uint32_t* r, uint32_t addr) {
    asm volatile("ldmatrix.sync.aligned.m8n8.x4.shared.b16 {%0,%1,%2,%3}, [%4];"
                 : "=r"(r[0]), "=r"(r[1]), "=r"(r[2]), "=r"(r[3]) : "r"(addr));
}
// TIN: 0 = bf16 operands, 1 = fp16 operands (fp32 accum both)
template <int TIN>
static __device__ __forceinline__ void mma16(float* c, const uint32_t* a,
                                             const uint32_t* b) {
    if (TIN == 0)
        asm volatile(
            "mma.sync.aligned.m16n8k16.row.col.f32.bf16.bf16.f32 "
            "{%0,%1,%2,%3}, {%4,%5,%6,%7}, {%8,%9}, {%0,%1,%2,%3};"
            : "+f"(c[0]), "+f"(c[1]), "+f"(c[2]), "+f"(c[3])
            : "r"(a[0]), "r"(a[1]), "r"(a[2]), "r"(a[3]), "r"(b[0]), "r"(b[1]));
    else
        asm volatile(
            "mma.sync.aligned.m16n8k16.row.col.f32.f16.f16.f32 "
            "{%0,%1,%2,%3}, {%4,%5,%6,%7}, {%8,%9}, {%0,%1,%2,%3};"
            : "+f"(c[0]), "+f"(c[1]), "+f"(c[2]), "+f"(c[3])
            : "r"(a[0]), "r"(a[1]), "r"(a[2]), "r"(a[3]), "r"(b[0]), "r"(b[1]));
}
static __device__ __forceinline__ void cpa16(uint32_t d, const void* s) {
    asm volatile("cp.async.cg.shared.global [%0], [%1], 16;" :: "r"(d), "l"(s));
}
static __device__ __forceinline__ void cpa_commit() {
    asm volatile("cp.async.commit_group;" ::: "memory");
}
template <int N> static __device__ __forceinline__ void cpa_wait() {
    asm volatile("cp.async.wait_group %0;" :: "n"(N) : "memory");
}
static __device__ __forceinline__ uint32_t packhf(float x, float y) {
    __half2 t = __floats2half2_rn(x, y);
    return *(uint32_t*)&t;
}

// ---------------------------------------------------------------------------
// GEMM: C = alpha * A @ B^T, 16-bit hi/lo planes in, 3-MMA split accumulation.
// MODE 0: fp32 out.             MODE 2: shifted fp32 out (skew epilogue).
// MODE 4: fp16 hi/lo plane out. MODE 5: fp16 hi/lo plane out, transposed
//         per-head ([B,S,D] tile -> [B,H,DH,S]) via smem staging.
// TIN: input operand type (0 bf16 / 1 fp16).
// ---------------------------------------------------------------------------
template <int BN, int MODE, int TIN>
__global__ void __launch_bounds__(256, 2) gemm2(
    const void* __restrict__ Av, const void* __restrict__ Bv,
    void* __restrict__ Cv,
    int K, int lda, int ldb, int ldc,
    long aOut, long aIn, long bOut, long bIn, long cOut, long cIn,
    long aPl, long bPl, long cPl, float alpha, int tri)
{
    constexpr int BM = 128, LDE = 40;
    constexpr int WM = 2;
    constexpr int MT = (BM / WM) / 16;            // 4
    constexpr int AH = 0;
    constexpr int AL = BM * LDE * 2;
    constexpr int BH = 2 * AL;
    constexpr int BL = BH + BN * LDE * 2;
    constexpr int STAGE = BH + 2 * BN * LDE * 2;

    if (tri && (int)(blockIdx.x * BN + blockIdx.y * BM) + 255 < NS) return;

    extern __shared__ __align__(128) char sm[];
    const uint32_t sb = smem_u32(sm);

    const int tid = threadIdx.x, wid = tid >> 5, lane = tid & 31;
    const int wm = wid % WM, wn = wid / WM;
    const int z = blockIdx.z, zo = z / NH, zi = z % NH;

    const uint16_t* A = (const uint16_t*)Av;
    const uint16_t* Bp = (const uint16_t*)Bv;
    const uint16_t* Ab = A + (long)zo * aOut + (long)zi * aIn
                         + (long)(blockIdx.y * BM) * lda;
    const uint16_t* Bb = Bp + (long)zo * bOut + (long)zi * bIn
                         + (long)(blockIdx.x * BN) * ldb;

    auto issue = [&](int s, int kt) {
        const uint32_t st = sb + s * STAGE;
        #pragma unroll
        for (int t = 0; t < 2; ++t) {
            int r = (tid + t * 256) >> 2, sg = tid & 3;
            const uint16_t* g = Ab + (long)r * lda + kt + sg * 8;
            uint32_t d = st + r * 80 + sg * 16;
            cpa16(d + AH, g);
            cpa16(d + AL, g + aPl);
        }
        #pragma unroll
        for (int t = 0; t < BN / 64; ++t) {
            int r = (tid + t * 256) >> 2, sg = tid & 3;
            const uint16_t* g = Bb + (long)r * ldb + kt + sg * 8;
            uint32_t d = st + r * 80 + sg * 16;
            cpa16(d + BH, g);
            cpa16(d + BL, g + bPl);
        }
        cpa_commit();
    };

    const uint32_t aRelH = AH +
        (uint32_t)(((wm * MT * 16 + (lane & 15)) * LDE + (lane >> 4) * 8) * 2);
    const uint32_t aRelL = aRelH + (AL - AH);
    const int brow = (lane & 7) | ((lane >> 1) & 8);
    const uint32_t bRelH = BH +
        (uint32_t)(((wn * 32 + brow) * LDE + ((lane >> 3) & 1) * 8) * 2);
    const uint32_t bRelL = bRelH + (BL - BH);

    float acc[MT][4][4] = {};
    issue(0, 0);

    const int nch = K >> 5;
    for (int c = 0; c < nch; ++c) {
        if (c + 1 < nch) { issue((c + 1) & 1, (c + 1) << 5); cpa_wait<1>(); }
        else             { cpa_wait<0>(); }
        __syncthreads();
        const uint32_t s0 = sb + (c & 1) * STAGE;
        #pragma unroll
        for (int ks = 0; ks < 2; ++ks) {
            uint32_t ah[MT][4], al[MT][4], bh[2][4], bl[2][4];
            #pragma unroll
            for (int mt = 0; mt < MT; ++mt) {
                ldsm_x4(ah[mt], s0 + aRelH + mt * (16 * LDE * 2) + ks * 32);
                ldsm_x4(al[mt], s0 + aRelL + mt * (16 * LDE * 2) + ks * 32);
            }
            #pragma unroll
            for (int nt2 = 0; nt2 < 2; ++nt2) {
                ldsm_x4(bh[nt2], s0 + bRelH + nt2 * (16 * LDE * 2) + ks * 32);
                ldsm_x4(bl[nt2], s0 + bRelL + nt2 * (16 * LDE * 2) + ks * 32);
            }
            #pragma unroll
            for (int mt = 0; mt < MT; ++mt)
                #pragma unroll
                for (int nt = 0; nt < 4; ++nt) {
                    float* cc = acc[mt][nt];
                    const uint32_t* bhp = &bh[nt >> 1][(nt & 1) * 2];
                    const uint32_t* blp = &bl[nt >> 1][(nt & 1) * 2];
                    mma16<TIN>(cc, ah[mt], bhp);
                    mma16<TIN>(cc, ah[mt], blp);
                    mma16<TIN>(cc, al[mt], bhp);
                }
        }
        __syncthreads();
    }

    const int r0 = wm * (MT * 16) + (lane >> 2);
    const int c0 = wn * 32 + (lane & 3) * 2;
    if (MODE == 4) {
        __half* Ch = (__half*)Cv + (long)zo * cOut + (long)zi * cIn
                     + (long)(blockIdx.y * BM) * ldc + blockIdx.x * BN;
        #pragma unroll
        for (int mt = 0; mt < MT; ++mt)
            #pragma unroll
            for (int nt = 0; nt < 4; ++nt)
                #pragma unroll
                for (int h = 0; h < 2; ++h) {
                    long off = (long)(r0 + mt * 16 + h * 8) * ldc + c0 + nt * 8;
                    float x0 = acc[mt][nt][h * 2 + 0] * alpha;
                    float x1 = acc[mt][nt][h * 2 + 1] * alpha;
                    __half2 hi = __floats2half2_rn(x0, x1);
                    __half2 lo = __floats2half2_rn(
                        x0 - __half2float(__low2half(hi)),
                        x1 - __half2float(__high2half(hi)));
                    *(__half2*)(Ch + off)       = hi;
                    *(__half2*)(Ch + off + cPl) = lo;
                }
    } else if (MODE == 5) {
        // Transposed per-head store: stage [c][r] in smem, write [B,H,DH,S].
        __half* st = (__half*)sm;
        constexpr int OFFE = 128 * 136;
        #pragma unroll
        for (int mt = 0; mt < MT; ++mt)
            #pragma unroll
            for (int nt = 0; nt < 4; ++nt)
                #pragma unroll
                for (int h = 0; h < 2; ++h) {
                    int r = r0 + mt * 16 + h * 8;
                    int c = c0 + nt * 8;
                    float x0 = acc[mt][nt][h * 2 + 0] * alpha;
                    float x1 = acc[mt][nt][h * 2 + 1] * alpha;
                    __half2 hi = __floats2half2_rn(x0, x1);
                    __half2 lo = __floats2half2_rn(
                        x0 - __half2float(__low2half(hi)),
                        x1 - __half2float(__high2half(hi)));
                    st[c * 136 + r]                = __low2half(hi);
                    st[(c + 1) * 136 + r]          = __high2half(hi);
                    st[OFFE + c * 136 + r]         = __low2half(lo);
                    st[OFFE + (c + 1) * 136 + r]   = __high2half(lo);
                }
        __syncthreads();
        const int b = blockIdx.y >> 3, s0 = (blockIdx.y & 7) * 128;
        __half* vt = (__half*)Cv;
        #pragma unroll
        for (int t = 0; t < 16; ++t) {
            int u = tid + t * 256;
            int pl = u >> 11, rem = u & 2047, c = rem >> 4, rch = rem & 15;
            int d = blockIdx.x * 128 + c;
            int hh = d >> 6, dh = d & 63;
            uint4 val = *(const uint4*)(st + pl * OFFE + c * 136 + rch * 8);
            *(uint4*)(vt + (long)pl * cPl
                      + ((long)(b * NH + hh) * NDH + dh) * NS + s0 + rch * 8) = val;
        }
    } else if (MODE == 0) {
        float* Cf = (float*)Cv + (long)zo * cOut + (long)zi * cIn
                    + (long)(blockIdx.y * BM) * ldc + blockIdx.x * BN;
        #pragma unroll
        for (int mt = 0; mt < MT; ++mt)
            #pragma unroll
            for (int nt = 0; nt < 4; ++nt)
                #pragma unroll
                for (int h = 0; h < 2; ++h) {
                    long off = (long)(r0 + mt * 16 + h * 8) * ldc + c0 + nt * 8;
                    float2 v = make_float2(acc[mt][nt][h * 2 + 0] * alpha,
                                           acc[mt][nt][h * 2 + 1] * alpha);
                    *(float2*)(Cf + off) = v;
                }
    } else {  // MODE 2: shifted store  Cshift[i, c-(NS-1)+i]
        float* Cf = (float*)Cv + (long)zo * cOut + (long)zi * cIn;
        const int ig0 = blockIdx.y * BM + r0;
        const int cg0 = blockIdx.x * BN + c0;
        #pragma unroll
        for (int mt = 0; mt < MT; ++mt)
            #pragma unroll
            for (int h = 0; h < 2; ++h) {
                int ig = ig0 + mt * 16 + h * 8;
                #pragma unroll
                for (int nt = 0; nt < 4; ++nt) {
                    int j = cg0 + nt * 8 - (NS - 1) + ig;
                    float x0 = acc[mt][nt][h * 2 + 0] * alpha;
                    float x1 = acc[mt][nt][h * 2 + 1] * alpha;
                    if (j >= 0)     Cf[(long)ig * NS + j]     = x0;
                    if (j + 1 >= 0) Cf[(long)ig * NS + j + 1] = x1;
                }
            }
    }
}

// ---------------------------------------------------------------------------
// Fused attention (fp16 operands): logit2 = SC*(q@k^T) + Pshift (j<=i) + mbias;
// online softmax base-2; O += P_fp16 @ (Vh + Vl)  -- 2-MMA AV.
// ---------------------------------------------------------------------------
constexpr int G_KST = 18432, G_KP = 9216;        // K/V stage: hi+lo, 64x72 fp16
constexpr int G_K  = 0;
constexpr int G_V  = 36864;
constexpr int G_MB = 73728;
constexpr int G_P  = 77824;                      // P single stage 128*68*4
constexpr int G_TOT = 112640;

__global__ void __launch_bounds__(256, 2) fused_attn(
    const __half* __restrict__ q, const __half* __restrict__ k,
    const __half* __restrict__ vt, const float* __restrict__ pshift,
    const int* __restrict__ mask, __nv_bfloat16* __restrict__ ctx)
{
    extern __shared__ __align__(128) char sm[];
    const uint32_t sb = smem_u32(sm);
    const int tid = threadIdx.x, wid = tid >> 5, lane = tid & 31;
    const int i0 = (7 - blockIdx.x) * 128;       // heavy-first
    const int bh = blockIdx.y, b = bh / NH, h = bh % NH;
    const float SC = 0.125f * LOG2E;

    const __half* qg  = q + (long)b * NS * ND + (long)i0 * ND + h * NDH;
    const __half* kg  = k + (long)b * NS * ND + h * NDH;
    const __half* vtg = vt + (long)bh * NDH * NS;
    const float* pg = pshift + (long)bh * NS * NS + (long)i0 * NS;

    float* mbias = (float*)(sm + G_MB);
    for (int j = tid; j < NS; j += 256)
        mbias[j] = mask[b * NS + j] ? 0.0f : -1.5e9f;

    // ---- Prologue: Q through the K area, consume to registers ----
    #pragma unroll
    for (int t = 0; t < 8; ++t) {
        int idx = tid + t * 256;
        int pl = idx >> 10, rem = idx & 1023, r = rem >> 3, ch = rem & 7;
        cpa16(sb + pl * G_KST + (r * 72 + ch * 8) * 2,
              qg + (long)pl * E_X + (long)r * ND + ch * 8);
    }
    cpa_commit();
    cpa_wait<0>();
    __syncthreads();

    uint32_t qah[4][4], qal[4][4];
    {
        uint32_t base = sb + ((wid * 16 + (lane & 15)) * 72 + (lane >> 4) * 8) * 2;
        #pragma unroll
        for (int kt = 0; kt < 4; ++kt) {
            ldsm_x4(qah[kt], base + kt * 32);
            ldsm_x4(qal[kt], base + G_KST + kt * 32);
        }
    }
    __syncthreads();     // Q fully consumed; K area free for reuse

    auto issueKV = [&](int jt) {
        const int st = jt & 1, j0 = jt * 64;
        #pragma unroll
        for (int t = 0; t < 4; ++t) {   // K tile
            int idx = tid + t * 256;
            int pl = idx >> 9, rem = idx & 511, r = rem >> 3, ch = rem & 7;
            cpa16(sb + G_K + st * G_KST + pl * G_KP + (r * 72 + ch * 8) * 2,
                  kg + (long)pl * E_X + (long)(j0 + r) * ND + ch * 8);
        }
        #pragma unroll
        for (int t = 0; t < 4; ++t) {   // V tile
            int idx = tid + t * 256;
            int pl = idx >> 9, rem = idx & 511, d = rem >> 3, ch = rem & 7;
            cpa16(sb + G_V + st * G_KST + pl * G_KP + (d * 72 + ch * 8) * 2,
                  vtg + (long)pl * E_X + (long)d * NS + j0 + ch * 8);
        }
        cpa_commit();
    };
    auto issueP = [&](int jt) {
        const int j0 = jt * 64;
        if (j0 <= i0 + 127) {
            #pragma unroll
            for (int t = 0; t < 8; ++t) {
                int idx = tid + t * 256;
                int r = idx >> 4, ch = idx & 15;
                cpa16(sb + G_P + (r * 68 + ch * 4) * 4,
                      pg + (long)r * NS + j0 + ch * 4);
            }
        }
        cpa_commit();   // always commit for group counting
    };

    issueKV(0);
    issueP(0);

    const int rA = wid * 16 + (lane >> 2);
    const int iA = i0 + rA, iB = iA + 8;
    const int miA = mask[b * NS + iA], miB = mask[b * NS + iB];
    const int brow = (lane & 7) | ((lane >> 1) & 8);
    const int bcol = ((lane >> 3) & 1) * 8;

    float oacc[8][4] = {};
    float mA = -1.0e30f, mB = -1.0e30f, lA = 0.0f, lB = 0.0f;

    for (int jt = 0; jt < 16; ++jt) {
        if (jt + 1 < 16) { issueKV(jt + 1); cpa_wait<2>(); }
        else             { cpa_wait<1>(); }
        __syncthreads();

        const int st = jt & 1, j0 = jt * 64;
        const uint32_t kb = sb + G_K + st * G_KST;
        const uint32_t vb = sb + G_V + st * G_KST;
        const bool anyP = (j0 <= i0 + 127);
        const float* psm = (const float*)(sm + G_P);

        // ---- S = q @ k^T (fp16x3) ----
        float sacc[8][4] = {};
        #pragma unroll
        for (int kt = 0; kt < 4; ++kt) {
            uint32_t bhf[4][4], blf[4][4];
            #pragma unroll
            for (int p = 0; p < 4; ++p) {
                ldsm_x4(bhf[p], kb + ((p * 16 + brow) * 72 + bcol + kt * 16) * 2);
                ldsm_x4(blf[p], kb + G_KP + ((p * 16 + brow) * 72 + bcol + kt * 16) * 2);
            }
            #pragma unroll
            for (int nt = 0; nt < 8; ++nt) {
                const uint32_t* bp = &bhf[nt >> 1][(nt & 1) * 2];
                const uint32_t* lp = &blf[nt >> 1][(nt & 1) * 2];
                mma16<1>(sacc[nt], qah[kt], bp);
                mma16<1>(sacc[nt], qah[kt], lp);
                mma16<1>(sacc[nt], qal[kt], bp);
            }
        }

        // ---- wait P(jt), make visible ----
        if (jt + 1 < 16) cpa_wait<1>();
        else             cpa_wait<0>();
        __syncthreads();

        // ---- logits (log2 domain): scale + pshift + mask ----
        #pragma unroll
        for (int nt = 0; nt < 8; ++nt) {
            int jl = nt * 8 + (lane & 3) * 2;
            int jg = j0 + jl;
            float p0A = 0, p1A = 0, p0B = 0, p1B = 0;
            if (anyP) {
                float2 fa = *(const float2*)(psm + rA * 68 + jl);
                float2 fb = *(const float2*)(psm + (rA + 8) * 68 + jl);
                p0A = (jg     <= iA) ? fa.x : 0.0f;
                p1A = (jg + 1 <= iA) ? fa.y : 0.0f;
                p0B = (jg     <= iB) ? fb.x : 0.0f;
                p1B = (jg + 1 <= iB) ? fb.y : 0.0f;
            }
            float b0 = mbias[jg], b1 = mbias[jg + 1];
            sacc[nt][0] = miA ? fmaf(sacc[nt][0], SC, p0A) + b0 : -1.0e9f;
            sacc[nt][1] = miA ? fmaf(sacc[nt][1], SC, p1A) + b1 : -1.0e9f;
            sacc[nt][2] = miB ? fmaf(sacc[nt][2], SC, p0B) + b0 : -1.0e9f;
            sacc[nt][3] = miB ? fmaf(sacc[nt][3], SC, p1B) + b1 : -1.0e9f;
        }
        __syncthreads();                   // all threads done reading P(jt)
        if (jt + 1 < 16) issueP(jt + 1);   // refill the single P buffer

        // ---- online softmax (base-2) ----
        float rmA = -1.0e30f, rmB = -1.0e30f;
        #pragma unroll
        for (int nt = 0; nt < 8; ++nt) {
            rmA = fmaxf(rmA, fmaxf(sacc[nt][0], sacc[nt][1]));
            rmB = fmaxf(rmB, fmaxf(sacc[nt][2], sacc[nt][3]));
        }
        rmA = fmaxf(rmA, __shfl_xor_sync(0xffffffffu, rmA, 1));
        rmA = fmaxf(rmA, __shfl_xor_sync(0xffffffffu, rmA, 2));
        rmB = fmaxf(rmB, __shfl_xor_sync(0xffffffffu, rmB, 1));
        rmB = fmaxf(rmB, __shfl_xor_sync(0xffffffffu, rmB, 2));

        float mnA = fmaxf(mA, rmA), mnB = fmaxf(mB, rmB);
        float alA = exp2f(mA - mnA), alB = exp2f(mB - mnB);
        mA = mnA; mB = mnB;

        float rsA = 0.0f, rsB = 0.0f;
        #pragma unroll
        for (int nt = 0; nt < 8; ++nt) {
            sacc[nt][0] = exp2f(sacc[nt][0] - mnA);
            sacc[nt][1] = exp2f(sacc[nt][1] - mnA);
            sacc[nt][2] = exp2f(sacc[nt][2] - mnB);
            sacc[nt][3] = exp2f(sacc[nt][3] - mnB);
            rsA += sacc[nt][0] + sacc[nt][1];
            rsB += sacc[nt][2] + sacc[nt][3];
        }
        rsA += __shfl_xor_sync(0xffffffffu, rsA, 1);
        rsA += __shfl_xor_sync(0xffffffffu, rsA, 2);
        rsB += __shfl_xor_sync(0xffffffffu, rsB, 1);
        rsB += __shfl_xor_sync(0xffffffffu, rsB, 2);
        lA = lA * alA + rsA;
        lB = lB * alB + rsB;
        #pragma unroll
        for (int nt = 0; nt < 8; ++nt) {
            oacc[nt][0] *= alA; oacc[nt][1] *= alA;
            oacc[nt][2] *= alB; oacc[nt][3] *= alB;
        }

        // ---- pack P into fp16 A-fragments (single plane) ----
        uint32_t pah[4][4];
        #pragma unroll
        for (int kt = 0; kt < 4; ++kt) {
            const float* e = sacc[2 * kt];
            const float* o = sacc[2 * kt + 1];
            pah[kt][0] = packhf(e[0], e[1]); pah[kt][1] = packhf(e[2], e[3]);
            pah[kt][2] = packhf(o[0], o[1]); pah[kt][3] = packhf(o[2], o[3]);
        }

        // ---- O += P @ (Vh + Vl)  (2-MMA AV) ----
        #pragma unroll
        for (int kt = 0; kt < 4; ++kt) {
            uint32_t vhf[4][4], vlf[4][4];
            #pragma unroll
            for (int p = 0; p < 4; ++p) {
                ldsm_x4(vhf[p], vb + ((p * 16 + brow) * 72 + bcol + kt * 16) * 2);
                ldsm_x4(vlf[p], vb + G_KP + ((p * 16 + brow) * 72 + bcol + kt * 16) * 2);
            }
            #pragma unroll
            for (int nt = 0; nt < 8; ++nt) {
                const uint32_t* bp = &vhf[nt >> 1][(nt & 1) * 2];
                const uint32_t* lp = &vlf[nt >> 1][(nt & 1) * 2];
                mma16<1>(oacc[nt], pah[kt], bp);
                mma16<1>(oacc[nt], pah[kt], lp);
            }
        }
        __syncthreads();
    }

    // ---- epilogue: normalize, stage in smem (K area), coalesced store ----
    const float ivA = 1.0f / lA, ivB = 1.0f / lB;
    __nv_bfloat16* so = (__nv_bfloat16*)sm;
    constexpr int OP = 128 * 72;
    #pragma unroll
    for (int nt = 0; nt < 8; ++nt) {
        int c = nt * 8 + (lane & 3) * 2;
        float a0 = oacc[nt][0] * ivA, a1 = oacc[nt][1] * ivA;
        float b0 = oacc[nt][2] * ivB, b1 = oacc[nt][3] * ivB;
        __nv_bfloat162 ha = __floats2bfloat162_rn(a0, a1);
        __nv_bfloat162 la = __floats2bfloat162_rn(a0 - __low2float(ha),
                                                  a1 - __high2float(ha));
        __nv_bfloat162 hb = __floats2bfloat162_rn(b0, b1);
        __nv_bfloat162 lb = __floats2bfloat162_rn(b0 - __low2float(hb),
                                                  b1 - __high2float(hb));
        *(__nv_bfloat162*)(so + rA * 72 + c)            = ha;
        *(__nv_bfloat162*)(so + OP + rA * 72 + c)       = la;
        *(__nv_bfloat162*)(so + (rA + 8) * 72 + c)      = hb;
        *(__nv_bfloat162*)(so + OP + (rA + 8) * 72 + c) = lb;
    }
    __syncthreads();
    __nv_bfloat16* cgb = ctx + (long)b * NS * ND + (long)i0 * ND + h * NDH;
    #pragma unroll
    for (int t = 0; t < 8; ++t) {
        int idx = tid + t * 256;
        int pl = idx >> 10, rem = idx & 1023, r = rem >> 3, ch = rem & 7;
        uint4 val = *(const uint4*)(so + pl * OP + r * 72 + ch * 8);
        *(uint4*)(cgb + (long)pl * E_X + (long)r * ND + ch * 8) = val;
    }
}

// ---------------------------------------------------------------------------
// Merged split: fp32 -> 16-bit hi/lo planes (bf16, or fp16 when f16[seg]=1)
// ---------------------------------------------------------------------------
struct SplitArgs {
    const float4* s[8];
    uint16_t* d[8];
    int n4[8];
    int f16[8];
};
__global__ void __launch_bounds__(256) split_all(SplitArgs a)
{
    const int seg = blockIdx.y;
    const int n4 = a.n4[seg];
    const float4* s = a.s[seg];
    uint16_t* dst = a.d[seg];
    const long pl = (long)n4 * 4;
    const bool f16 = a.f16[seg] != 0;
    for (int i = blockIdx.x * 256 + threadIdx.x; i < n4; i += gridDim.x * 256) {
        float4 x = s[i];
        uint32_t h0, h1, l0, l1;
        if (f16) {
            __half2 a0 = __floats2half2_rn(x.x, x.y);
            __half2 a1 = __floats2half2_rn(x.z, x.w);
            __half2 b0 = __floats2half2_rn(x.x - __half2float(__low2half(a0)),
                                           x.y - __half2float(__high2half(a0)));
            __half2 b1 = __floats2half2_rn(x.z - __half2float(__low2half(a1)),
                                           x.w - __half2float(__high2half(a1)));
            h0 = *(uint32_t*)&a0; h1 = *(uint32_t*)&a1;
            l0 = *(uint32_t*)&b0; l1 = *(uint32_t*)&b1;
        } else {
            __nv_bfloat162 a0 = __floats2bfloat162_rn(x.x, x.y);
            __nv_bfloat162 a1 = __floats2bfloat162_rn(x.z, x.w);
            __nv_bfloat162 b0 = __floats2bfloat162_rn(x.x - __low2float(a0),
                                                      x.y - __high2float(a0));
            __nv_bfloat162 b1 = __floats2bfloat162_rn(x.z - __low2float(a1),
                                                      x.w - __high2float(a1));
            h0 = *(uint32_t*)&a0; h1 = *(uint32_t*)&a1;
            l0 = *(uint32_t*)&b0; l1 = *(uint32_t*)&b1;
        }
        ((uint32_t*)dst)[2 * i]          = h0;
        ((uint32_t*)dst)[2 * i + 1]      = h1;
        ((uint32_t*)(dst + pl))[2 * i]     = l0;
        ((uint32_t*)(dst + pl))[2 * i + 1] = l1;
    }
}

// ---------------------------------------------------------------------------
extern "C" void kernel_launch(void* const* d_in, const int* in_sizes, int n_in,
                              void* d_out, int out_size)
{
    const float* query = (const float*)d_in[0];
    const float* key   = (const float*)d_in[1];
    const float* value = (const float*)d_in[2];
    const int*   mask  = (const int*)  d_in[3];
    const float* pe    = (const float*)d_in[4];
    const float* Wq    = (const float*)d_in[5];
    const float* Wk    = (const float*)d_in[6];
    const float* Wv    = (const float*)d_in[7];
    const float* Wo    = (const float*)d_in[8];
    float* out = (float*)d_out;

    void *vx, *vy, *vz, *vq, *vk, *vvt, *vctx, *vwq, *vwk, *vwv, *vwo,
         *vpe, *vps;
    cudaGetSymbolAddress(&vx, p_x);     cudaGetSymbolAddress(&vy, p_y);
    cudaGetSymbolAddress(&vz, p_z);     cudaGetSymbolAddress(&vq, p_q);
    cudaGetSymbolAddress(&vk, p_k);     cudaGetSymbolAddress(&vvt, p_vt);
    cudaGetSymbolAddress(&vctx, p_ctx);
    cudaGetSymbolAddress(&vwq, p_wq);   cudaGetSymbolAddress(&vwk, p_wk);
    cudaGetSymbolAddress(&vwv, p_wv);   cudaGetSymbolAddress(&vwo, p_wo);
    cudaGetSymbolAddress(&vpe, p_pe);   cudaGetSymbolAddress(&vps, g_pshift);

    SplitArgs sa;
    sa.s[0] = (const float4*)query; sa.d[0] = (uint16_t*)vx;  sa.n4[0] = (int)(E_X / 4);  sa.f16[0] = 0;
    sa.s[1] = (const float4*)key;   sa.d[1] = (uint16_t*)vy;  sa.n4[1] = (int)(E_X / 4);  sa.f16[1] = 0;
    sa.s[2] = (const float4*)value; sa.d[2] = (uint16_t*)vz;  sa.n4[2] = (int)(E_X / 4);  sa.f16[2] = 0;
    sa.s[3] = (const float4*)Wq;    sa.d[3] = (uint16_t*)vwq; sa.n4[3] = (int)(E_W / 4);  sa.f16[3] = 0;
    sa.s[4] = (const float4*)Wk;    sa.d[4] = (uint16_t*)vwk; sa.n4[4] = (int)(E_W / 4);  sa.f16[4] = 0;
    sa.s[5] = (const float4*)Wv;    sa.d[5] = (uint16_t*)vwv; sa.n4[5] = (int)(E_W / 4);  sa.f16[5] = 0;
    sa.s[6] = (const float4*)Wo;    sa.d[6] = (uint16_t*)vwo; sa.n4[6] = (int)(E_W / 4);  sa.f16[6] = 0;
    sa.s[7] = (const float4*)pe;    sa.d[7] = (uint16_t*)vpe; sa.n4[7] = (int)(E_PE / 4); sa.f16[7] = 1;
    split_all<<<dim3(1024, 8), 256>>>(sa);

    const int SM128 = 2 * (20480 + 2 * 128 * 80);  // 81920
    cudaFuncSetAttribute(gemm2<128, 0, 0>, cudaFuncAttributeMaxDynamicSharedMemorySize, SM128);
    cudaFuncSetAttribute(gemm2<128, 2, 1>, cudaFuncAttributeMaxDynamicSharedMemorySize, SM128);
    cudaFuncSetAttribute(gemm2<128, 4, 0>, cudaFuncAttributeMaxDynamicSharedMemorySize, SM128);
    cudaFuncSetAttribute(gemm2<128, 5, 0>, cudaFuncAttributeMaxDynamicSharedMemorySize, SM128);
    cudaFuncSetAttribute(fused_attn, cudaFuncAttributeMaxDynamicSharedMemorySize, G_TOT);

    const dim3 th(256);
    const long SD  = (long)NS * ND;
    const long SS  = (long)NS * NS;
    const long HSS = (long)NH * SS;

    // q,k projections merged (z via runtime pointer deltas) -> fp16 planes
    const long dA = (long)(((char*)vy - (char*)vx) / 2);
    const long dB = (long)(((char*)vwk - (char*)vwq) / 2);
    const long dC = (long)(((char*)vk - (char*)vq) / 2);
    gemm2<128, 4, 0><<<dim3(8, 32, 2), th, SM128>>>(
        vx, vwq, vq, ND, ND, ND, ND,
        0, dA, 0, dB, 0, dC, E_X, E_W, E_X, 1.0f, 0);

    // v projection -> vt fp16 planes, transposed per head
    gemm2<128, 5, 0><<<dim3(8, 32, 1), th, SM128>>>(
        vz, vwv, vvt, ND, ND, ND, ND,
        0, 0, 0, 0, 0, 0, E_X, E_W, E_X, 1.0f, 0);

    // Pshift = shifted (q @ pe^T) * 8 * log2e  (fp16 in, triangular)
    gemm2<128, 2, 1><<<dim3(8, 8, NB * NH), th, SM128>>>(
        vq, vpe, vps, NDH, ND, NDH, NS,
        SD, NDH, 0, (long)NS * NDH, HSS, SS, E_X, E_PE, 0, 8.0f * LOG2E, 1);

    // fused: QK^T + skew + mask + softmax + AV -> ctx planes (bf16)
    fused_attn<<<dim3(8, NB * NH), th, G_TOT>>>(
        (const __half*)vq, (const __half*)vk, (const __half*)vvt,
        (const float*)vps, mask, (__nv_bfloat16*)vctx);

    // out = ctx @ Wo^T (bf16 in, fp32 out)
    gemm2<128, 0, 0><<<dim3(8, 32, 1), th, SM128>>>(
        vctx, vwo, out, ND, ND, ND, ND,
        0, 0, 0, 0, 0, 0, E_X, E_W, 0, 1.0f, 0);
}

// round 9
// speedup vs baseline: 3.4532x; 1.1960x over previous
#include <cuda_runtime.h>
#include <cuda_bf16.h>
#include <cuda_fp16.h>
#include <cstdint>

#define NB 4
#define NS 1024
#define ND 1024
#define NH 16
#define NDH 64

#define E_X   ((long)NB * NS * ND)       // 4194304
#define E_W   ((long)ND * ND)            // 1048576
#define E_PE  ((long)NH * NS * NDH)      // 1048576
#define E_ATT ((long)NB * NH * NS * NS)  // 67108864

#define LOG2E 1.4426950408889634f

// Plane buffers (hi at [0,E), lo at [E,2E)), uint4-declared for 16B alignment.
__device__ uint4 p_x[E_X / 4],  p_y[E_X / 4],  p_z[E_X / 4];
__device__ uint4 p_q[E_X / 4],  p_k[E_X / 4];
__device__ uint4 p_vt[E_X / 4], p_ctx[E_X / 4];
__device__ uint4 p_wq[E_W / 4], p_wk[E_W / 4], p_wv[E_W / 4], p_wo[E_W / 4];
__device__ uint4 p_pe[E_PE / 4];
__device__ float g_pshift[E_ATT];        // shifted pos logits (log2-scaled)

// ---------------------------------------------------------------------------
// Base-ISA helpers
// ---------------------------------------------------------------------------
static __device__ __forceinline__ uint32_t smem_u32(const void* p) {
    uint32_t a;
    asm("{ .reg .u64 t; cvta.to.shared.u64 t, %1; cvt.u32.u64 %0, t; }"
        : "=r"(a) : "l"(p));
    return a;
}
static __device__ __forceinline__ void ldsm_x4(uint32_t* r, uint32_t addr) {
    asm volatile("ldmatrix.sync.aligned.m8n8.x4.shared.b16 {%0,%1,%2,%3}, [%4];"
                 : "=r"(r[0]), "=r"(r[1]), "=r"(r[2]), "=r"(r[3]) : "r"(addr));
}
// TIN: 0 = bf16 operands, 1 = fp16 operands (fp32 accum both)
template <int TIN>
static __device__ __forceinline__ void mma16(float* c, const uint32_t* a,
                                             const uint32_t* b) {
    if (TIN == 0)
        asm volatile(
            "mma.sync.aligned.m16n8k16.row.col.f32.bf16.bf16.f32 "
            "{%0,%1,%2,%3}, {%4,%5,%6,%7}, {%8,%9}, {%0,%1,%2,%3};"
            : "+f"(c[0]), "+f"(c[1]), "+f"(c[2]), "+f"(c[3])
            : "r"(a[0]), "r"(a[1]), "r"(a[2]), "r"(a[3]), "r"(b[0]), "r"(b[1]));
    else
        asm volatile(
            "mma.sync.aligned.m16n8k16.row.col.f32.f16.f16.f32 "
            "{%0,%1,%2,%3}, {%4,%5,%6,%7}, {%8,%9}, {%0,%1,%2,%3};"
            : "+f"(c[0]), "+f"(c[1]), "+f"(c[2]), "+f"(c[3])
            : "r"(a[0]), "r"(a[1]), "r"(a[2]), "r"(a[3]), "r"(b[0]), "r"(b[1]));
}
static __device__ __forceinline__ void cpa16(uint32_t d, const void* s) {
    asm volatile("cp.async.cg.shared.global [%0], [%1], 16;" :: "r"(d), "l"(s));
}
static __device__ __forceinline__ void cpa_commit() {
    asm volatile("cp.async.commit_group;" ::: "memory");
}
template <int N> static __device__ __forceinline__ void cpa_wait() {
    asm volatile("cp.async.wait_group %0;" :: "n"(N) : "memory");
}
static __device__ __forceinline__ uint32_t packhf(float x, float y) {
    __half2 t = __floats2half2_rn(x, y);
    return *(uint32_t*)&t;
}

// ---------------------------------------------------------------------------
// GEMM: C = alpha * A @ B^T, 16-bit hi/lo planes in, split accumulation.
// MODE 0: fp32 out.             MODE 2: shifted fp32 out (skew epilogue).
// MODE 4: fp16 hi/lo plane out. MODE 5: fp16 SINGLE-plane out, transposed
//         per-head ([B,S,D] tile -> [B,H,DH,S]) via smem staging.
// TIN: operand type (0 bf16 / 1 fp16).
// ASP: A single plane (2-MMA: ah*bh + ah*bl) instead of 3-MMA split.
// ---------------------------------------------------------------------------
template <int BN, int MODE, int TIN, int ASP>
__global__ void __launch_bounds__(256, 2) gemm2(
    const void* __restrict__ Av, const void* __restrict__ Bv,
    void* __restrict__ Cv,
    int K, int lda, int ldb, int ldc,
    long aOut, long aIn, long bOut, long bIn, long cOut, long cIn,
    long aPl, long bPl, long cPl, float alpha, int tri)
{
    constexpr int BM = 128, LDE = 40;
    constexpr int WM = 2;
    constexpr int MT = (BM / WM) / 16;            // 4
    constexpr int AH = 0;
    constexpr int AL = BM * LDE * 2;
    constexpr int BH = 2 * AL;
    constexpr int BL = BH + BN * LDE * 2;
    constexpr int STAGE = BH + 2 * BN * LDE * 2;

    if (tri && (int)(blockIdx.x * BN + blockIdx.y * BM) + 255 < NS) return;

    extern __shared__ __align__(128) char sm[];
    const uint32_t sb = smem_u32(sm);

    const int tid = threadIdx.x, wid = tid >> 5, lane = tid & 31;
    const int wm = wid % WM, wn = wid / WM;
    const int z = blockIdx.z, zo = z / NH, zi = z % NH;

    const uint16_t* A = (const uint16_t*)Av;
    const uint16_t* Bp = (const uint16_t*)Bv;
    const uint16_t* Ab = A + (long)zo * aOut + (long)zi * aIn
                         + (long)(blockIdx.y * BM) * lda;
    const uint16_t* Bb = Bp + (long)zo * bOut + (long)zi * bIn
                         + (long)(blockIdx.x * BN) * ldb;

    auto issue = [&](int s, int kt) {
        const uint32_t st = sb + s * STAGE;
        #pragma unroll
        for (int t = 0; t < 2; ++t) {
            int r = (tid + t * 256) >> 2, sg = tid & 3;
            const uint16_t* g = Ab + (long)r * lda + kt + sg * 8;
            uint32_t d = st + r * 80 + sg * 16;
            cpa16(d + AH, g);
            if (!ASP) cpa16(d + AL, g + aPl);
        }
        #pragma unroll
        for (int t = 0; t < BN / 64; ++t) {
            int r = (tid + t * 256) >> 2, sg = tid & 3;
            const uint16_t* g = Bb + (long)r * ldb + kt + sg * 8;
            uint32_t d = st + r * 80 + sg * 16;
            cpa16(d + BH, g);
            cpa16(d + BL, g + bPl);
        }
        cpa_commit();
    };

    const uint32_t aRelH = AH +
        (uint32_t)(((wm * MT * 16 + (lane & 15)) * LDE + (lane >> 4) * 8) * 2);
    const uint32_t aRelL = aRelH + (AL - AH);
    const int brow = (lane & 7) | ((lane >> 1) & 8);
    const uint32_t bRelH = BH +
        (uint32_t)(((wn * 32 + brow) * LDE + ((lane >> 3) & 1) * 8) * 2);
    const uint32_t bRelL = bRelH + (BL - BH);

    float acc[MT][4][4] = {};
    issue(0, 0);

    const int nch = K >> 5;
    for (int c = 0; c < nch; ++c) {
        if (c + 1 < nch) { issue((c + 1) & 1, (c + 1) << 5); cpa_wait<1>(); }
        else             { cpa_wait<0>(); }
        __syncthreads();
        const uint32_t s0 = sb + (c & 1) * STAGE;
        #pragma unroll
        for (int ks = 0; ks < 2; ++ks) {
            uint32_t ah[MT][4], al[MT][4], bh[2][4], bl[2][4];
            #pragma unroll
            for (int mt = 0; mt < MT; ++mt) {
                ldsm_x4(ah[mt], s0 + aRelH + mt * (16 * LDE * 2) + ks * 32);
                if (!ASP)
                    ldsm_x4(al[mt], s0 + aRelL + mt * (16 * LDE * 2) + ks * 32);
            }
            #pragma unroll
            for (int nt2 = 0; nt2 < 2; ++nt2) {
                ldsm_x4(bh[nt2], s0 + bRelH + nt2 * (16 * LDE * 2) + ks * 32);
                ldsm_x4(bl[nt2], s0 + bRelL + nt2 * (16 * LDE * 2) + ks * 32);
            }
            #pragma unroll
            for (int mt = 0; mt < MT; ++mt)
                #pragma unroll
                for (int nt = 0; nt < 4; ++nt) {
                    float* cc = acc[mt][nt];
                    const uint32_t* bhp = &bh[nt >> 1][(nt & 1) * 2];
                    const uint32_t* blp = &bl[nt >> 1][(nt & 1) * 2];
                    mma16<TIN>(cc, ah[mt], bhp);
                    mma16<TIN>(cc, ah[mt], blp);
                    if (!ASP) mma16<TIN>(cc, al[mt], bhp);
                }
        }
        __syncthreads();
    }

    const int r0 = wm * (MT * 16) + (lane >> 2);
    const int c0 = wn * 32 + (lane & 3) * 2;
    if (MODE == 4) {
        __half* Ch = (__half*)Cv + (long)zo * cOut + (long)zi * cIn
                     + (long)(blockIdx.y * BM) * ldc + blockIdx.x * BN;
        #pragma unroll
        for (int mt = 0; mt < MT; ++mt)
            #pragma unroll
            for (int nt = 0; nt < 4; ++nt)
                #pragma unroll
                for (int h = 0; h < 2; ++h) {
                    long off = (long)(r0 + mt * 16 + h * 8) * ldc + c0 + nt * 8;
                    float x0 = acc[mt][nt][h * 2 + 0] * alpha;
                    float x1 = acc[mt][nt][h * 2 + 1] * alpha;
                    __half2 hi = __floats2half2_rn(x0, x1);
                    __half2 lo = __floats2half2_rn(
                        x0 - __half2float(__low2half(hi)),
                        x1 - __half2float(__high2half(hi)));
                    *(__half2*)(Ch + off)       = hi;
                    *(__half2*)(Ch + off + cPl) = lo;
                }
    } else if (MODE == 5) {
        // Transposed per-head single-plane store: [B,S,D] tile -> [B,H,DH,S]
        __half* st = (__half*)sm;
        #pragma unroll
        for (int mt = 0; mt < MT; ++mt)
            #pragma unroll
            for (int nt = 0; nt < 4; ++nt)
                #pragma unroll
                for (int h = 0; h < 2; ++h) {
                    int r = r0 + mt * 16 + h * 8;
                    int c = c0 + nt * 8;
                    float x0 = acc[mt][nt][h * 2 + 0] * alpha;
                    float x1 = acc[mt][nt][h * 2 + 1] * alpha;
                    __half2 hi = __floats2half2_rn(x0, x1);
                    st[c * 136 + r]       = __low2half(hi);
                    st[(c + 1) * 136 + r] = __high2half(hi);
                }
        __syncthreads();
        const int b = blockIdx.y >> 3, s0 = (blockIdx.y & 7) * 128;
        __half* vt = (__half*)Cv;
        #pragma unroll
        for (int t = 0; t < 8; ++t) {
            int u = tid + t * 256;
            int c = u >> 4, rch = u & 15;
            int d = blockIdx.x * 128 + c;
            int hh = d >> 6, dh = d & 63;
            uint4 val = *(const uint4*)(st + c * 136 + rch * 8);
            *(uint4*)(vt + ((long)(b * NH + hh) * NDH + dh) * NS + s0 + rch * 8) = val;
        }
    } else if (MODE == 0) {
        float* Cf = (float*)Cv + (long)zo * cOut + (long)zi * cIn
                    + (long)(blockIdx.y * BM) * ldc + blockIdx.x * BN;
        #pragma unroll
        for (int mt = 0; mt < MT; ++mt)
            #pragma unroll
            for (int nt = 0; nt < 4; ++nt)
                #pragma unroll
                for (int h = 0; h < 2; ++h) {
                    long off = (long)(r0 + mt * 16 + h * 8) * ldc + c0 + nt * 8;
                    float2 v = make_float2(acc[mt][nt][h * 2 + 0] * alpha,
                                           acc[mt][nt][h * 2 + 1] * alpha);
                    *(float2*)(Cf + off) = v;
                }
    } else {  // MODE 2: shifted store  Cshift[i, c-(NS-1)+i]
        float* Cf = (float*)Cv + (long)zo * cOut + (long)zi * cIn;
        const int ig0 = blockIdx.y * BM + r0;
        const int cg0 = blockIdx.x * BN + c0;
        #pragma unroll
        for (int mt = 0; mt < MT; ++mt)
            #pragma unroll
            for (int h = 0; h < 2; ++h) {
                int ig = ig0 + mt * 16 + h * 8;
                #pragma unroll
                for (int nt = 0; nt < 4; ++nt) {
                    int j = cg0 + nt * 8 - (NS - 1) + ig;
                    float x0 = acc[mt][nt][h * 2 + 0] * alpha;
                    float x1 = acc[mt][nt][h * 2 + 1] * alpha;
                    if (j >= 0)     Cf[(long)ig * NS + j]     = x0;
                    if (j + 1 >= 0) Cf[(long)ig * NS + j + 1] = x1;
                }
            }
    }
}

// ---------------------------------------------------------------------------
// Fused attention, lean precision: QK = qh*kh (1 MMA), AV = P*Vh (1 MMA).
// K/V/Q single fp16 plane; P fp32 double-buffered; ctx single fp16 plane.
// ---------------------------------------------------------------------------
constexpr int G_KS = 9216;                       // 64 x 72 fp16 stage
constexpr int G_K  = 0;                          // 2 stages -> [0, 18432)
constexpr int G_V  = 18432;                      // 2 stages -> [18432, 36864)
constexpr int G_MB = 36864;                      // mask bias -> [36864, 40960)
constexpr int G_P  = 40960;                      // 2 stages x 34816 -> 110592
constexpr int G_PST = 34816;
constexpr int G_TOT = 110592;

__global__ void __launch_bounds__(256, 2) fused_attn(
    const __half* __restrict__ q, const __half* __restrict__ k,
    const __half* __restrict__ vt, const float* __restrict__ pshift,
    const int* __restrict__ mask, __half* __restrict__ ctx)
{
    extern __shared__ __align__(128) char sm[];
    const uint32_t sb = smem_u32(sm);
    const int tid = threadIdx.x, wid = tid >> 5, lane = tid & 31;
    const int i0 = (7 - blockIdx.x) * 128;       // heavy-first
    const int bh = blockIdx.y, b = bh / NH, h = bh % NH;
    const float SC = 0.125f * LOG2E;

    const __half* qg  = q + (long)b * NS * ND + (long)i0 * ND + h * NDH;
    const __half* kg  = k + (long)b * NS * ND + h * NDH;
    const __half* vtg = vt + (long)bh * NDH * NS;
    const float* pg = pshift + (long)bh * NS * NS + (long)i0 * NS;

    float* mbias = (float*)(sm + G_MB);
    for (int j = tid; j < NS; j += 256)
        mbias[j] = mask[b * NS + j] ? 0.0f : -1.5e9f;

    // ---- Prologue: Q hi plane through the K area, consume to registers ----
    #pragma unroll
    for (int t = 0; t < 4; ++t) {
        int idx = tid + t * 256;
        int r = idx >> 3, ch = idx & 7;
        cpa16(sb + (r * 72 + ch * 8) * 2, qg + (long)r * ND + ch * 8);
    }
    cpa_commit();
    cpa_wait<0>();
    __syncthreads();

    uint32_t qah[4][4];
    {
        uint32_t base = sb + ((wid * 16 + (lane & 15)) * 72 + (lane >> 4) * 8) * 2;
        #pragma unroll
        for (int kt = 0; kt < 4; ++kt) ldsm_x4(qah[kt], base + kt * 32);
    }
    __syncthreads();     // Q fully consumed; K area free for reuse

    auto issue = [&](int jt) {
        const int st = jt & 1, j0 = jt * 64;
        #pragma unroll
        for (int t = 0; t < 2; ++t) {   // K hi tile
            int idx = tid + t * 256;
            int r = idx >> 3, ch = idx & 7;
            cpa16(sb + G_K + st * G_KS + (r * 72 + ch * 8) * 2,
                  kg + (long)(j0 + r) * ND + ch * 8);
        }
        #pragma unroll
        for (int t = 0; t < 2; ++t) {   // V hi tile
            int idx = tid + t * 256;
            int d = idx >> 3, ch = idx & 7;
            cpa16(sb + G_V + st * G_KS + (d * 72 + ch * 8) * 2,
                  vtg + (long)d * NS + j0 + ch * 8);
        }
        if (j0 <= i0 + 127) {           // Pshift tile (fp32)
            #pragma unroll
            for (int t = 0; t < 8; ++t) {
                int idx = tid + t * 256;
                int r = idx >> 4, ch = idx & 15;
                cpa16(sb + G_P + st * G_PST + (r * 68 + ch * 4) * 4,
                      pg + (long)r * NS + j0 + ch * 4);
            }
        }
        cpa_commit();
    };

    issue(0);

    const int rA = wid * 16 + (lane >> 2);
    const int iA = i0 + rA, iB = iA + 8;
    const int miA = mask[b * NS + iA], miB = mask[b * NS + iB];
    const int brow = (lane & 7) | ((lane >> 1) & 8);
    const int bcol = ((lane >> 3) & 1) * 8;

    float oacc[8][4] = {};
    float mA = -1.0e30f, mB = -1.0e30f, lA = 0.0f, lB = 0.0f;

    for (int jt = 0; jt < 16; ++jt) {
        if (jt + 1 < 16) { issue(jt + 1); cpa_wait<1>(); }
        else             { cpa_wait<0>(); }
        __syncthreads();

        const int st = jt & 1, j0 = jt * 64;
        const uint32_t kb = sb + G_K + st * G_KS;
        const uint32_t vb = sb + G_V + st * G_KS;
        const bool anyP = (j0 <= i0 + 127);
        const float* psm = (const float*)(sm + G_P + st * G_PST);

        // ---- S = qh @ kh^T (1 MMA) ----
        float sacc[8][4] = {};
        #pragma unroll
        for (int kt = 0; kt < 4; ++kt) {
            uint32_t bhf[4][4];
            #pragma unroll
            for (int p = 0; p < 4; ++p)
                ldsm_x4(bhf[p], kb + ((p * 16 + brow) * 72 + bcol + kt * 16) * 2);
            #pragma unroll
            for (int nt = 0; nt < 8; ++nt)
                mma16<1>(sacc[nt], qah[kt], &bhf[nt >> 1][(nt & 1) * 2]);
        }

        // ---- logits (log2 domain): scale + pshift + mask ----
        #pragma unroll
        for (int nt = 0; nt < 8; ++nt) {
            int jl = nt * 8 + (lane & 3) * 2;
            int jg = j0 + jl;
            float p0A = 0, p1A = 0, p0B = 0, p1B = 0;
            if (anyP) {
                float2 fa = *(const float2*)(psm + rA * 68 + jl);
                float2 fb = *(const float2*)(psm + (rA + 8) * 68 + jl);
                p0A = (jg     <= iA) ? fa.x : 0.0f;
                p1A = (jg + 1 <= iA) ? fa.y : 0.0f;
                p0B = (jg     <= iB) ? fb.x : 0.0f;
                p1B = (jg + 1 <= iB) ? fb.y : 0.0f;
            }
            float b0 = mbias[jg], b1 = mbias[jg + 1];
            sacc[nt][0] = miA ? fmaf(sacc[nt][0], SC, p0A) + b0 : -1.0e9f;
            sacc[nt][1] = miA ? fmaf(sacc[nt][1], SC, p1A) + b1 : -1.0e9f;
            sacc[nt][2] = miB ? fmaf(sacc[nt][2], SC, p0B) + b0 : -1.0e9f;
            sacc[nt][3] = miB ? fmaf(sacc[nt][3], SC, p1B) + b1 : -1.0e9f;
        }

        // ---- online softmax (base-2) ----
        float rmA = -1.0e30f, rmB = -1.0e30f;
        #pragma unroll
        for (int nt = 0; nt < 8; ++nt) {
            rmA = fmaxf(rmA, fmaxf(sacc[nt][0], sacc[nt][1]));
            rmB = fmaxf(rmB, fmaxf(sacc[nt][2], sacc[nt][3]));
        }
        rmA = fmaxf(rmA, __shfl_xor_sync(0xffffffffu, rmA, 1));
        rmA = fmaxf(rmA, __shfl_xor_sync(0xffffffffu, rmA, 2));
        rmB = fmaxf(rmB, __shfl_xor_sync(0xffffffffu, rmB, 1));
        rmB = fmaxf(rmB, __shfl_xor_sync(0xffffffffu, rmB, 2));

        float mnA = fmaxf(mA, rmA), mnB = fmaxf(mB, rmB);
        float alA = exp2f(mA - mnA), alB = exp2f(mB - mnB);
        mA = mnA; mB = mnB;

        float rsA = 0.0f, rsB = 0.0f;
        #pragma unroll
        for (int nt = 0; nt < 8; ++nt) {
            sacc[nt][0] = exp2f(sacc[nt][0] - mnA);
            sacc[nt][1] = exp2f(sacc[nt][1] - mnA);
            sacc[nt][2] = exp2f(sacc[nt][2] - mnB);
            sacc[nt][3] = exp2f(sacc[nt][3] - mnB);
            rsA += sacc[nt][0] + sacc[nt][1];
            rsB += sacc[nt][2] + sacc[nt][3];
        }
        rsA += __shfl_xor_sync(0xffffffffu, rsA, 1);
        rsA += __shfl_xor_sync(0xffffffffu, rsA, 2);
        rsB += __shfl_xor_sync(0xffffffffu, rsB, 1);
        rsB += __shfl_xor_sync(0xffffffffu, rsB, 2);
        lA = lA * alA + rsA;
        lB = lB * alB + rsB;
        #pragma unroll
        for (int nt = 0; nt < 8; ++nt) {
            oacc[nt][0] *= alA; oacc[nt][1] *= alA;
            oacc[nt][2] *= alB; oacc[nt][3] *= alB;
        }

        // ---- pack P into fp16 A-fragments ----
        uint32_t pah[4][4];
        #pragma unroll
        for (int kt = 0; kt < 4; ++kt) {
            const float* e = sacc[2 * kt];
            const float* o = sacc[2 * kt + 1];
            pah[kt][0] = packhf(e[0], e[1]); pah[kt][1] = packhf(e[2], e[3]);
            pah[kt][2] = packhf(o[0], o[1]); pah[kt][3] = packhf(o[2], o[3]);
        }

        // ---- O += P @ Vh (1 MMA) ----
        #pragma unroll
        for (int kt = 0; kt < 4; ++kt) {
            uint32_t vhf[4][4];
            #pragma unroll
            for (int p = 0; p < 4; ++p)
                ldsm_x4(vhf[p], vb + ((p * 16 + brow) * 72 + bcol + kt * 16) * 2);
            #pragma unroll
            for (int nt = 0; nt < 8; ++nt)
                mma16<1>(oacc[nt], pah[kt], &vhf[nt >> 1][(nt & 1) * 2]);
        }
        __syncthreads();     // protect stages from next iteration's issue
    }

    // ---- epilogue: normalize, stage fp16 in smem (K area), coalesced store ----
    const float ivA = 1.0f / lA, ivB = 1.0f / lB;
    __half* so = (__half*)sm;
    #pragma unroll
    for (int nt = 0; nt < 8; ++nt) {
        int c = nt * 8 + (lane & 3) * 2;
        *(__half2*)(so + rA * 72 + c) =
            __floats2half2_rn(oacc[nt][0] * ivA, oacc[nt][1] * ivA);
        *(__half2*)(so + (rA + 8) * 72 + c) =
            __floats2half2_rn(oacc[nt][2] * ivB, oacc[nt][3] * ivB);
    }
    __syncthreads();
    __half* cgb = ctx + (long)b * NS * ND + (long)i0 * ND + h * NDH;
    #pragma unroll
    for (int t = 0; t < 4; ++t) {
        int idx = tid + t * 256;
        int r = idx >> 3, ch = idx & 7;
        uint4 val = *(const uint4*)(so + r * 72 + ch * 8);
        *(uint4*)(cgb + (long)r * ND + ch * 8) = val;
    }
}

// ---------------------------------------------------------------------------
// Merged split: fp32 -> 16-bit hi/lo planes (bf16, or fp16 when f16[seg]=1)
// ---------------------------------------------------------------------------
struct SplitArgs {
    const float4* s[8];
    uint16_t* d[8];
    int n4[8];
    int f16[8];
};
__global__ void __launch_bounds__(256) split_all(SplitArgs a)
{
    const int seg = blockIdx.y;
    const int n4 = a.n4[seg];
    const float4* s = a.s[seg];
    uint16_t* dst = a.d[seg];
    const long pl = (long)n4 * 4;
    const bool f16 = a.f16[seg] != 0;
    for (int i = blockIdx.x * 256 + threadIdx.x; i < n4; i += gridDim.x * 256) {
        float4 x = s[i];
        uint32_t h0, h1, l0, l1;
        if (f16) {
            __half2 a0 = __floats2half2_rn(x.x, x.y);
            __half2 a1 = __floats2half2_rn(x.z, x.w);
            __half2 b0 = __floats2half2_rn(x.x - __half2float(__low2half(a0)),
                                           x.y - __half2float(__high2half(a0)));
            __half2 b1 = __floats2half2_rn(x.z - __half2float(__low2half(a1)),
                                           x.w - __half2float(__high2half(a1)));
            h0 = *(uint32_t*)&a0; h1 = *(uint32_t*)&a1;
            l0 = *(uint32_t*)&b0; l1 = *(uint32_t*)&b1;
        } else {
            __nv_bfloat162 a0 = __floats2bfloat162_rn(x.x, x.y);
            __nv_bfloat162 a1 = __floats2bfloat162_rn(x.z, x.w);
            __nv_bfloat162 b0 = __floats2bfloat162_rn(x.x - __low2float(a0),
                                                      x.y - __high2float(a0));
            __nv_bfloat162 b1 = __floats2bfloat162_rn(x.z - __low2float(a1),
                                                      x.w - __high2float(a1));
            h0 = *(uint32_t*)&a0; h1 = *(uint32_t*)&a1;
            l0 = *(uint32_t*)&b0; l1 = *(uint32_t*)&b1;
        }
        ((uint32_t*)dst)[2 * i]          = h0;
        ((uint32_t*)dst)[2 * i + 1]      = h1;
        ((uint32_t*)(dst + pl))[2 * i]     = l0;
        ((uint32_t*)(dst + pl))[2 * i + 1] = l1;
    }
}

// ---------------------------------------------------------------------------
extern "C" void kernel_launch(void* const* d_in, const int* in_sizes, int n_in,
                              void* d_out, int out_size)
{
    const float* query = (const float*)d_in[0];
    const float* key   = (const float*)d_in[1];
    const float* value = (const float*)d_in[2];
    const int*   mask  = (const int*)  d_in[3];
    const float* pe    = (const float*)d_in[4];
    const float* Wq    = (const float*)d_in[5];
    const float* Wk    = (const float*)d_in[6];
    const float* Wv    = (const float*)d_in[7];
    const float* Wo    = (const float*)d_in[8];
    float* out = (float*)d_out;

    void *vx, *vy, *vz, *vq, *vk, *vvt, *vctx, *vwq, *vwk, *vwv, *vwo,
         *vpe, *vps;
    cudaGetSymbolAddress(&vx, p_x);     cudaGetSymbolAddress(&vy, p_y);
    cudaGetSymbolAddress(&vz, p_z);     cudaGetSymbolAddress(&vq, p_q);
    cudaGetSymbolAddress(&vk, p_k);     cudaGetSymbolAddress(&vvt, p_vt);
    cudaGetSymbolAddress(&vctx, p_ctx);
    cudaGetSymbolAddress(&vwq, p_wq);   cudaGetSymbolAddress(&vwk, p_wk);
    cudaGetSymbolAddress(&vwv, p_wv);   cudaGetSymbolAddress(&vwo, p_wo);
    cudaGetSymbolAddress(&vpe, p_pe);   cudaGetSymbolAddress(&vps, g_pshift);

    SplitArgs sa;
    sa.s[0] = (const float4*)query; sa.d[0] = (uint16_t*)vx;  sa.n4[0] = (int)(E_X / 4);  sa.f16[0] = 0;
    sa.s[1] = (const float4*)key;   sa.d[1] = (uint16_t*)vy;  sa.n4[1] = (int)(E_X / 4);  sa.f16[1] = 0;
    sa.s[2] = (const float4*)value; sa.d[2] = (uint16_t*)vz;  sa.n4[2] = (int)(E_X / 4);  sa.f16[2] = 0;
    sa.s[3] = (const float4*)Wq;    sa.d[3] = (uint16_t*)vwq; sa.n4[3] = (int)(E_W / 4);  sa.f16[3] = 0;
    sa.s[4] = (const float4*)Wk;    sa.d[4] = (uint16_t*)vwk; sa.n4[4] = (int)(E_W / 4);  sa.f16[4] = 0;
    sa.s[5] = (const float4*)Wv;    sa.d[5] = (uint16_t*)vwv; sa.n4[5] = (int)(E_W / 4);  sa.f16[5] = 0;
    sa.s[6] = (const float4*)Wo;    sa.d[6] = (uint16_t*)vwo; sa.n4[6] = (int)(E_W / 4);  sa.f16[6] = 1;
    sa.s[7] = (const float4*)pe;    sa.d[7] = (uint16_t*)vpe; sa.n4[7] = (int)(E_PE / 4); sa.f16[7] = 1;
    split_all<<<dim3(1024, 8), 256>>>(sa);

    const int SM128 = 2 * (20480 + 2 * 128 * 80);  // 81920
    cudaFuncSetAttribute(gemm2<128, 0, 1, 1>, cudaFuncAttributeMaxDynamicSharedMemorySize, SM128);
    cudaFuncSetAttribute(gemm2<128, 2, 1, 0>, cudaFuncAttributeMaxDynamicSharedMemorySize, SM128);
    cudaFuncSetAttribute(gemm2<128, 4, 0, 0>, cudaFuncAttributeMaxDynamicSharedMemorySize, SM128);
    cudaFuncSetAttribute(gemm2<128, 5, 0, 0>, cudaFuncAttributeMaxDynamicSharedMemorySize, SM128);
    cudaFuncSetAttribute(fused_attn, cudaFuncAttributeMaxDynamicSharedMemorySize, G_TOT);

    const dim3 th(256);
    const long SD  = (long)NS * ND;
    const long SS  = (long)NS * NS;
    const long HSS = (long)NH * SS;

    // q,k projections merged (z via runtime pointer deltas) -> fp16 planes
    const long dA = (long)(((char*)vy - (char*)vx) / 2);
    const long dB = (long)(((char*)vwk - (char*)vwq) / 2);
    const long dC = (long)(((char*)vk - (char*)vq) / 2);
    gemm2<128, 4, 0, 0><<<dim3(8, 32, 2), th, SM128>>>(
        vx, vwq, vq, ND, ND, ND, ND,
        0, dA, 0, dB, 0, dC, E_X, E_W, E_X, 1.0f, 0);

    // v projection -> vt single fp16 plane, transposed per head
    gemm2<128, 5, 0, 0><<<dim3(8, 32, 1), th, SM128>>>(
        vz, vwv, vvt, ND, ND, ND, ND,
        0, 0, 0, 0, 0, 0, E_X, E_W, 0, 1.0f, 0);

    // Pshift = shifted (q @ pe^T) * 8 * log2e  (fp16 hi/lo 3-MMA, triangular)
    gemm2<128, 2, 1, 0><<<dim3(8, 8, NB * NH), th, SM128>>>(
        vq, vpe, vps, NDH, ND, NDH, NS,
        SD, NDH, 0, (long)NS * NDH, HSS, SS, E_X, E_PE, 0, 8.0f * LOG2E, 1);

    // fused: QK^T + skew + mask + softmax + AV -> ctx (single fp16 plane)
    fused_attn<<<dim3(8, NB * NH), th, G_TOT>>>(
        (const __half*)vq, (const __half*)vk, (const __half*)vvt,
        (const float*)vps, mask, (__half*)vctx);

    // out = ctx(fp16, single plane) @ Wo(fp16 hi/lo)^T  -- 2-MMA
    gemm2<128, 0, 1, 1><<<dim3(8, 32, 1), th, SM128>>>(
        vctx, vwo, out, ND, ND, ND, ND,
        0, 0, 0, 0, 0, 0, 0, E_W, 0, 1.0f, 0);
}

// round 10
// speedup vs baseline: 3.5515x; 1.0285x over previous
#include <cuda_runtime.h>
#include <cuda_bf16.h>
#include <cuda_fp16.h>
#include <cstdint>

#define NB 4
#define NS 1024
#define ND 1024
#define NH 16
#define NDH 64

#define E_X   ((long)NB * NS * ND)       // 4194304
#define E_W   ((long)ND * ND)            // 1048576
#define E_PE  ((long)NH * NS * NDH)      // 1048576
#define E_ATT ((long)NB * NH * NS * NS)  // 67108864

#define LOG2E 1.4426950408889634f

// Plane buffers (hi at [0,E), lo at [E,2E)), uint4-declared for 16B alignment.
__device__ uint4 p_x[E_X / 4],  p_y[E_X / 4],  p_z[E_X / 4];
__device__ uint4 p_q[E_X / 4],  p_k[E_X / 4];
__device__ uint4 p_vt[E_X / 4], p_ctx[E_X / 4];
__device__ uint4 p_wq[E_W / 4], p_wk[E_W / 4], p_wv[E_W / 4], p_wo[E_W / 4];
__device__ uint4 p_pe[E_PE / 4];
__device__ float g_pshift[E_ATT];        // shifted pos logits (log2-scaled)

// ---------------------------------------------------------------------------
// Base-ISA helpers
// ---------------------------------------------------------------------------
static __device__ __forceinline__ uint32_t smem_u32(const void* p) {
    uint32_t a;
    asm("{ .reg .u64 t; cvta.to.shared.u64 t, %1; cvt.u32.u64 %0, t; }"
        : "=r"(a) : "l"(p));
    return a;
}
static __device__ __forceinline__ void ldsm_x4(uint32_t* r, uint32_t addr) {
    asm volatile("ldmatrix.sync.aligned.m8n8.x4.shared.b16 {%0,%1,%2,%3}, [%4];"
                 : "=r"(r[0]), "=r"(r[1]), "=r"(r[2]), "=r"(r[3]) : "r"(addr));
}
// TIN: 0 = bf16 operands, 1 = fp16 operands (fp32 accum both)
template <int TIN>
static __device__ __forceinline__ void mma16(float* c, const uint32_t* a,
                                             const uint32_t* b) {
    if (TIN == 0)
        asm volatile(
            "mma.sync.aligned.m16n8k16.row.col.f32.bf16.bf16.f32 "
            "{%0,%1,%2,%3}, {%4,%5,%6,%7}, {%8,%9}, {%0,%1,%2,%3};"
            : "+f"(c[0]), "+f"(c[1]), "+f"(c[2]), "+f"(c[3])
            : "r"(a[0]), "r"(a[1]), "r"(a[2]), "r"(a[3]), "r"(b[0]), "r"(b[1]));
    else
        asm volatile(
            "mma.sync.aligned.m16n8k16.row.col.f32.f16.f16.f32 "
            "{%0,%1,%2,%3}, {%4,%5,%6,%7}, {%8,%9}, {%0,%1,%2,%3};"
            : "+f"(c[0]), "+f"(c[1]), "+f"(c[2]), "+f"(c[3])
            : "r"(a[0]), "r"(a[1]), "r"(a[2]), "r"(a[3]), "r"(b[0]), "r"(b[1]));
}
static __device__ __forceinline__ void cpa16(uint32_t d, const void* s) {
    asm volatile("cp.async.cg.shared.global [%0], [%1], 16;" :: "r"(d), "l"(s));
}
static __device__ __forceinline__ void cpa_commit() {
    asm volatile("cp.async.commit_group;" ::: "memory");
}
template <int N> static __device__ __forceinline__ void cpa_wait() {
    asm volatile("cp.async.wait_group %0;" :: "n"(N) : "memory");
}
static __device__ __forceinline__ uint32_t packhf(float x, float y) {
    __half2 t = __floats2half2_rn(x, y);
    return *(uint32_t*)&t;
}

// ---------------------------------------------------------------------------
// GEMM: C = alpha * A @ B^T, 16-bit hi/lo planes in, split accumulation.
// MODE 0: fp32 out.
// MODE 2: shifted fp32 out (skew), smem-staged coalesced per-row stores.
// MODE 6: merged qkv projection — z<2: fp16 hi/lo plane out (q,k);
//         z==2: fp16 single-plane transposed per-head out (uses Av2/Bv2/Cv2).
// TIN: operand type (0 bf16 / 1 fp16).  ASP: A single-plane (2-MMA).
// Pipeline: one sync per K-chunk ({wait; sync; issue(next); compute}).
// ---------------------------------------------------------------------------
template <int BN, int MODE, int TIN, int ASP>
__global__ void __launch_bounds__(256, 2) gemm2(
    const void* __restrict__ Av, const void* __restrict__ Bv,
    void* __restrict__ Cv,
    const void* __restrict__ Av2, const void* __restrict__ Bv2,
    void* __restrict__ Cv2,
    int K, int lda, int ldb, int ldc,
    long aOut, long aIn, long bOut, long bIn, long cOut, long cIn,
    long aPl, long bPl, long cPl, float alpha, int tri)
{
    constexpr int BM = 128, LDE = 40;
    constexpr int WM = 2;
    constexpr int MT = (BM / WM) / 16;            // 4
    constexpr int AH = 0;
    constexpr int AL = BM * LDE * 2;
    constexpr int BH = 2 * AL;
    constexpr int BL = BH + BN * LDE * 2;
    constexpr int STAGE = BH + 2 * BN * LDE * 2;

    if (tri && (int)(blockIdx.x * BN + blockIdx.y * BM) + 255 < NS) return;

    extern __shared__ __align__(128) char sm[];
    const uint32_t sb = smem_u32(sm);

    const int tid = threadIdx.x, wid = tid >> 5, lane = tid & 31;
    const int wm = wid % WM, wn = wid / WM;
    const int z = blockIdx.z;
    const bool alt = (MODE == 6 && z == 2);
    const int ze = alt ? 0 : z;
    const int zo = ze / NH, zi = ze % NH;

    const uint16_t* A = (const uint16_t*)(alt ? Av2 : Av);
    const uint16_t* Bp = (const uint16_t*)(alt ? Bv2 : Bv);
    const uint16_t* Ab = A + (long)zo * aOut + (long)zi * aIn
                         + (long)(blockIdx.y * BM) * lda;
    const uint16_t* Bb = Bp + (long)zo * bOut + (long)zi * bIn
                         + (long)(blockIdx.x * BN) * ldb;

    auto issue = [&](int s, int kt) {
        const uint32_t st = sb + s * STAGE;
        #pragma unroll
        for (int t = 0; t < 2; ++t) {
            int r = (tid + t * 256) >> 2, sg = tid & 3;
            const uint16_t* g = Ab + (long)r * lda + kt + sg * 8;
            uint32_t d = st + r * 80 + sg * 16;
            cpa16(d + AH, g);
            if (!ASP) cpa16(d + AL, g + aPl);
        }
        #pragma unroll
        for (int t = 0; t < BN / 64; ++t) {
            int r = (tid + t * 256) >> 2, sg = tid & 3;
            const uint16_t* g = Bb + (long)r * ldb + kt + sg * 8;
            uint32_t d = st + r * 80 + sg * 16;
            cpa16(d + BH, g);
            cpa16(d + BL, g + bPl);
        }
        cpa_commit();
    };

    const uint32_t aRelH = AH +
        (uint32_t)(((wm * MT * 16 + (lane & 15)) * LDE + (lane >> 4) * 8) * 2);
    const uint32_t aRelL = aRelH + (AL - AH);
    const int brow = (lane & 7) | ((lane >> 1) & 8);
    const uint32_t bRelH = BH +
        (uint32_t)(((wn * 32 + brow) * LDE + ((lane >> 3) & 1) * 8) * 2);
    const uint32_t bRelL = bRelH + (BL - BH);

    float acc[MT][4][4] = {};
    issue(0, 0);

    const int nch = K >> 5;
    for (int c = 0; c < nch; ++c) {
        cpa_wait<0>();
        __syncthreads();
        if (c + 1 < nch) issue((c + 1) & 1, (c + 1) << 5);
        const uint32_t s0 = sb + (c & 1) * STAGE;
        #pragma unroll
        for (int ks = 0; ks < 2; ++ks) {
            uint32_t ah[MT][4], al[MT][4], bh[2][4], bl[2][4];
            #pragma unroll
            for (int mt = 0; mt < MT; ++mt) {
                ldsm_x4(ah[mt], s0 + aRelH + mt * (16 * LDE * 2) + ks * 32);
                if (!ASP)
                    ldsm_x4(al[mt], s0 + aRelL + mt * (16 * LDE * 2) + ks * 32);
            }
            #pragma unroll
            for (int nt2 = 0; nt2 < 2; ++nt2) {
                ldsm_x4(bh[nt2], s0 + bRelH + nt2 * (16 * LDE * 2) + ks * 32);
                ldsm_x4(bl[nt2], s0 + bRelL + nt2 * (16 * LDE * 2) + ks * 32);
            }
            #pragma unroll
            for (int mt = 0; mt < MT; ++mt)
                #pragma unroll
                for (int nt = 0; nt < 4; ++nt) {
                    float* cc = acc[mt][nt];
                    const uint32_t* bhp = &bh[nt >> 1][(nt & 1) * 2];
                    const uint32_t* blp = &bl[nt >> 1][(nt & 1) * 2];
                    mma16<TIN>(cc, ah[mt], bhp);
                    mma16<TIN>(cc, ah[mt], blp);
                    if (!ASP) mma16<TIN>(cc, al[mt], bhp);
                }
        }
    }

    const int r0 = wm * (MT * 16) + (lane >> 2);
    const int c0 = wn * 32 + (lane & 3) * 2;
    if (MODE == 6) {
        if (z < 2) {
            __half* Ch = (__half*)Cv + (long)zo * cOut + (long)zi * cIn
                         + (long)(blockIdx.y * BM) * ldc + blockIdx.x * BN;
            #pragma unroll
            for (int mt = 0; mt < MT; ++mt)
                #pragma unroll
                for (int nt = 0; nt < 4; ++nt)
                    #pragma unroll
                    for (int h = 0; h < 2; ++h) {
                        long off = (long)(r0 + mt * 16 + h * 8) * ldc + c0 + nt * 8;
                        float x0 = acc[mt][nt][h * 2 + 0] * alpha;
                        float x1 = acc[mt][nt][h * 2 + 1] * alpha;
                        __half2 hi = __floats2half2_rn(x0, x1);
                        __half2 lo = __floats2half2_rn(
                            x0 - __half2float(__low2half(hi)),
                            x1 - __half2float(__high2half(hi)));
                        *(__half2*)(Ch + off)       = hi;
                        *(__half2*)(Ch + off + cPl) = lo;
                    }
        } else {
            // Transposed per-head single-plane store -> Cv2 ([B,H,DH,S])
            __half* st = (__half*)sm;
            __syncthreads();     // other warps may still read load stages
            #pragma unroll
            for (int mt = 0; mt < MT; ++mt)
                #pragma unroll
                for (int nt = 0; nt < 4; ++nt)
                    #pragma unroll
                    for (int h = 0; h < 2; ++h) {
                        int r = r0 + mt * 16 + h * 8;
                        int c = c0 + nt * 8;
                        float x0 = acc[mt][nt][h * 2 + 0] * alpha;
                        float x1 = acc[mt][nt][h * 2 + 1] * alpha;
                        __half2 hi = __floats2half2_rn(x0, x1);
                        st[c * 136 + r]       = __low2half(hi);
                        st[(c + 1) * 136 + r] = __high2half(hi);
                    }
            __syncthreads();
            const int b = blockIdx.y >> 3, s0r = (blockIdx.y & 7) * 128;
            __half* vt = (__half*)Cv2;
            #pragma unroll
            for (int t = 0; t < 8; ++t) {
                int u = tid + t * 256;
                int c = u >> 4, rch = u & 15;
                int d = blockIdx.x * 128 + c;
                int hh = d >> 6, dh = d & 63;
                uint4 val = *(const uint4*)(st + c * 136 + rch * 8);
                *(uint4*)(vt + ((long)(b * NH + hh) * NDH + dh) * NS + s0r + rch * 8) = val;
            }
        }
    } else if (MODE == 0) {
        float* Cf = (float*)Cv + (long)zo * cOut + (long)zi * cIn
                    + (long)(blockIdx.y * BM) * ldc + blockIdx.x * BN;
        #pragma unroll
        for (int mt = 0; mt < MT; ++mt)
            #pragma unroll
            for (int nt = 0; nt < 4; ++nt)
                #pragma unroll
                for (int h = 0; h < 2; ++h) {
                    long off = (long)(r0 + mt * 16 + h * 8) * ldc + c0 + nt * 8;
                    float2 v = make_float2(acc[mt][nt][h * 2 + 0] * alpha,
                                           acc[mt][nt][h * 2 + 1] * alpha);
                    *(float2*)(Cf + off) = v;
                }
    } else {  // MODE 2: shifted store via smem staging -> coalesced rows
        float* stf = (float*)sm;       // 128 x 132 fp32 = 67584 B
        __syncthreads();               // protect load stages before reuse
        #pragma unroll
        for (int mt = 0; mt < MT; ++mt)
            #pragma unroll
            for (int nt = 0; nt < 4; ++nt)
                #pragma unroll
                for (int h = 0; h < 2; ++h) {
                    int r = r0 + mt * 16 + h * 8;
                    int c = c0 + nt * 8;
                    stf[r * 132 + c]     = acc[mt][nt][h * 2 + 0] * alpha;
                    stf[r * 132 + c + 1] = acc[mt][nt][h * 2 + 1] * alpha;
                }
        __syncthreads();
        float* Cf = (float*)Cv + (long)zo * cOut + (long)zi * cIn;
        const int ig0 = blockIdx.y * BM, cg0 = blockIdx.x * BN;
        #pragma unroll
        for (int t = 0; t < 64; ++t) {
            int idx = tid + t * 256;
            int r = idx >> 7, c = idx & 127;
            int ig = ig0 + r;
            int j = cg0 + c - (NS - 1) + ig;
            if (j >= 0) Cf[(long)ig * NS + j] = stf[r * 132 + c];
        }
    }
}

// ---------------------------------------------------------------------------
// Fused attention, lean precision: QK = qh*kh (1 MMA), AV = P*Vh (1 MMA).
// One sync per j-tile ({wait; sync; issue(next); compute}).
// ---------------------------------------------------------------------------
constexpr int G_KS = 9216;                       // 64 x 72 fp16 stage
constexpr int G_K  = 0;                          // 2 stages -> [0, 18432)
constexpr int G_V  = 18432;                      // 2 stages -> [18432, 36864)
constexpr int G_MB = 36864;                      // mask bias -> [36864, 40960)
constexpr int G_P  = 40960;                      // 2 stages x 34816 -> 110592
constexpr int G_PST = 34816;
constexpr int G_TOT = 110592;

__global__ void __launch_bounds__(256, 2) fused_attn(
    const __half* __restrict__ q, const __half* __restrict__ k,
    const __half* __restrict__ vt, const float* __restrict__ pshift,
    const int* __restrict__ mask, __half* __restrict__ ctx)
{
    extern __shared__ __align__(128) char sm[];
    const uint32_t sb = smem_u32(sm);
    const int tid = threadIdx.x, wid = tid >> 5, lane = tid & 31;
    const int i0 = (7 - blockIdx.x) * 128;       // heavy-first
    const int bh = blockIdx.y, b = bh / NH, h = bh % NH;
    const float SC = 0.125f * LOG2E;

    const __half* qg  = q + (long)b * NS * ND + (long)i0 * ND + h * NDH;
    const __half* kg  = k + (long)b * NS * ND + h * NDH;
    const __half* vtg = vt + (long)bh * NDH * NS;
    const float* pg = pshift + (long)bh * NS * NS + (long)i0 * NS;

    float* mbias = (float*)(sm + G_MB);
    for (int j = tid; j < NS; j += 256)
        mbias[j] = mask[b * NS + j] ? 0.0f : -1.5e9f;

    // ---- Prologue: Q hi plane through the K area, consume to registers ----
    #pragma unroll
    for (int t = 0; t < 4; ++t) {
        int idx = tid + t * 256;
        int r = idx >> 3, ch = idx & 7;
        cpa16(sb + (r * 72 + ch * 8) * 2, qg + (long)r * ND + ch * 8);
    }
    cpa_commit();
    cpa_wait<0>();
    __syncthreads();

    uint32_t qah[4][4];
    {
        uint32_t base = sb + ((wid * 16 + (lane & 15)) * 72 + (lane >> 4) * 8) * 2;
        #pragma unroll
        for (int kt = 0; kt < 4; ++kt) ldsm_x4(qah[kt], base + kt * 32);
    }
    __syncthreads();     // Q fully consumed; K area free for reuse

    auto issue = [&](int jt) {
        const int st = jt & 1, j0 = jt * 64;
        #pragma unroll
        for (int t = 0; t < 2; ++t) {   // K hi tile
            int idx = tid + t * 256;
            int r = idx >> 3, ch = idx & 7;
            cpa16(sb + G_K + st * G_KS + (r * 72 + ch * 8) * 2,
                  kg + (long)(j0 + r) * ND + ch * 8);
        }
        #pragma unroll
        for (int t = 0; t < 2; ++t) {   // V hi tile
            int idx = tid + t * 256;
            int d = idx >> 3, ch = idx & 7;
            cpa16(sb + G_V + st * G_KS + (d * 72 + ch * 8) * 2,
                  vtg + (long)d * NS + j0 + ch * 8);
        }
        if (j0 <= i0 + 127) {           // Pshift tile (fp32)
            #pragma unroll
            for (int t = 0; t < 8; ++t) {
                int idx = tid + t * 256;
                int r = idx >> 4, ch = idx & 15;
                cpa16(sb + G_P + st * G_PST + (r * 68 + ch * 4) * 4,
                      pg + (long)r * NS + j0 + ch * 4);
            }
        }
        cpa_commit();
    };

    issue(0);

    const int rA = wid * 16 + (lane >> 2);
    const int iA = i0 + rA, iB = iA + 8;
    const int miA = mask[b * NS + iA], miB = mask[b * NS + iB];
    const int brow = (lane & 7) | ((lane >> 1) & 8);
    const int bcol = ((lane >> 3) & 1) * 8;

    float oacc[8][4] = {};
    float mA = -1.0e30f, mB = -1.0e30f, lA = 0.0f, lB = 0.0f;

    for (int jt = 0; jt < 16; ++jt) {
        cpa_wait<0>();
        __syncthreads();
        if (jt + 1 < 16) issue(jt + 1);

        const int st = jt & 1, j0 = jt * 64;
        const uint32_t kb = sb + G_K + st * G_KS;
        const uint32_t vb = sb + G_V + st * G_KS;
        const bool anyP = (j0 <= i0 + 127);
        const float* psm = (const float*)(sm + G_P + st * G_PST);

        // ---- S = qh @ kh^T (1 MMA) ----
        float sacc[8][4] = {};
        #pragma unroll
        for (int kt = 0; kt < 4; ++kt) {
            uint32_t bhf[4][4];
            #pragma unroll
            for (int p = 0; p < 4; ++p)
                ldsm_x4(bhf[p], kb + ((p * 16 + brow) * 72 + bcol + kt * 16) * 2);
            #pragma unroll
            for (int nt = 0; nt < 8; ++nt)
                mma16<1>(sacc[nt], qah[kt], &bhf[nt >> 1][(nt & 1) * 2]);
        }

        // ---- logits (log2 domain): scale + pshift + mask ----
        #pragma unroll
        for (int nt = 0; nt < 8; ++nt) {
            int jl = nt * 8 + (lane & 3) * 2;
            int jg = j0 + jl;
            float p0A = 0, p1A = 0, p0B = 0, p1B = 0;
            if (anyP) {
                float2 fa = *(const float2*)(psm + rA * 68 + jl);
                float2 fb = *(const float2*)(psm + (rA + 8) * 68 + jl);
                p0A = (jg     <= iA) ? fa.x : 0.0f;
                p1A = (jg + 1 <= iA) ? fa.y : 0.0f;
                p0B = (jg     <= iB) ? fb.x : 0.0f;
                p1B = (jg + 1 <= iB) ? fb.y : 0.0f;
            }
            float b0 = mbias[jg], b1 = mbias[jg + 1];
            sacc[nt][0] = miA ? fmaf(sacc[nt][0], SC, p0A) + b0 : -1.0e9f;
            sacc[nt][1] = miA ? fmaf(sacc[nt][1], SC, p1A) + b1 : -1.0e9f;
            sacc[nt][2] = miB ? fmaf(sacc[nt][2], SC, p0B) + b0 : -1.0e9f;
            sacc[nt][3] = miB ? fmaf(sacc[nt][3], SC, p1B) + b1 : -1.0e9f;
        }

        // ---- online softmax (base-2) ----
        float rmA = -1.0e30f, rmB = -1.0e30f;
        #pragma unroll
        for (int nt = 0; nt < 8; ++nt) {
            rmA = fmaxf(rmA, fmaxf(sacc[nt][0], sacc[nt][1]));
            rmB = fmaxf(rmB, fmaxf(sacc[nt][2], sacc[nt][3]));
        }
        rmA = fmaxf(rmA, __shfl_xor_sync(0xffffffffu, rmA, 1));
        rmA = fmaxf(rmA, __shfl_xor_sync(0xffffffffu, rmA, 2));
        rmB = fmaxf(rmB, __shfl_xor_sync(0xffffffffu, rmB, 1));
        rmB = fmaxf(rmB, __shfl_xor_sync(0xffffffffu, rmB, 2));

        float mnA = fmaxf(mA, rmA), mnB = fmaxf(mB, rmB);
        float alA = exp2f(mA - mnA), alB = exp2f(mB - mnB);
        mA = mnA; mB = mnB;

        float rsA = 0.0f, rsB = 0.0f;
        #pragma unroll
        for (int nt = 0; nt < 8; ++nt) {
            sacc[nt][0] = exp2f(sacc[nt][0] - mnA);
            sacc[nt][1] = exp2f(sacc[nt][1] - mnA);
            sacc[nt][2] = exp2f(sacc[nt][2] - mnB);
            sacc[nt][3] = exp2f(sacc[nt][3] - mnB);
            rsA += sacc[nt][0] + sacc[nt][1];
            rsB += sacc[nt][2] + sacc[nt][3];
        }
        rsA += __shfl_xor_sync(0xffffffffu, rsA, 1);
        rsA += __shfl_xor_sync(0xffffffffu, rsA, 2);
        rsB += __shfl_xor_sync(0xffffffffu, rsB, 1);
        rsB += __shfl_xor_sync(0xffffffffu, rsB, 2);
        lA = lA * alA + rsA;
        lB = lB * alB + rsB;
        #pragma unroll
        for (int nt = 0; nt < 8; ++nt) {
            oacc[nt][0] *= alA; oacc[nt][1] *= alA;
            oacc[nt][2] *= alB; oacc[nt][3] *= alB;
        }

        // ---- pack P into fp16 A-fragments ----
        uint32_t pah[4][4];
        #pragma unroll
        for (int kt = 0; kt < 4; ++kt) {
            const float* e = sacc[2 * kt];
            const float* o = sacc[2 * kt + 1];
            pah[kt][0] = packhf(e[0], e[1]); pah[kt][1] = packhf(e[2], e[3]);
            pah[kt][2] = packhf(o[0], o[1]); pah[kt][3] = packhf(o[2], o[3]);
        }

        // ---- O += P @ Vh (1 MMA) ----
        #pragma unroll
        for (int kt = 0; kt < 4; ++kt) {
            uint32_t vhf[4][4];
            #pragma unroll
            for (int p = 0; p < 4; ++p)
                ldsm_x4(vhf[p], vb + ((p * 16 + brow) * 72 + bcol + kt * 16) * 2);
            #pragma unroll
            for (int nt = 0; nt < 8; ++nt)
                mma16<1>(oacc[nt], pah[kt], &vhf[nt >> 1][(nt & 1) * 2]);
        }
    }

    // ---- epilogue: normalize, stage fp16 in smem (K area), coalesced store ----
    __syncthreads();     // other warps may still read stage 1 (overlaps staging)
    const float ivA = 1.0f / lA, ivB = 1.0f / lB;
    __half* so = (__half*)sm;
    #pragma unroll
    for (int nt = 0; nt < 8; ++nt) {
        int c = nt * 8 + (lane & 3) * 2;
        *(__half2*)(so + rA * 72 + c) =
            __floats2half2_rn(oacc[nt][0] * ivA, oacc[nt][1] * ivA);
        *(__half2*)(so + (rA + 8) * 72 + c) =
            __floats2half2_rn(oacc[nt][2] * ivB, oacc[nt][3] * ivB);
    }
    __syncthreads();
    __half* cgb = ctx + (long)b * NS * ND + (long)i0 * ND + h * NDH;
    #pragma unroll
    for (int t = 0; t < 4; ++t) {
        int idx = tid + t * 256;
        int r = idx >> 3, ch = idx & 7;
        uint4 val = *(const uint4*)(so + r * 72 + ch * 8);
        *(uint4*)(cgb + (long)r * ND + ch * 8) = val;
    }
}

// ---------------------------------------------------------------------------
// Merged split: fp32 -> 16-bit hi/lo planes (bf16, or fp16 when f16[seg]=1)
// ---------------------------------------------------------------------------
struct SplitArgs {
    const float4* s[8];
    uint16_t* d[8];
    int n4[8];
    int f16[8];
};
__global__ void __launch_bounds__(256) split_all(SplitArgs a)
{
    const int seg = blockIdx.y;
    const int n4 = a.n4[seg];
    const float4* s = a.s[seg];
    uint16_t* dst = a.d[seg];
    const long pl = (long)n4 * 4;
    const bool f16 = a.f16[seg] != 0;
    for (int i = blockIdx.x * 256 + threadIdx.x; i < n4; i += gridDim.x * 256) {
        float4 x = s[i];
        uint32_t h0, h1, l0, l1;
        if (f16) {
            __half2 a0 = __floats2half2_rn(x.x, x.y);
            __half2 a1 = __floats2half2_rn(x.z, x.w);
            __half2 b0 = __floats2half2_rn(x.x - __half2float(__low2half(a0)),
                                           x.y - __half2float(__high2half(a0)));
            __half2 b1 = __floats2half2_rn(x.z - __half2float(__low2half(a1)),
                                           x.w - __half2float(__high2half(a1)));
            h0 = *(uint32_t*)&a0; h1 = *(uint32_t*)&a1;
            l0 = *(uint32_t*)&b0; l1 = *(uint32_t*)&b1;
        } else {
            __nv_bfloat162 a0 = __floats2bfloat162_rn(x.x, x.y);
            __nv_bfloat162 a1 = __floats2bfloat162_rn(x.z, x.w);
            __nv_bfloat162 b0 = __floats2bfloat162_rn(x.x - __low2float(a0),
                                                      x.y - __high2float(a0));
            __nv_bfloat162 b1 = __floats2bfloat162_rn(x.z - __low2float(a1),
                                                      x.w - __high2float(a1));
            h0 = *(uint32_t*)&a0; h1 = *(uint32_t*)&a1;
            l0 = *(uint32_t*)&b0; l1 = *(uint32_t*)&b1;
        }
        ((uint32_t*)dst)[2 * i]          = h0;
        ((uint32_t*)dst)[2 * i + 1]      = h1;
        ((uint32_t*)(dst + pl))[2 * i]     = l0;
        ((uint32_t*)(dst + pl))[2 * i + 1] = l1;
    }
}

// ---------------------------------------------------------------------------
extern "C" void kernel_launch(void* const* d_in, const int* in_sizes, int n_in,
                              void* d_out, int out_size)
{
    const float* query = (const float*)d_in[0];
    const float* key   = (const float*)d_in[1];
    const float* value = (const float*)d_in[2];
    const int*   mask  = (const int*)  d_in[3];
    const float* pe    = (const float*)d_in[4];
    const float* Wq    = (const float*)d_in[5];
    const float* Wk    = (const float*)d_in[6];
    const float* Wv    = (const float*)d_in[7];
    const float* Wo    = (const float*)d_in[8];
    float* out = (float*)d_out;

    void *vx, *vy, *vz, *vq, *vk, *vvt, *vctx, *vwq, *vwk, *vwv, *vwo,
         *vpe, *vps;
    cudaGetSymbolAddress(&vx, p_x);     cudaGetSymbolAddress(&vy, p_y);
    cudaGetSymbolAddress(&vz, p_z);     cudaGetSymbolAddress(&vq, p_q);
    cudaGetSymbolAddress(&vk, p_k);     cudaGetSymbolAddress(&vvt, p_vt);
    cudaGetSymbolAddress(&vctx, p_ctx);
    cudaGetSymbolAddress(&vwq, p_wq);   cudaGetSymbolAddress(&vwk, p_wk);
    cudaGetSymbolAddress(&vwv, p_wv);   cudaGetSymbolAddress(&vwo, p_wo);
    cudaGetSymbolAddress(&vpe, p_pe);   cudaGetSymbolAddress(&vps, g_pshift);

    SplitArgs sa;
    sa.s[0] = (const float4*)query; sa.d[0] = (uint16_t*)vx;  sa.n4[0] = (int)(E_X / 4);  sa.f16[0] = 0;
    sa.s[1] = (const float4*)key;   sa.d[1] = (uint16_t*)vy;  sa.n4[1] = (int)(E_X / 4);  sa.f16[1] = 0;
    sa.s[2] = (const float4*)value; sa.d[2] = (uint16_t*)vz;  sa.n4[2] = (int)(E_X / 4);  sa.f16[2] = 0;
    sa.s[3] = (const float4*)Wq;    sa.d[3] = (uint16_t*)vwq; sa.n4[3] = (int)(E_W / 4);  sa.f16[3] = 0;
    sa.s[4] = (const float4*)Wk;    sa.d[4] = (uint16_t*)vwk; sa.n4[4] = (int)(E_W / 4);  sa.f16[4] = 0;
    sa.s[5] = (const float4*)Wv;    sa.d[5] = (uint16_t*)vwv; sa.n4[5] = (int)(E_W / 4);  sa.f16[5] = 0;
    sa.s[6] = (const float4*)Wo;    sa.d[6] = (uint16_t*)vwo; sa.n4[6] = (int)(E_W / 4);  sa.f16[6] = 1;
    sa.s[7] = (const float4*)pe;    sa.d[7] = (uint16_t*)vpe; sa.n4[7] = (int)(E_PE / 4); sa.f16[7] = 1;
    split_all<<<dim3(1024, 8), 256>>>(sa);

    const int SM128 = 2 * (20480 + 2 * 128 * 80);  // 81920
    cudaFuncSetAttribute(gemm2<128, 0, 1, 1>, cudaFuncAttributeMaxDynamicSharedMemorySize, SM128);
    cudaFuncSetAttribute(gemm2<128, 2, 1, 0>, cudaFuncAttributeMaxDynamicSharedMemorySize, SM128);
    cudaFuncSetAttribute(gemm2<128, 6, 0, 0>, cudaFuncAttributeMaxDynamicSharedMemorySize, SM128);
    cudaFuncSetAttribute(fused_attn, cudaFuncAttributeMaxDynamicSharedMemorySize, G_TOT);

    const dim3 th(256);
    const long SD  = (long)NS * ND;
    const long SS  = (long)NS * NS;
    const long HSS = (long)NH * SS;

    // q,k,v projections merged: z<2 -> plane out (q,k); z==2 -> transposed vt
    const long dA = (long)(((char*)vy - (char*)vx) / 2);
    const long dB = (long)(((char*)vwk - (char*)vwq) / 2);
    const long dC = (long)(((char*)vk - (char*)vq) / 2);
    gemm2<128, 6, 0, 0><<<dim3(8, 32, 3), th, SM128>>>(
        vx, vwq, vq, vz, vwv, vvt,
        ND, ND, ND, ND,
        0, dA, 0, dB, 0, dC, E_X, E_W, E_X, 1.0f, 0);

    // Pshift = shifted (q @ pe^T) * 8 * log2e  (fp16 hi/lo 3-MMA, triangular)
    gemm2<128, 2, 1, 0><<<dim3(8, 8, NB * NH), th, SM128>>>(
        vq, vpe, vps, nullptr, nullptr, nullptr,
        NDH, ND, NDH, NS,
        SD, NDH, 0, (long)NS * NDH, HSS, SS, E_X, E_PE, 0, 8.0f * LOG2E, 1);

    // fused: QK^T + skew + mask + softmax + AV -> ctx (single fp16 plane)
    fused_attn<<<dim3(8, NB * NH), th, G_TOT>>>(
        (const __half*)vq, (const __half*)vk, (const __half*)vvt,
        (const float*)vps, mask, (__half*)vctx);

    // out = ctx(fp16, single plane) @ Wo(fp16 hi/lo)^T  -- 2-MMA
    gemm2<128, 0, 1, 1><<<dim3(8, 32, 1), th, SM128>>>(
        vctx, vwo, out, nullptr, nullptr, nullptr,
        ND, ND, ND, ND,
        0, 0, 0, 0, 0, 0, 0, E_W, 0, 1.0f, 0);
}